// round 2
// baseline (speedup 1.0000x reference)
#include <cuda_runtime.h>

#define Bsz 16
#define Cdim 512
#define HWp 4096
#define Sctx 77
#define CTXd 768
#define NHEADS 8
#define HD 64
#define NGROUPS 32
#define CPG 16
#define EPSV 1e-5f

// ---- scratch (static device globals; no runtime allocation) ----
__device__ float g_q [(size_t)Bsz * Cdim * HWp];   // Q  (B, C, HW)
__device__ float g_ao[(size_t)Bsz * Cdim * HWp];   // attn out (B, C, HW)
__device__ float g_cn[(size_t)Bsz * Sctx * CTXd];  // layernormed context
__device__ float g_k [(size_t)Bsz * Sctx * Cdim];  // K (B*S, C)
__device__ float g_v [(size_t)Bsz * Sctx * Cdim];  // V (B*S, C)
__device__ float g_stats[Bsz * NGROUPS * 2];       // (mean, rstd) per (b,g)

// ============================================================
// GroupNorm statistics: one block per (b, g); region is contiguous
// ============================================================
__global__ void gn_stats_kernel(const float* __restrict__ x) {
    int blk = blockIdx.x;
    int b = blk / NGROUPS, g = blk % NGROUPS;
    const float4* p = (const float4*)(x + ((size_t)b * Cdim + (size_t)g * CPG) * HWp);
    const int n4 = CPG * HWp / 4;  // 16384
    float s = 0.f, sq = 0.f;
    for (int i = threadIdx.x; i < n4; i += blockDim.x) {
        float4 v = p[i];
        s  += v.x + v.y + v.z + v.w;
        sq += v.x * v.x + v.y * v.y + v.z * v.z + v.w * v.w;
    }
    __shared__ float ss[32], ssq[32];
    #pragma unroll
    for (int o = 16; o > 0; o >>= 1) {
        s  += __shfl_down_sync(0xffffffffu, s, o);
        sq += __shfl_down_sync(0xffffffffu, sq, o);
    }
    int wid = threadIdx.x >> 5, lid = threadIdx.x & 31;
    if (lid == 0) { ss[wid] = s; ssq[wid] = sq; }
    __syncthreads();
    if (wid == 0) {
        int nw = blockDim.x >> 5;
        s  = (lid < nw) ? ss[lid]  : 0.f;
        sq = (lid < nw) ? ssq[lid] : 0.f;
        #pragma unroll
        for (int o = 16; o > 0; o >>= 1) {
            s  += __shfl_down_sync(0xffffffffu, s, o);
            sq += __shfl_down_sync(0xffffffffu, sq, o);
        }
        if (lid == 0) {
            const float invn = 1.f / (float)(CPG * HWp);
            float mean = s * invn;
            float var  = sq * invn - mean * mean;
            g_stats[blk * 2]     = mean;
            g_stats[blk * 2 + 1] = rsqrtf(var + EPSV);
        }
    }
}

// ============================================================
// LayerNorm on context: one block per row (B*S = 1232 rows of 768)
// ============================================================
__global__ void ln_kernel(const float* __restrict__ ctx,
                          const float* __restrict__ w,
                          const float* __restrict__ bb) {
    int row = blockIdx.x;
    const float* xr = ctx + (size_t)row * CTXd;
    float s = 0.f, sq = 0.f;
    for (int i = threadIdx.x; i < CTXd; i += blockDim.x) {
        float v = xr[i];
        s += v; sq += v * v;
    }
    __shared__ float ss[32], ssq[32];
    __shared__ float smean, srstd;
    #pragma unroll
    for (int o = 16; o > 0; o >>= 1) {
        s  += __shfl_down_sync(0xffffffffu, s, o);
        sq += __shfl_down_sync(0xffffffffu, sq, o);
    }
    int wid = threadIdx.x >> 5, lid = threadIdx.x & 31;
    if (lid == 0) { ss[wid] = s; ssq[wid] = sq; }
    __syncthreads();
    if (wid == 0) {
        int nw = blockDim.x >> 5;
        s  = (lid < nw) ? ss[lid]  : 0.f;
        sq = (lid < nw) ? ssq[lid] : 0.f;
        #pragma unroll
        for (int o = 16; o > 0; o >>= 1) {
            s  += __shfl_down_sync(0xffffffffu, s, o);
            sq += __shfl_down_sync(0xffffffffu, sq, o);
        }
        if (lid == 0) {
            const float invn = 1.f / (float)CTXd;
            float mean = s * invn;
            float var  = sq * invn - mean * mean;
            smean = mean;
            srstd = rsqrtf(var + EPSV);
        }
    }
    __syncthreads();
    float mean = smean, rstd = srstd;
    for (int i = threadIdx.x; i < CTXd; i += blockDim.x) {
        g_cn[(size_t)row * CTXd + i] = (xr[i] - mean) * rstd * w[i] + bb[i];
    }
}

// ============================================================
// K/V projection: out[n,o] = sum_j cn[n,j]*W[o,j] + b[o]
// NT GEMM, M=1232 (n), N=512 (o), K=768. blockIdx.z: 0 -> K, 1 -> V
// ============================================================
#define KV_BM 64
#define KV_BN 64
#define KV_BK 16
__global__ void kv_gemm(const float* __restrict__ kw, const float* __restrict__ kb,
                        const float* __restrict__ vw, const float* __restrict__ vb) {
    __shared__ float As[KV_BM][KV_BK + 1];
    __shared__ float Ws[KV_BN][KV_BK + 1];
    const float* W    = blockIdx.z ? vw : kw;
    const float* bias = blockIdx.z ? vb : kb;
    float*       out  = blockIdx.z ? g_v : g_k;
    const int NROWS = Bsz * Sctx;  // 1232

    int n0 = blockIdx.x * KV_BM;
    int o0 = blockIdx.y * KV_BN;
    int tid = threadIdx.x;
    int tx = tid & 15, ty = tid >> 4;
    int lrow = tid >> 2;
    int lcol = (tid & 3) * 4;

    float acc[4][4] = {};
    for (int k0 = 0; k0 < CTXd; k0 += KV_BK) {
        int n = n0 + lrow;
        float4 av = (n < NROWS)
            ? *(const float4*)(g_cn + (size_t)n * CTXd + k0 + lcol)
            : make_float4(0.f, 0.f, 0.f, 0.f);
        As[lrow][lcol] = av.x; As[lrow][lcol + 1] = av.y;
        As[lrow][lcol + 2] = av.z; As[lrow][lcol + 3] = av.w;
        float4 wv = *(const float4*)(W + (size_t)(o0 + lrow) * CTXd + k0 + lcol);
        Ws[lrow][lcol] = wv.x; Ws[lrow][lcol + 1] = wv.y;
        Ws[lrow][lcol + 2] = wv.z; Ws[lrow][lcol + 3] = wv.w;
        __syncthreads();
        #pragma unroll
        for (int k = 0; k < KV_BK; k++) {
            float af[4], wf[4];
            #pragma unroll
            for (int i = 0; i < 4; i++) af[i] = As[ty * 4 + i][k];
            #pragma unroll
            for (int j = 0; j < 4; j++) wf[j] = Ws[tx * 4 + j][k];
            #pragma unroll
            for (int i = 0; i < 4; i++)
                #pragma unroll
                for (int j = 0; j < 4; j++)
                    acc[i][j] += af[i] * wf[j];
        }
        __syncthreads();
    }
    #pragma unroll
    for (int i = 0; i < 4; i++) {
        int n = n0 + ty * 4 + i;
        if (n >= NROWS) continue;
        #pragma unroll
        for (int j = 0; j < 4; j++) {
            int o = o0 + tx * 4 + j;
            out[(size_t)n * Cdim + o] = acc[i][j] + bias[o];
        }
    }
}

// ============================================================
// Projection GEMM: out[b,o,p] = sum_c W[o,c]*X[b,c,p] + bias[o] (+residual)
// Optional fused GroupNorm affine applied to X on load (for Q projection).
// 128x128x8 tile, 256 threads, 8x8 per thread.
// ============================================================
__global__ void proj_gemm(const float* __restrict__ W,
                          const float* __restrict__ X,
                          const float* __restrict__ bias,
                          float* __restrict__ out,
                          const float* __restrict__ gnw,   // null -> no GN
                          const float* __restrict__ gnb,
                          const float* __restrict__ residual) {  // null -> none
    __shared__ float As[8][128];
    __shared__ float Bs[8][128];
    int b  = blockIdx.z;
    int o0 = blockIdx.y * 128;
    int p0 = blockIdx.x * 128;
    const float* Xb = X + (size_t)b * Cdim * HWp;
    int tid = threadIdx.x;
    int tx = tid & 15, ty = tid >> 4;
    int arow = tid >> 1, acol = (tid & 1) * 4;
    int brow = tid >> 5, bcol = (tid & 31) * 4;

    float acc[8][8] = {};
    for (int k0 = 0; k0 < Cdim; k0 += 8) {
        float4 aw = *(const float4*)(W + (size_t)(o0 + arow) * Cdim + k0 + acol);
        As[acol][arow] = aw.x; As[acol + 1][arow] = aw.y;
        As[acol + 2][arow] = aw.z; As[acol + 3][arow] = aw.w;

        int c = k0 + brow;
        float4 xv = *(const float4*)(Xb + (size_t)c * HWp + p0 + bcol);
        if (gnw) {
            int g = c >> 4;
            float mean = g_stats[(b * NGROUPS + g) * 2];
            float rstd = g_stats[(b * NGROUPS + g) * 2 + 1];
            float a  = rstd * gnw[c];
            float bb = gnb[c] - mean * a;
            xv.x = xv.x * a + bb; xv.y = xv.y * a + bb;
            xv.z = xv.z * a + bb; xv.w = xv.w * a + bb;
        }
        *(float4*)&Bs[brow][bcol] = xv;
        __syncthreads();
        #pragma unroll
        for (int k = 0; k < 8; k++) {
            float af[8], bf[8];
            *(float4*)&af[0] = *(const float4*)&As[k][ty * 8];
            *(float4*)&af[4] = *(const float4*)&As[k][ty * 8 + 4];
            *(float4*)&bf[0] = *(const float4*)&Bs[k][tx * 8];
            *(float4*)&bf[4] = *(const float4*)&Bs[k][tx * 8 + 4];
            #pragma unroll
            for (int i = 0; i < 8; i++)
                #pragma unroll
                for (int j = 0; j < 8; j++)
                    acc[i][j] += af[i] * bf[j];
        }
        __syncthreads();
    }
    #pragma unroll
    for (int i = 0; i < 8; i++) {
        int o = o0 + ty * 8 + i;
        float bi = bias[o];
        size_t base = (size_t)b * Cdim * HWp + (size_t)o * HWp + p0 + tx * 8;
        #pragma unroll
        for (int j = 0; j < 8; j += 4) {
            float4 r;
            r.x = acc[i][j] + bi;     r.y = acc[i][j + 1] + bi;
            r.z = acc[i][j + 2] + bi; r.w = acc[i][j + 3] + bi;
            if (residual) {
                float4 rv = *(const float4*)(residual + base + j);
                r.x += rv.x; r.y += rv.y; r.z += rv.z; r.w += rv.w;
            }
            *(float4*)(out + base + j) = r;
        }
    }
}

// ============================================================
// Fused attention: per (b, h, 64-pixel tile). K,V staged in smem,
// per-thread (= per-pixel) softmax over S=77.
// ============================================================
__global__ void attn_kernel() {
    __shared__ float ks[Sctx * HD];   // K tile, then reused for V
    __shared__ float ps[Sctx * 64];   // scores [s][pix]
    int b = blockIdx.z, h = blockIdx.y;
    int p0 = blockIdx.x * 64;
    int tid = threadIdx.x;  // 64 threads

    for (int i = tid; i < Sctx * HD; i += 64) {
        int s = i >> 6, d = i & 63;
        ks[i] = g_k[(size_t)(b * Sctx + s) * Cdim + h * HD + d];
    }
    float qreg[64];
    const float* qp = g_q + (size_t)b * Cdim * HWp + (size_t)h * HD * HWp + p0 + tid;
    #pragma unroll
    for (int d = 0; d < 64; d++) qreg[d] = qp[(size_t)d * HWp];
    __syncthreads();

    for (int s = 0; s < Sctx; s++) {
        const float4* kk = (const float4*)(ks + s * 64);
        float a = 0.f;
        #pragma unroll
        for (int d4 = 0; d4 < 16; d4++) {
            float4 k4 = kk[d4];
            a += qreg[d4 * 4] * k4.x + qreg[d4 * 4 + 1] * k4.y
               + qreg[d4 * 4 + 2] * k4.z + qreg[d4 * 4 + 3] * k4.w;
        }
        ps[s * 64 + tid] = a * 0.125f;  // HD^-0.5
    }
    // softmax over own column
    float m = -1e30f;
    for (int s = 0; s < Sctx; s++) m = fmaxf(m, ps[s * 64 + tid]);
    float sum = 0.f;
    for (int s = 0; s < Sctx; s++) {
        float e = __expf(ps[s * 64 + tid] - m);
        ps[s * 64 + tid] = e;
        sum += e;
    }
    float inv = 1.f / sum;
    __syncthreads();  // all reads of K done -> safe to overwrite with V

    for (int i = tid; i < Sctx * HD; i += 64) {
        int s = i >> 6, d = i & 63;
        ks[i] = g_v[(size_t)(b * Sctx + s) * Cdim + h * HD + d];
    }
    __syncthreads();

    float oacc[64];
    #pragma unroll
    for (int d = 0; d < 64; d++) oacc[d] = 0.f;
    for (int s = 0; s < Sctx; s++) {
        float pw = ps[s * 64 + tid];
        const float4* vv = (const float4*)(ks + s * 64);
        #pragma unroll
        for (int d4 = 0; d4 < 16; d4++) {
            float4 v4 = vv[d4];
            oacc[d4 * 4]     += pw * v4.x;
            oacc[d4 * 4 + 1] += pw * v4.y;
            oacc[d4 * 4 + 2] += pw * v4.z;
            oacc[d4 * 4 + 3] += pw * v4.w;
        }
    }
    float* op = g_ao + (size_t)b * Cdim * HWp + (size_t)h * HD * HWp + p0 + tid;
    #pragma unroll
    for (int d = 0; d < 64; d++) op[(size_t)d * HWp] = oacc[d] * inv;
}

// ============================================================
extern "C" void kernel_launch(void* const* d_in, const int* in_sizes, int n_in,
                              void* d_out, int out_size) {
    const float* x       = (const float*)d_in[0];
    const float* context = (const float*)d_in[1];
    const float* gn_w    = (const float*)d_in[2];
    const float* gn_b    = (const float*)d_in[3];
    const float* ln_w    = (const float*)d_in[4];
    const float* ln_b    = (const float*)d_in[5];
    const float* q_w     = (const float*)d_in[6];
    const float* q_b     = (const float*)d_in[7];
    const float* k_w     = (const float*)d_in[8];
    const float* k_b     = (const float*)d_in[9];
    const float* v_w     = (const float*)d_in[10];
    const float* v_b     = (const float*)d_in[11];
    const float* out_w   = (const float*)d_in[12];
    const float* out_b   = (const float*)d_in[13];
    float* out = (float*)d_out;

    float *qptr = nullptr, *aoptr = nullptr;
    cudaGetSymbolAddress((void**)&qptr, g_q);
    cudaGetSymbolAddress((void**)&aoptr, g_ao);

    // 1. GroupNorm stats on x
    gn_stats_kernel<<<Bsz * NGROUPS, 256>>>(x);
    // 2. LayerNorm on context
    ln_kernel<<<Bsz * Sctx, 256>>>(context, ln_w, ln_b);
    // 3. K/V projection
    kv_gemm<<<dim3((Bsz * Sctx + KV_BM - 1) / KV_BM, Cdim / KV_BN, 2), 256>>>(
        k_w, k_b, v_w, v_b);
    // 4. Q projection with fused GroupNorm on X
    proj_gemm<<<dim3(HWp / 128, Cdim / 128, Bsz), 256>>>(
        q_w, x, q_b, qptr, gn_w, gn_b, nullptr);
    // 5. Attention
    attn_kernel<<<dim3(HWp / 64, NHEADS, Bsz), 64>>>();
    // 6. Output projection + residual
    proj_gemm<<<dim3(HWp / 128, Cdim / 128, Bsz), 256>>>(
        out_w, aoptr, out_b, out, nullptr, nullptr, x);
}

// round 4
// speedup vs baseline: 2.6344x; 2.6344x over previous
#include <cuda_runtime.h>
#include <cuda_bf16.h>
#include <cstdint>

#define Bsz 16
#define Cdim 512
#define HWp 4096
#define Sctx 77
#define CTXd 768
#define NHEADS 8
#define HD 64
#define NGROUPS 32
#define CPG 16
#define EPSV 1e-5f

// ---- scratch (static device globals; no runtime allocation) ----
__device__ float g_q [(size_t)Bsz * Cdim * HWp];          // Q  (B, C, HW) fp32
__device__ __nv_bfloat16 g_xnb[(size_t)Bsz * Cdim * HWp]; // GN(x) bf16
__device__ __nv_bfloat16 g_aob[(size_t)Bsz * Cdim * HWp]; // attn out bf16
__device__ float g_cn[(size_t)Bsz * Sctx * CTXd];         // layernormed context
__device__ float g_k [(size_t)Bsz * Sctx * Cdim];         // K (B*S, C)
__device__ float g_v [(size_t)Bsz * Sctx * Cdim];         // V (B*S, C)
__device__ float g_stats[Bsz * NGROUPS * 2];              // (mean, rstd)
__device__ __nv_bfloat16 g_qwb[Cdim * Cdim];              // q_w bf16
__device__ __nv_bfloat16 g_owb[Cdim * Cdim];              // out_w bf16

__device__ __forceinline__ uint32_t smem_u32(const void* p) {
    uint32_t a;
    asm("{ .reg .u64 t; cvta.to.shared.u64 t, %1; cvt.u32.u64 %0, t; }"
        : "=r"(a) : "l"(p));
    return a;
}

// ============================================================
// GroupNorm statistics
// ============================================================
__global__ void gn_stats_kernel(const float* __restrict__ x) {
    int blk = blockIdx.x;
    int b = blk / NGROUPS, g = blk % NGROUPS;
    const float4* p = (const float4*)(x + ((size_t)b * Cdim + (size_t)g * CPG) * HWp);
    const int n4 = CPG * HWp / 4;
    float s = 0.f, sq = 0.f;
    for (int i = threadIdx.x; i < n4; i += blockDim.x) {
        float4 v = p[i];
        s  += v.x + v.y + v.z + v.w;
        sq += v.x * v.x + v.y * v.y + v.z * v.z + v.w * v.w;
    }
    __shared__ float ss[32], ssq[32];
    #pragma unroll
    for (int o = 16; o > 0; o >>= 1) {
        s  += __shfl_down_sync(0xffffffffu, s, o);
        sq += __shfl_down_sync(0xffffffffu, sq, o);
    }
    int wid = threadIdx.x >> 5, lid = threadIdx.x & 31;
    if (lid == 0) { ss[wid] = s; ssq[wid] = sq; }
    __syncthreads();
    if (wid == 0) {
        int nw = blockDim.x >> 5;
        s  = (lid < nw) ? ss[lid]  : 0.f;
        sq = (lid < nw) ? ssq[lid] : 0.f;
        #pragma unroll
        for (int o = 16; o > 0; o >>= 1) {
            s  += __shfl_down_sync(0xffffffffu, s, o);
            sq += __shfl_down_sync(0xffffffffu, sq, o);
        }
        if (lid == 0) {
            const float invn = 1.f / (float)(CPG * HWp);
            float mean = s * invn;
            float var  = sq * invn - mean * mean;
            g_stats[blk * 2]     = mean;
            g_stats[blk * 2 + 1] = rsqrtf(var + EPSV);
        }
    }
}

// ============================================================
// LayerNorm on context
// ============================================================
__global__ void ln_kernel(const float* __restrict__ ctx,
                          const float* __restrict__ w,
                          const float* __restrict__ bb) {
    int row = blockIdx.x;
    const float* xr = ctx + (size_t)row * CTXd;
    float s = 0.f, sq = 0.f;
    for (int i = threadIdx.x; i < CTXd; i += blockDim.x) {
        float v = xr[i];
        s += v; sq += v * v;
    }
    __shared__ float ss[32], ssq[32];
    __shared__ float smean, srstd;
    #pragma unroll
    for (int o = 16; o > 0; o >>= 1) {
        s  += __shfl_down_sync(0xffffffffu, s, o);
        sq += __shfl_down_sync(0xffffffffu, sq, o);
    }
    int wid = threadIdx.x >> 5, lid = threadIdx.x & 31;
    if (lid == 0) { ss[wid] = s; ssq[wid] = sq; }
    __syncthreads();
    if (wid == 0) {
        int nw = blockDim.x >> 5;
        s  = (lid < nw) ? ss[lid]  : 0.f;
        sq = (lid < nw) ? ssq[lid] : 0.f;
        #pragma unroll
        for (int o = 16; o > 0; o >>= 1) {
            s  += __shfl_down_sync(0xffffffffu, s, o);
            sq += __shfl_down_sync(0xffffffffu, sq, o);
        }
        if (lid == 0) {
            const float invn = 1.f / (float)CTXd;
            float mean = s * invn;
            float var  = sq * invn - mean * mean;
            smean = mean;
            srstd = rsqrtf(var + EPSV);
        }
    }
    __syncthreads();
    float mean = smean, rstd = srstd;
    for (int i = threadIdx.x; i < CTXd; i += blockDim.x) {
        g_cn[(size_t)row * CTXd + i] = (xr[i] - mean) * rstd * w[i] + bb[i];
    }
}

// ============================================================
// Weight bf16 conversion (q_w, out_w)
// ============================================================
__global__ void conv_w_kernel(const float* __restrict__ qw, const float* __restrict__ ow) {
    int i = blockIdx.x * blockDim.x + threadIdx.x;
    const int N = Cdim * Cdim;
    if (i < N) g_qwb[i] = __float2bfloat16(qw[i]);
    else       g_owb[i - N] = __float2bfloat16(ow[i - N]);
}

// ============================================================
// GN-apply + bf16 conversion of x -> g_xnb
// ============================================================
__global__ void conv_x_kernel(const float* __restrict__ x,
                              const float* __restrict__ gnw,
                              const float* __restrict__ gnb) {
    int bc = blockIdx.x;
    int b = bc >> 9, c = bc & 511;
    int g = c >> 4;
    float mean = g_stats[(b * NGROUPS + g) * 2];
    float rstd = g_stats[(b * NGROUPS + g) * 2 + 1];
    float a  = rstd * gnw[c];
    float bb = gnb[c] - mean * a;
    const float4* src = (const float4*)(x + (size_t)bc * HWp);
    __nv_bfloat162* dst = (__nv_bfloat162*)(g_xnb + (size_t)bc * HWp);
    for (int i = threadIdx.x; i < HWp / 4; i += blockDim.x) {
        float4 v = src[i];
        dst[2 * i]     = __floats2bfloat162_rn(v.x * a + bb, v.y * a + bb);
        dst[2 * i + 1] = __floats2bfloat162_rn(v.z * a + bb, v.w * a + bb);
    }
}

// ============================================================
// K/V projection (fp32, small)
// ============================================================
#define KV_BM 64
#define KV_BN 64
#define KV_BK 16
__global__ void kv_gemm(const float* __restrict__ kw, const float* __restrict__ kb,
                        const float* __restrict__ vw, const float* __restrict__ vb) {
    __shared__ float As[KV_BM][KV_BK + 1];
    __shared__ float Ws[KV_BN][KV_BK + 1];
    const float* W    = blockIdx.z ? vw : kw;
    const float* bias = blockIdx.z ? vb : kb;
    float*       out  = blockIdx.z ? g_v : g_k;
    const int NROWS = Bsz * Sctx;

    int n0 = blockIdx.x * KV_BM;
    int o0 = blockIdx.y * KV_BN;
    int tid = threadIdx.x;
    int tx = tid & 15, ty = tid >> 4;
    int lrow = tid >> 2;
    int lcol = (tid & 3) * 4;

    float acc[4][4] = {};
    for (int k0 = 0; k0 < CTXd; k0 += KV_BK) {
        int n = n0 + lrow;
        float4 av = (n < NROWS)
            ? *(const float4*)(g_cn + (size_t)n * CTXd + k0 + lcol)
            : make_float4(0.f, 0.f, 0.f, 0.f);
        As[lrow][lcol] = av.x; As[lrow][lcol + 1] = av.y;
        As[lrow][lcol + 2] = av.z; As[lrow][lcol + 3] = av.w;
        float4 wv = *(const float4*)(W + (size_t)(o0 + lrow) * CTXd + k0 + lcol);
        Ws[lrow][lcol] = wv.x; Ws[lrow][lcol + 1] = wv.y;
        Ws[lrow][lcol + 2] = wv.z; Ws[lrow][lcol + 3] = wv.w;
        __syncthreads();
        #pragma unroll
        for (int k = 0; k < KV_BK; k++) {
            float af[4], wf[4];
            #pragma unroll
            for (int i = 0; i < 4; i++) af[i] = As[ty * 4 + i][k];
            #pragma unroll
            for (int j = 0; j < 4; j++) wf[j] = Ws[tx * 4 + j][k];
            #pragma unroll
            for (int i = 0; i < 4; i++)
                #pragma unroll
                for (int j = 0; j < 4; j++)
                    acc[i][j] += af[i] * wf[j];
        }
        __syncthreads();
    }
    #pragma unroll
    for (int i = 0; i < 4; i++) {
        int n = n0 + ty * 4 + i;
        if (n >= NROWS) continue;
        #pragma unroll
        for (int j = 0; j < 4; j++) {
            int o = o0 + tx * 4 + j;
            out[(size_t)n * Cdim + o] = acc[i][j] + bias[o];
        }
    }
}

// ============================================================
// bf16 mma.sync GEMM: D[o,p] = sum_c W[o,c] * X[c,p] (+bias,+residual)
// CTA tile M=128 (o) x N=128 (p) x K=32; 256 threads = 8 warps (2x4),
// warp tile 64x32 via m16n8k16. Double-buffered smem, padded strides.
// grid: (HWp/128, Cdim/128, B)
// ============================================================
#define A_STRIDE 40   // halfwords per A smem row (32 + 8 pad)
#define B_STRIDE 136  // halfwords per B smem row (128 + 8 pad)
#define A_BUF_BYTES (128 * A_STRIDE * 2)
#define B_BUF_BYTES (32 * B_STRIDE * 2)

__global__ void __launch_bounds__(256, 2)
mma_gemm(const __nv_bfloat16* __restrict__ Wb,
         const __nv_bfloat16* __restrict__ Xb,
         const float* __restrict__ bias,
         const float* __restrict__ residual,
         float* __restrict__ out) {
    __shared__ __align__(16) char smem_[2 * A_BUF_BYTES + 2 * B_BUF_BYTES];

    const int tid  = threadIdx.x;
    const int warp = tid >> 5, lane = tid & 31;
    const int wm = warp >> 2, wn = warp & 3;
    const int p0 = blockIdx.x * 128;
    const int o0 = blockIdx.y * 128;
    const int b  = blockIdx.z;
    const __nv_bfloat16* Xbb = Xb + (size_t)b * Cdim * HWp;

    const uint32_t sbase = smem_u32(smem_);
    const uint32_t sA0 = sbase;
    const uint32_t sB0 = sbase + 2 * A_BUF_BYTES;

    // global load coords
    const int a_ld_row = tid >> 2;            // 0..63, +64 for second
    const int a_ld_col = (tid & 3) * 8;       // 0,8,16,24
    const int b_ld_row = tid >> 4;            // 0..15, +16 for second
    const int b_ld_col = (tid & 15) * 8;      // 0..120

    // ldmatrix lane addresses (byte offsets within a buffer)
    // A: row = wm*64 + mt*16 + (lane&15), col = (lane>>4)*8 (+kk*16)
    const uint32_t a_lm_base =
        ((wm * 64 + (lane & 15)) * A_STRIDE + (lane >> 4) * 8) * 2;
    // B: krow = (lane&15) (+kk*16), col = wn*32 (+nt*8)
    const uint32_t b_lm_base = ((lane & 15) * B_STRIDE + wn * 32) * 2;

    float acc[4][4][4] = {};

    // ---- preload tile 0 ----
    {
        const int k0 = 0;
        #pragma unroll
        for (int j = 0; j < 2; j++) {
            int r = a_ld_row + j * 64;
            uint4 v = *(const uint4*)(Wb + (size_t)(o0 + r) * Cdim + k0 + a_ld_col);
            *(uint4*)(smem_ + (r * A_STRIDE + a_ld_col) * 2) = v;
        }
        #pragma unroll
        for (int j = 0; j < 2; j++) {
            int r = b_ld_row + j * 16;
            uint4 v = *(const uint4*)(Xbb + (size_t)(k0 + r) * HWp + p0 + b_ld_col);
            *(uint4*)(smem_ + 2 * A_BUF_BYTES + (r * B_STRIDE + b_ld_col) * 2) = v;
        }
    }
    __syncthreads();

    #pragma unroll 1
    for (int it = 0; it < 16; it++) {
        // prefetch next tile into registers
        uint4 pa[2], pb[2];
        const int kn = (it + 1) * 32;
        if (it < 15) {
            #pragma unroll
            for (int j = 0; j < 2; j++) {
                int r = a_ld_row + j * 64;
                pa[j] = *(const uint4*)(Wb + (size_t)(o0 + r) * Cdim + kn + a_ld_col);
            }
            #pragma unroll
            for (int j = 0; j < 2; j++) {
                int r = b_ld_row + j * 16;
                pb[j] = *(const uint4*)(Xbb + (size_t)(kn + r) * HWp + p0 + b_ld_col);
            }
        }

        const uint32_t aBuf = sA0 + (it & 1) * A_BUF_BYTES;
        const uint32_t bBuf = sB0 + (it & 1) * B_BUF_BYTES;

        #pragma unroll
        for (int kk = 0; kk < 2; kk++) {
            uint32_t af[4][4];
            #pragma unroll
            for (int mt = 0; mt < 4; mt++) {
                uint32_t addr = aBuf + a_lm_base + (mt * 16 * A_STRIDE + kk * 16) * 2;
                asm volatile(
                    "ldmatrix.sync.aligned.m8n8.x4.shared.b16 {%0,%1,%2,%3}, [%4];"
                    : "=r"(af[mt][0]), "=r"(af[mt][1]), "=r"(af[mt][2]), "=r"(af[mt][3])
                    : "r"(addr));
            }
            uint32_t bf[4][2];
            #pragma unroll
            for (int nt = 0; nt < 4; nt++) {
                uint32_t addr = bBuf + b_lm_base + (kk * 16 * B_STRIDE + nt * 8) * 2;
                asm volatile(
                    "ldmatrix.sync.aligned.m8n8.x2.trans.shared.b16 {%0,%1}, [%2];"
                    : "=r"(bf[nt][0]), "=r"(bf[nt][1]) : "r"(addr));
            }
            #pragma unroll
            for (int mt = 0; mt < 4; mt++)
                #pragma unroll
                for (int nt = 0; nt < 4; nt++) {
                    asm volatile(
                        "mma.sync.aligned.m16n8k16.row.col.f32.bf16.bf16.f32 "
                        "{%0,%1,%2,%3}, {%4,%5,%6,%7}, {%8,%9}, {%0,%1,%2,%3};"
                        : "+f"(acc[mt][nt][0]), "+f"(acc[mt][nt][1]),
                          "+f"(acc[mt][nt][2]), "+f"(acc[mt][nt][3])
                        : "r"(af[mt][0]), "r"(af[mt][1]), "r"(af[mt][2]), "r"(af[mt][3]),
                          "r"(bf[nt][0]), "r"(bf[nt][1]));
                }
        }

        if (it < 15) {
            char* dA = smem_ + ((it + 1) & 1) * A_BUF_BYTES;
            char* dB = smem_ + 2 * A_BUF_BYTES + ((it + 1) & 1) * B_BUF_BYTES;
            #pragma unroll
            for (int j = 0; j < 2; j++) {
                int r = a_ld_row + j * 64;
                *(uint4*)(dA + (r * A_STRIDE + a_ld_col) * 2) = pa[j];
            }
            #pragma unroll
            for (int j = 0; j < 2; j++) {
                int r = b_ld_row + j * 16;
                *(uint4*)(dB + (r * B_STRIDE + b_ld_col) * 2) = pb[j];
            }
        }
        __syncthreads();
    }

    // ---- epilogue ----
    const int row_base = o0 + wm * 64 + (lane >> 2);
    const int col_base = p0 + wn * 32 + (lane & 3) * 2;
    #pragma unroll
    for (int mt = 0; mt < 4; mt++) {
        #pragma unroll
        for (int half = 0; half < 2; half++) {
            int row = row_base + mt * 16 + half * 8;
            float bi = bias[row];
            size_t rb = ((size_t)b * Cdim + row) * HWp;
            #pragma unroll
            for (int nt = 0; nt < 4; nt++) {
                int col = col_base + nt * 8;
                float2 r;
                r.x = acc[mt][nt][half * 2]     + bi;
                r.y = acc[mt][nt][half * 2 + 1] + bi;
                if (residual) {
                    float2 rv = *(const float2*)(residual + rb + col);
                    r.x += rv.x; r.y += rv.y;
                }
                *(float2*)(out + rb + col) = r;
            }
        }
    }
}

// ============================================================
// Fused attention (fp32 compute, bf16 output)
// ============================================================
__global__ void attn_kernel() {
    __shared__ float ks[Sctx * HD];
    __shared__ float ps[Sctx * 64];
    int b = blockIdx.z, h = blockIdx.y;
    int p0 = blockIdx.x * 64;
    int tid = threadIdx.x;

    for (int i = tid; i < Sctx * HD; i += 64) {
        int s = i >> 6, d = i & 63;
        ks[i] = g_k[(size_t)(b * Sctx + s) * Cdim + h * HD + d];
    }
    float qreg[64];
    const float* qp = g_q + (size_t)b * Cdim * HWp + (size_t)h * HD * HWp + p0 + tid;
    #pragma unroll
    for (int d = 0; d < 64; d++) qreg[d] = qp[(size_t)d * HWp];
    __syncthreads();

    for (int s = 0; s < Sctx; s++) {
        const float4* kk = (const float4*)(ks + s * 64);
        float a = 0.f;
        #pragma unroll
        for (int d4 = 0; d4 < 16; d4++) {
            float4 k4 = kk[d4];
            a += qreg[d4 * 4] * k4.x + qreg[d4 * 4 + 1] * k4.y
               + qreg[d4 * 4 + 2] * k4.z + qreg[d4 * 4 + 3] * k4.w;
        }
        ps[s * 64 + tid] = a * 0.125f;
    }
    float m = -1e30f;
    for (int s = 0; s < Sctx; s++) m = fmaxf(m, ps[s * 64 + tid]);
    float sum = 0.f;
    for (int s = 0; s < Sctx; s++) {
        float e = __expf(ps[s * 64 + tid] - m);
        ps[s * 64 + tid] = e;
        sum += e;
    }
    float inv = 1.f / sum;
    __syncthreads();

    for (int i = tid; i < Sctx * HD; i += 64) {
        int s = i >> 6, d = i & 63;
        ks[i] = g_v[(size_t)(b * Sctx + s) * Cdim + h * HD + d];
    }
    __syncthreads();

    float oacc[64];
    #pragma unroll
    for (int d = 0; d < 64; d++) oacc[d] = 0.f;
    for (int s = 0; s < Sctx; s++) {
        float pw = ps[s * 64 + tid];
        const float4* vv = (const float4*)(ks + s * 64);
        #pragma unroll
        for (int d4 = 0; d4 < 16; d4++) {
            float4 v4 = vv[d4];
            oacc[d4 * 4]     += pw * v4.x;
            oacc[d4 * 4 + 1] += pw * v4.y;
            oacc[d4 * 4 + 2] += pw * v4.z;
            oacc[d4 * 4 + 3] += pw * v4.w;
        }
    }
    __nv_bfloat16* op = g_aob + (size_t)b * Cdim * HWp + (size_t)h * HD * HWp + p0 + tid;
    #pragma unroll
    for (int d = 0; d < 64; d++) op[(size_t)d * HWp] = __float2bfloat16(oacc[d] * inv);
}

// ============================================================
extern "C" void kernel_launch(void* const* d_in, const int* in_sizes, int n_in,
                              void* d_out, int out_size) {
    const float* x       = (const float*)d_in[0];
    const float* context = (const float*)d_in[1];
    const float* gn_w    = (const float*)d_in[2];
    const float* gn_b    = (const float*)d_in[3];
    const float* ln_w    = (const float*)d_in[4];
    const float* ln_b    = (const float*)d_in[5];
    const float* q_w     = (const float*)d_in[6];
    const float* q_b     = (const float*)d_in[7];
    const float* k_w     = (const float*)d_in[8];
    const float* k_b     = (const float*)d_in[9];
    const float* v_w     = (const float*)d_in[10];
    const float* v_b     = (const float*)d_in[11];
    const float* out_w   = (const float*)d_in[12];
    const float* out_b   = (const float*)d_in[13];
    float* out = (float*)d_out;

    float *qptr = nullptr;
    __nv_bfloat16 *xnb = nullptr, *aob = nullptr, *qwb = nullptr, *owb = nullptr;
    cudaGetSymbolAddress((void**)&qptr, g_q);
    cudaGetSymbolAddress((void**)&xnb, g_xnb);
    cudaGetSymbolAddress((void**)&aob, g_aob);
    cudaGetSymbolAddress((void**)&qwb, g_qwb);
    cudaGetSymbolAddress((void**)&owb, g_owb);

    gn_stats_kernel<<<Bsz * NGROUPS, 256>>>(x);
    ln_kernel<<<Bsz * Sctx, 256>>>(context, ln_w, ln_b);
    conv_w_kernel<<<(2 * Cdim * Cdim) / 512, 512>>>(q_w, out_w);
    conv_x_kernel<<<Bsz * Cdim, 256>>>(x, gn_w, gn_b);
    kv_gemm<<<dim3((Bsz * Sctx + KV_BM - 1) / KV_BM, Cdim / KV_BN, 2), 256>>>(
        k_w, k_b, v_w, v_b);
    // Q projection (tensor cores): g_q = q_w @ GN(x)
    mma_gemm<<<dim3(HWp / 128, Cdim / 128, Bsz), 256>>>(qwb, xnb, q_b, nullptr, qptr);
    attn_kernel<<<dim3(HWp / 64, NHEADS, Bsz), 64>>>();
    // Out projection + residual
    mma_gemm<<<dim3(HWp / 128, Cdim / 128, Bsz), 256>>>(owb, aob, out_b, x, out);
}

// round 5
// speedup vs baseline: 3.9052x; 1.4824x over previous
#include <cuda_runtime.h>
#include <cuda_bf16.h>
#include <cstdint>

#define Bsz 16
#define Cdim 512
#define HWp 4096
#define Sctx 77
#define CTXd 768
#define NHEADS 8
#define HD 64
#define NGROUPS 32
#define CPG 16
#define EPSV 1e-5f

// ---- scratch (static device globals; no runtime allocation) ----
__device__ __nv_bfloat16 g_qb [(size_t)Bsz * Cdim * HWp]; // Q  (B, C, HW) bf16
__device__ __nv_bfloat16 g_xnb[(size_t)Bsz * Cdim * HWp]; // GN(x) bf16
__device__ __nv_bfloat16 g_aob[(size_t)Bsz * Cdim * HWp]; // attn out bf16
__device__ float g_cn[(size_t)Bsz * Sctx * CTXd];         // layernormed context
__device__ float g_k [(size_t)Bsz * Sctx * Cdim];         // K (B*S, C)
__device__ float g_v [(size_t)Bsz * Sctx * Cdim];         // V (B*S, C)
__device__ float g_stats[Bsz * NGROUPS * 2];              // (mean, rstd)
__device__ __nv_bfloat16 g_qwb[Cdim * Cdim];              // q_w bf16
__device__ __nv_bfloat16 g_owb[Cdim * Cdim];              // out_w bf16

__device__ __forceinline__ uint32_t smem_u32(const void* p) {
    uint32_t a;
    asm("{ .reg .u64 t; cvta.to.shared.u64 t, %1; cvt.u32.u64 %0, t; }"
        : "=r"(a) : "l"(p));
    return a;
}
__device__ __forceinline__ uint32_t pack_bf16(float lo, float hi) {
    __nv_bfloat162 p = __floats2bfloat162_rn(lo, hi);
    return *reinterpret_cast<uint32_t*>(&p);
}

// ============================================================
// GroupNorm statistics
// ============================================================
__global__ void gn_stats_kernel(const float* __restrict__ x) {
    int blk = blockIdx.x;
    int b = blk / NGROUPS, g = blk % NGROUPS;
    const float4* p = (const float4*)(x + ((size_t)b * Cdim + (size_t)g * CPG) * HWp);
    const int n4 = CPG * HWp / 4;
    float s = 0.f, sq = 0.f;
    for (int i = threadIdx.x; i < n4; i += blockDim.x) {
        float4 v = p[i];
        s  += v.x + v.y + v.z + v.w;
        sq += v.x * v.x + v.y * v.y + v.z * v.z + v.w * v.w;
    }
    __shared__ float ss[32], ssq[32];
    #pragma unroll
    for (int o = 16; o > 0; o >>= 1) {
        s  += __shfl_down_sync(0xffffffffu, s, o);
        sq += __shfl_down_sync(0xffffffffu, sq, o);
    }
    int wid = threadIdx.x >> 5, lid = threadIdx.x & 31;
    if (lid == 0) { ss[wid] = s; ssq[wid] = sq; }
    __syncthreads();
    if (wid == 0) {
        int nw = blockDim.x >> 5;
        s  = (lid < nw) ? ss[lid]  : 0.f;
        sq = (lid < nw) ? ssq[lid] : 0.f;
        #pragma unroll
        for (int o = 16; o > 0; o >>= 1) {
            s  += __shfl_down_sync(0xffffffffu, s, o);
            sq += __shfl_down_sync(0xffffffffu, sq, o);
        }
        if (lid == 0) {
            const float invn = 1.f / (float)(CPG * HWp);
            float mean = s * invn;
            float var  = sq * invn - mean * mean;
            g_stats[blk * 2]     = mean;
            g_stats[blk * 2 + 1] = rsqrtf(var + EPSV);
        }
    }
}

// ============================================================
// LayerNorm on context
// ============================================================
__global__ void ln_kernel(const float* __restrict__ ctx,
                          const float* __restrict__ w,
                          const float* __restrict__ bb) {
    int row = blockIdx.x;
    const float* xr = ctx + (size_t)row * CTXd;
    float s = 0.f, sq = 0.f;
    for (int i = threadIdx.x; i < CTXd; i += blockDim.x) {
        float v = xr[i];
        s += v; sq += v * v;
    }
    __shared__ float ss[32], ssq[32];
    __shared__ float smean, srstd;
    #pragma unroll
    for (int o = 16; o > 0; o >>= 1) {
        s  += __shfl_down_sync(0xffffffffu, s, o);
        sq += __shfl_down_sync(0xffffffffu, sq, o);
    }
    int wid = threadIdx.x >> 5, lid = threadIdx.x & 31;
    if (lid == 0) { ss[wid] = s; ssq[wid] = sq; }
    __syncthreads();
    if (wid == 0) {
        int nw = blockDim.x >> 5;
        s  = (lid < nw) ? ss[lid]  : 0.f;
        sq = (lid < nw) ? ssq[lid] : 0.f;
        #pragma unroll
        for (int o = 16; o > 0; o >>= 1) {
            s  += __shfl_down_sync(0xffffffffu, s, o);
            sq += __shfl_down_sync(0xffffffffu, sq, o);
        }
        if (lid == 0) {
            const float invn = 1.f / (float)CTXd;
            float mean = s * invn;
            float var  = sq * invn - mean * mean;
            smean = mean;
            srstd = rsqrtf(var + EPSV);
        }
    }
    __syncthreads();
    float mean = smean, rstd = srstd;
    for (int i = threadIdx.x; i < CTXd; i += blockDim.x) {
        g_cn[(size_t)row * CTXd + i] = (xr[i] - mean) * rstd * w[i] + bb[i];
    }
}

// ============================================================
// Weight bf16 conversion (q_w, out_w)
// ============================================================
__global__ void conv_w_kernel(const float* __restrict__ qw, const float* __restrict__ ow) {
    int i = blockIdx.x * blockDim.x + threadIdx.x;
    const int N = Cdim * Cdim;
    if (i < N) g_qwb[i] = __float2bfloat16(qw[i]);
    else       g_owb[i - N] = __float2bfloat16(ow[i - N]);
}

// ============================================================
// GN-apply + bf16 conversion of x -> g_xnb
// ============================================================
__global__ void conv_x_kernel(const float* __restrict__ x,
                              const float* __restrict__ gnw,
                              const float* __restrict__ gnb) {
    int bc = blockIdx.x;
    int b = bc >> 9, c = bc & 511;
    int g = c >> 4;
    float mean = g_stats[(b * NGROUPS + g) * 2];
    float rstd = g_stats[(b * NGROUPS + g) * 2 + 1];
    float a  = rstd * gnw[c];
    float bb = gnb[c] - mean * a;
    const float4* src = (const float4*)(x + (size_t)bc * HWp);
    __nv_bfloat162* dst = (__nv_bfloat162*)(g_xnb + (size_t)bc * HWp);
    for (int i = threadIdx.x; i < HWp / 4; i += blockDim.x) {
        float4 v = src[i];
        dst[2 * i]     = __floats2bfloat162_rn(v.x * a + bb, v.y * a + bb);
        dst[2 * i + 1] = __floats2bfloat162_rn(v.z * a + bb, v.w * a + bb);
    }
}

// ============================================================
// K/V projection (fp32, small)
// ============================================================
#define KV_BM 64
#define KV_BN 64
#define KV_BK 16
__global__ void kv_gemm(const float* __restrict__ kw, const float* __restrict__ kb,
                        const float* __restrict__ vw, const float* __restrict__ vb) {
    __shared__ float As[KV_BM][KV_BK + 1];
    __shared__ float Ws[KV_BN][KV_BK + 1];
    const float* W    = blockIdx.z ? vw : kw;
    const float* bias = blockIdx.z ? vb : kb;
    float*       out  = blockIdx.z ? g_v : g_k;
    const int NROWS = Bsz * Sctx;

    int n0 = blockIdx.x * KV_BM;
    int o0 = blockIdx.y * KV_BN;
    int tid = threadIdx.x;
    int tx = tid & 15, ty = tid >> 4;
    int lrow = tid >> 2;
    int lcol = (tid & 3) * 4;

    float acc[4][4] = {};
    for (int k0 = 0; k0 < CTXd; k0 += KV_BK) {
        int n = n0 + lrow;
        float4 av = (n < NROWS)
            ? *(const float4*)(g_cn + (size_t)n * CTXd + k0 + lcol)
            : make_float4(0.f, 0.f, 0.f, 0.f);
        As[lrow][lcol] = av.x; As[lrow][lcol + 1] = av.y;
        As[lrow][lcol + 2] = av.z; As[lrow][lcol + 3] = av.w;
        float4 wv = *(const float4*)(W + (size_t)(o0 + lrow) * CTXd + k0 + lcol);
        Ws[lrow][lcol] = wv.x; Ws[lrow][lcol + 1] = wv.y;
        Ws[lrow][lcol + 2] = wv.z; Ws[lrow][lcol + 3] = wv.w;
        __syncthreads();
        #pragma unroll
        for (int k = 0; k < KV_BK; k++) {
            float af[4], wf[4];
            #pragma unroll
            for (int i = 0; i < 4; i++) af[i] = As[ty * 4 + i][k];
            #pragma unroll
            for (int j = 0; j < 4; j++) wf[j] = Ws[tx * 4 + j][k];
            #pragma unroll
            for (int i = 0; i < 4; i++)
                #pragma unroll
                for (int j = 0; j < 4; j++)
                    acc[i][j] += af[i] * wf[j];
        }
        __syncthreads();
    }
    #pragma unroll
    for (int i = 0; i < 4; i++) {
        int n = n0 + ty * 4 + i;
        if (n >= NROWS) continue;
        #pragma unroll
        for (int j = 0; j < 4; j++) {
            int o = o0 + tx * 4 + j;
            out[(size_t)n * Cdim + o] = acc[i][j] + bias[o];
        }
    }
}

// ============================================================
// bf16 mma.sync GEMM: D[o,p] = sum_c W[o,c] * X[c,p] (+bias,+residual)
// Templated output type: fp32 (+residual) or bf16.
// ============================================================
#define A_STRIDE 40
#define B_STRIDE 136
#define A_BUF_BYTES (128 * A_STRIDE * 2)
#define B_BUF_BYTES (32 * B_STRIDE * 2)

template <bool BF16OUT>
__global__ void __launch_bounds__(256, 2)
mma_gemm(const __nv_bfloat16* __restrict__ Wb,
         const __nv_bfloat16* __restrict__ Xb,
         const float* __restrict__ bias,
         const float* __restrict__ residual,
         void* __restrict__ outv) {
    __shared__ __align__(16) char smem_[2 * A_BUF_BYTES + 2 * B_BUF_BYTES];

    const int tid  = threadIdx.x;
    const int warp = tid >> 5, lane = tid & 31;
    const int wm = warp >> 2, wn = warp & 3;
    const int p0 = blockIdx.x * 128;
    const int o0 = blockIdx.y * 128;
    const int b  = blockIdx.z;
    const __nv_bfloat16* Xbb = Xb + (size_t)b * Cdim * HWp;

    const uint32_t sbase = smem_u32(smem_);
    const uint32_t sA0 = sbase;
    const uint32_t sB0 = sbase + 2 * A_BUF_BYTES;

    const int a_ld_row = tid >> 2;
    const int a_ld_col = (tid & 3) * 8;
    const int b_ld_row = tid >> 4;
    const int b_ld_col = (tid & 15) * 8;

    const uint32_t a_lm_base =
        ((wm * 64 + (lane & 15)) * A_STRIDE + (lane >> 4) * 8) * 2;
    const uint32_t b_lm_base = ((lane & 15) * B_STRIDE + wn * 32) * 2;

    float acc[4][4][4] = {};

    {
        #pragma unroll
        for (int j = 0; j < 2; j++) {
            int r = a_ld_row + j * 64;
            uint4 v = *(const uint4*)(Wb + (size_t)(o0 + r) * Cdim + a_ld_col);
            *(uint4*)(smem_ + (r * A_STRIDE + a_ld_col) * 2) = v;
        }
        #pragma unroll
        for (int j = 0; j < 2; j++) {
            int r = b_ld_row + j * 16;
            uint4 v = *(const uint4*)(Xbb + (size_t)r * HWp + p0 + b_ld_col);
            *(uint4*)(smem_ + 2 * A_BUF_BYTES + (r * B_STRIDE + b_ld_col) * 2) = v;
        }
    }
    __syncthreads();

    #pragma unroll 1
    for (int it = 0; it < 16; it++) {
        uint4 pa[2], pb[2];
        const int kn = (it + 1) * 32;
        if (it < 15) {
            #pragma unroll
            for (int j = 0; j < 2; j++) {
                int r = a_ld_row + j * 64;
                pa[j] = *(const uint4*)(Wb + (size_t)(o0 + r) * Cdim + kn + a_ld_col);
            }
            #pragma unroll
            for (int j = 0; j < 2; j++) {
                int r = b_ld_row + j * 16;
                pb[j] = *(const uint4*)(Xbb + (size_t)(kn + r) * HWp + p0 + b_ld_col);
            }
        }

        const uint32_t aBuf = sA0 + (it & 1) * A_BUF_BYTES;
        const uint32_t bBuf = sB0 + (it & 1) * B_BUF_BYTES;

        #pragma unroll
        for (int kk = 0; kk < 2; kk++) {
            uint32_t af[4][4];
            #pragma unroll
            for (int mt = 0; mt < 4; mt++) {
                uint32_t addr = aBuf + a_lm_base + (mt * 16 * A_STRIDE + kk * 16) * 2;
                asm volatile(
                    "ldmatrix.sync.aligned.m8n8.x4.shared.b16 {%0,%1,%2,%3}, [%4];"
                    : "=r"(af[mt][0]), "=r"(af[mt][1]), "=r"(af[mt][2]), "=r"(af[mt][3])
                    : "r"(addr));
            }
            uint32_t bf[4][2];
            #pragma unroll
            for (int nt = 0; nt < 4; nt++) {
                uint32_t addr = bBuf + b_lm_base + (kk * 16 * B_STRIDE + nt * 8) * 2;
                asm volatile(
                    "ldmatrix.sync.aligned.m8n8.x2.trans.shared.b16 {%0,%1}, [%2];"
                    : "=r"(bf[nt][0]), "=r"(bf[nt][1]) : "r"(addr));
            }
            #pragma unroll
            for (int mt = 0; mt < 4; mt++)
                #pragma unroll
                for (int nt = 0; nt < 4; nt++) {
                    asm volatile(
                        "mma.sync.aligned.m16n8k16.row.col.f32.bf16.bf16.f32 "
                        "{%0,%1,%2,%3}, {%4,%5,%6,%7}, {%8,%9}, {%0,%1,%2,%3};"
                        : "+f"(acc[mt][nt][0]), "+f"(acc[mt][nt][1]),
                          "+f"(acc[mt][nt][2]), "+f"(acc[mt][nt][3])
                        : "r"(af[mt][0]), "r"(af[mt][1]), "r"(af[mt][2]), "r"(af[mt][3]),
                          "r"(bf[nt][0]), "r"(bf[nt][1]));
                }
        }

        if (it < 15) {
            char* dA = smem_ + ((it + 1) & 1) * A_BUF_BYTES;
            char* dB = smem_ + 2 * A_BUF_BYTES + ((it + 1) & 1) * B_BUF_BYTES;
            #pragma unroll
            for (int j = 0; j < 2; j++) {
                int r = a_ld_row + j * 64;
                *(uint4*)(dA + (r * A_STRIDE + a_ld_col) * 2) = pa[j];
            }
            #pragma unroll
            for (int j = 0; j < 2; j++) {
                int r = b_ld_row + j * 16;
                *(uint4*)(dB + (r * B_STRIDE + b_ld_col) * 2) = pb[j];
            }
        }
        __syncthreads();
    }

    const int row_base = o0 + wm * 64 + (lane >> 2);
    const int col_base = p0 + wn * 32 + (lane & 3) * 2;
    #pragma unroll
    for (int mt = 0; mt < 4; mt++) {
        #pragma unroll
        for (int half = 0; half < 2; half++) {
            int row = row_base + mt * 16 + half * 8;
            float bi = bias[row];
            size_t rb = ((size_t)b * Cdim + row) * HWp;
            #pragma unroll
            for (int nt = 0; nt < 4; nt++) {
                int col = col_base + nt * 8;
                float rx = acc[mt][nt][half * 2]     + bi;
                float ry = acc[mt][nt][half * 2 + 1] + bi;
                if (BF16OUT) {
                    __nv_bfloat16* outb = (__nv_bfloat16*)outv;
                    *(__nv_bfloat162*)(outb + rb + col) = __floats2bfloat162_rn(rx, ry);
                } else {
                    float* outf = (float*)outv;
                    if (residual) {
                        float2 rv = *(const float2*)(residual + rb + col);
                        rx += rv.x; ry += rv.y;
                    }
                    float2 r; r.x = rx; r.y = ry;
                    *(float2*)(outf + rb + col) = r;
                }
            }
        }
    }
}

// ============================================================
// Tensor-core flash attention: block = (b, h, 128-pixel tile)
// S = Q(128x64) @ K^T(64x80pad) ; softmax in regs ; O = P @ V(80x64)
// 128 threads = 4 warps, each warp owns 32 rows (px).
// ============================================================
#define QS_STR 72    // halfwords; 144B = 9*16 -> ldmatrix conflict-free
#define KS_STR 88    // 176B = 11*16
#define VS_STR 72    // 144B
#define OD_STR 136   // 272B = 17*16
#define SPAD 80

__global__ void __launch_bounds__(128)
attn_mma_kernel() {
    __shared__ __align__(16) __nv_bfloat16 sQ[128 * QS_STR];  // reused as O [64][OD_STR]
    __shared__ __align__(16) __nv_bfloat16 sK[64 * KS_STR];   // K^T [d][s]
    __shared__ __align__(16) __nv_bfloat16 sV[SPAD * VS_STR]; // V [s][d]

    const int tid = threadIdx.x;
    const int warp = tid >> 5, lane = tid & 31;
    const int b = blockIdx.z, h = blockIdx.y;
    const int p0 = blockIdx.x * 128;
    const int ch0 = h * HD;

    // ---- stage Q [px][d] (transpose from d-major global) ----
    const __nv_bfloat16* qg = g_qb + ((size_t)b * Cdim + ch0) * HWp + p0;
    #pragma unroll 4
    for (int i = tid; i < 128 * 64; i += 128) {
        int d = i >> 7, px = i & 127;
        sQ[px * QS_STR + d] = qg[(size_t)d * HWp + px];
    }
    // ---- stage K^T [d][s], zero pad s=77..79 ----
    const float* kg = g_k + (size_t)b * Sctx * Cdim + ch0;
    #pragma unroll 4
    for (int i = tid; i < 77 * 64; i += 128) {
        int s = i >> 6, d = i & 63;
        sK[d * KS_STR + s] = __float2bfloat16(kg[(size_t)s * Cdim + d]);
    }
    for (int i = tid; i < 3 * 64; i += 128) {
        int s = 77 + (i >> 6), d = i & 63;
        sK[d * KS_STR + s] = __float2bfloat16(0.f);
    }
    // ---- stage V [s][d], zero rows 77..79 ----
    const float* vg = g_v + (size_t)b * Sctx * Cdim + ch0;
    #pragma unroll 4
    for (int i = tid; i < SPAD * 64; i += 128) {
        int s = i >> 6, d = i & 63;
        float v = (s < Sctx) ? vg[(size_t)s * Cdim + d] : 0.f;
        sV[s * VS_STR + d] = __float2bfloat16(v);
    }
    __syncthreads();

    const uint32_t qbase = smem_u32(sQ);
    const uint32_t kbase = smem_u32(sK);
    const uint32_t vbase = smem_u32(sV);

    // ---- S = Q @ K^T : M=128(warp:32) x N=80 x K=64 ----
    float c[2][10][4];
    #pragma unroll
    for (int mt = 0; mt < 2; mt++)
        #pragma unroll
        for (int nt = 0; nt < 10; nt++)
            #pragma unroll
            for (int r = 0; r < 4; r++) c[mt][nt][r] = 0.f;

    const uint32_t a_lm = qbase +
        ((warp * 32 + (lane & 15)) * QS_STR + (lane >> 4) * 8) * 2;

    #pragma unroll
    for (int kk = 0; kk < 4; kk++) {
        uint32_t af[2][4];
        #pragma unroll
        for (int mt = 0; mt < 2; mt++) {
            uint32_t addr = a_lm + (mt * 16 * QS_STR + kk * 16) * 2;
            asm volatile(
                "ldmatrix.sync.aligned.m8n8.x4.shared.b16 {%0,%1,%2,%3}, [%4];"
                : "=r"(af[mt][0]), "=r"(af[mt][1]), "=r"(af[mt][2]), "=r"(af[mt][3])
                : "r"(addr));
        }
        uint32_t bf[10][2];
        #pragma unroll
        for (int nt = 0; nt < 10; nt++) {
            uint32_t addr = kbase + ((kk * 16 + (lane & 15)) * KS_STR + nt * 8) * 2;
            asm volatile(
                "ldmatrix.sync.aligned.m8n8.x2.trans.shared.b16 {%0,%1}, [%2];"
                : "=r"(bf[nt][0]), "=r"(bf[nt][1]) : "r"(addr));
        }
        #pragma unroll
        for (int mt = 0; mt < 2; mt++)
            #pragma unroll
            for (int nt = 0; nt < 10; nt++) {
                asm volatile(
                    "mma.sync.aligned.m16n8k16.row.col.f32.bf16.bf16.f32 "
                    "{%0,%1,%2,%3}, {%4,%5,%6,%7}, {%8,%9}, {%0,%1,%2,%3};"
                    : "+f"(c[mt][nt][0]), "+f"(c[mt][nt][1]),
                      "+f"(c[mt][nt][2]), "+f"(c[mt][nt][3])
                    : "r"(af[mt][0]), "r"(af[mt][1]), "r"(af[mt][2]), "r"(af[mt][3]),
                      "r"(bf[nt][0]), "r"(bf[nt][1]));
            }
    }
    __syncthreads();  // done reading sQ (reused as O below)

    // ---- softmax (rows owned per lane-quad) + pack P to bf16 in regs ----
    const float scale = 0.125f;  // HD^-0.5
    uint32_t pu[2][10][2];
    float iv[2][2];
    #pragma unroll
    for (int mt = 0; mt < 2; mt++) {
        float mx0 = -1e30f, mx1 = -1e30f;
        #pragma unroll
        for (int nt = 0; nt < 10; nt++) {
            int col = nt * 8 + (lane & 3) * 2;
            c[mt][nt][0] = (col     < Sctx) ? c[mt][nt][0] * scale : -1e30f;
            c[mt][nt][1] = (col + 1 < Sctx) ? c[mt][nt][1] * scale : -1e30f;
            c[mt][nt][2] = (col     < Sctx) ? c[mt][nt][2] * scale : -1e30f;
            c[mt][nt][3] = (col + 1 < Sctx) ? c[mt][nt][3] * scale : -1e30f;
            mx0 = fmaxf(mx0, fmaxf(c[mt][nt][0], c[mt][nt][1]));
            mx1 = fmaxf(mx1, fmaxf(c[mt][nt][2], c[mt][nt][3]));
        }
        mx0 = fmaxf(mx0, __shfl_xor_sync(0xffffffffu, mx0, 1));
        mx0 = fmaxf(mx0, __shfl_xor_sync(0xffffffffu, mx0, 2));
        mx1 = fmaxf(mx1, __shfl_xor_sync(0xffffffffu, mx1, 1));
        mx1 = fmaxf(mx1, __shfl_xor_sync(0xffffffffu, mx1, 2));
        float s0 = 0.f, s1 = 0.f;
        #pragma unroll
        for (int nt = 0; nt < 10; nt++) {
            float e0 = __expf(c[mt][nt][0] - mx0);
            float e1 = __expf(c[mt][nt][1] - mx0);
            float e2 = __expf(c[mt][nt][2] - mx1);
            float e3 = __expf(c[mt][nt][3] - mx1);
            s0 += e0 + e1; s1 += e2 + e3;
            pu[mt][nt][0] = pack_bf16(e0, e1);
            pu[mt][nt][1] = pack_bf16(e2, e3);
        }
        s0 += __shfl_xor_sync(0xffffffffu, s0, 1);
        s0 += __shfl_xor_sync(0xffffffffu, s0, 2);
        s1 += __shfl_xor_sync(0xffffffffu, s1, 1);
        s1 += __shfl_xor_sync(0xffffffffu, s1, 2);
        iv[mt][0] = 1.f / s0;
        iv[mt][1] = 1.f / s1;
    }

    // ---- O = P @ V : M=32/warp x N=64 x K=80 (A from registers) ----
    float o[2][8][4];
    #pragma unroll
    for (int mt = 0; mt < 2; mt++)
        #pragma unroll
        for (int nt = 0; nt < 8; nt++)
            #pragma unroll
            for (int r = 0; r < 4; r++) o[mt][nt][r] = 0.f;

    #pragma unroll
    for (int kk = 0; kk < 5; kk++) {
        uint32_t bv[8][2];
        #pragma unroll
        for (int nt = 0; nt < 8; nt++) {
            uint32_t addr = vbase + ((kk * 16 + (lane & 15)) * VS_STR + nt * 8) * 2;
            asm volatile(
                "ldmatrix.sync.aligned.m8n8.x2.trans.shared.b16 {%0,%1}, [%2];"
                : "=r"(bv[nt][0]), "=r"(bv[nt][1]) : "r"(addr));
        }
        #pragma unroll
        for (int mt = 0; mt < 2; mt++) {
            uint32_t a0 = pu[mt][2 * kk][0];
            uint32_t a1 = pu[mt][2 * kk][1];
            uint32_t a2 = pu[mt][2 * kk + 1][0];
            uint32_t a3 = pu[mt][2 * kk + 1][1];
            #pragma unroll
            for (int nt = 0; nt < 8; nt++) {
                asm volatile(
                    "mma.sync.aligned.m16n8k16.row.col.f32.bf16.bf16.f32 "
                    "{%0,%1,%2,%3}, {%4,%5,%6,%7}, {%8,%9}, {%0,%1,%2,%3};"
                    : "+f"(o[mt][nt][0]), "+f"(o[mt][nt][1]),
                      "+f"(o[mt][nt][2]), "+f"(o[mt][nt][3])
                    : "r"(a0), "r"(a1), "r"(a2), "r"(a3),
                      "r"(bv[nt][0]), "r"(bv[nt][1]));
            }
        }
    }

    // ---- normalize + transpose through smem (sQ reused as O [d][px]) ----
    __nv_bfloat16* Od = sQ;
    #pragma unroll
    for (int mt = 0; mt < 2; mt++) {
        int pxa = warp * 32 + mt * 16 + (lane >> 2);
        #pragma unroll
        for (int nt = 0; nt < 8; nt++) {
            int d = nt * 8 + (lane & 3) * 2;
            Od[d * OD_STR + pxa]           = __float2bfloat16(o[mt][nt][0] * iv[mt][0]);
            Od[(d + 1) * OD_STR + pxa]     = __float2bfloat16(o[mt][nt][1] * iv[mt][0]);
            Od[d * OD_STR + pxa + 8]       = __float2bfloat16(o[mt][nt][2] * iv[mt][1]);
            Od[(d + 1) * OD_STR + pxa + 8] = __float2bfloat16(o[mt][nt][3] * iv[mt][1]);
        }
    }
    __syncthreads();

    __nv_bfloat16* og = g_aob + ((size_t)b * Cdim + ch0) * HWp + p0;
    #pragma unroll 2
    for (int i = tid; i < 64 * 16; i += 128) {
        int d = i >> 4, cc = (i & 15) * 8;
        *(uint4*)(og + (size_t)d * HWp + cc) = *(const uint4*)(Od + d * OD_STR + cc);
    }
}

// ============================================================
extern "C" void kernel_launch(void* const* d_in, const int* in_sizes, int n_in,
                              void* d_out, int out_size) {
    const float* x       = (const float*)d_in[0];
    const float* context = (const float*)d_in[1];
    const float* gn_w    = (const float*)d_in[2];
    const float* gn_b    = (const float*)d_in[3];
    const float* ln_w    = (const float*)d_in[4];
    const float* ln_b    = (const float*)d_in[5];
    const float* q_w     = (const float*)d_in[6];
    const float* q_b     = (const float*)d_in[7];
    const float* k_w     = (const float*)d_in[8];
    const float* k_b     = (const float*)d_in[9];
    const float* v_w     = (const float*)d_in[10];
    const float* v_b     = (const float*)d_in[11];
    const float* out_w   = (const float*)d_in[12];
    const float* out_b   = (const float*)d_in[13];
    float* out = (float*)d_out;

    __nv_bfloat16 *qb = nullptr, *xnb = nullptr, *aob = nullptr, *qwb = nullptr, *owb = nullptr;
    cudaGetSymbolAddress((void**)&qb,  g_qb);
    cudaGetSymbolAddress((void**)&xnb, g_xnb);
    cudaGetSymbolAddress((void**)&aob, g_aob);
    cudaGetSymbolAddress((void**)&qwb, g_qwb);
    cudaGetSymbolAddress((void**)&owb, g_owb);

    gn_stats_kernel<<<Bsz * NGROUPS, 256>>>(x);
    ln_kernel<<<Bsz * Sctx, 256>>>(context, ln_w, ln_b);
    conv_w_kernel<<<(2 * Cdim * Cdim) / 512, 512>>>(q_w, out_w);
    conv_x_kernel<<<Bsz * Cdim, 256>>>(x, gn_w, gn_b);
    kv_gemm<<<dim3((Bsz * Sctx + KV_BM - 1) / KV_BM, Cdim / KV_BN, 2), 256>>>(
        k_w, k_b, v_w, v_b);
    // Q projection (tensor cores, bf16 out): g_qb = q_w @ GN(x)
    mma_gemm<true><<<dim3(HWp / 128, Cdim / 128, Bsz), 256>>>(
        qwb, xnb, q_b, nullptr, qb);
    // Tensor-core attention
    attn_mma_kernel<<<dim3(HWp / 128, NHEADS, Bsz), 128>>>();
    // Out projection + residual (fp32 out)
    mma_gemm<false><<<dim3(HWp / 128, Cdim / 128, Bsz), 256>>>(
        owb, aob, out_b, x, out);
}

// round 6
// speedup vs baseline: 3.9926x; 1.0224x over previous
#include <cuda_runtime.h>
#include <cuda_bf16.h>
#include <cstdint>

#define Bsz 16
#define Cdim 512
#define HWp 4096
#define Sctx 77
#define CTXd 768
#define NHEADS 8
#define HD 64
#define NGROUPS 32
#define CPG 16
#define EPSV 1e-5f

// ---- scratch (static device globals; no runtime allocation) ----
__device__ __nv_bfloat16 g_qb [(size_t)Bsz * Cdim * HWp]; // Q  (B, C, HW) bf16
__device__ __nv_bfloat16 g_xnb[(size_t)Bsz * Cdim * HWp]; // GN(x) bf16
__device__ __nv_bfloat16 g_aob[(size_t)Bsz * Cdim * HWp]; // attn out bf16
__device__ float g_cn[(size_t)Bsz * Sctx * CTXd];         // layernormed context
__device__ float g_k [(size_t)Bsz * Sctx * Cdim];         // K (B*S, C)
__device__ float g_v [(size_t)Bsz * Sctx * Cdim];         // V (B*S, C)
__device__ __nv_bfloat16 g_qwb[Cdim * Cdim];              // q_w bf16
__device__ __nv_bfloat16 g_owb[Cdim * Cdim];              // out_w bf16

__device__ __forceinline__ uint32_t smem_u32(const void* p) {
    uint32_t a;
    asm("{ .reg .u64 t; cvta.to.shared.u64 t, %1; cvt.u32.u64 %0, t; }"
        : "=r"(a) : "l"(p));
    return a;
}
__device__ __forceinline__ uint32_t pack_bf16(float lo, float hi) {
    __nv_bfloat162 p = __floats2bfloat162_rn(lo, hi);
    return *reinterpret_cast<uint32_t*>(&p);
}
__device__ __forceinline__ void cp_async16(uint32_t dst, const void* src) {
    asm volatile("cp.async.cg.shared.global [%0], [%1], 16;"
                 :: "r"(dst), "l"(src));
}
__device__ __forceinline__ void cp_commit() {
    asm volatile("cp.async.commit_group;" ::: "memory");
}
template <int N>
__device__ __forceinline__ void cp_wait() {
    asm volatile("cp.async.wait_group %0;" :: "n"(N) : "memory");
}

// ============================================================
// Fused GroupNorm: one block per (b,g); reduce, then apply + bf16
// ============================================================
__global__ void __launch_bounds__(512)
gn_fuse_kernel(const float* __restrict__ x,
               const float* __restrict__ gnw,
               const float* __restrict__ gnb) {
    int blk = blockIdx.x;
    int b = blk / NGROUPS, g = blk % NGROUPS;
    const size_t base = ((size_t)b * Cdim + (size_t)g * CPG) * HWp;
    const float4* p = (const float4*)(x + base);
    const int n4 = CPG * HWp / 4;  // 16384
    float s = 0.f, sq = 0.f;
    for (int i = threadIdx.x; i < n4; i += blockDim.x) {
        float4 v = p[i];
        s  += v.x + v.y + v.z + v.w;
        sq += v.x * v.x + v.y * v.y + v.z * v.z + v.w * v.w;
    }
    __shared__ float ss[32], ssq[32];
    __shared__ float sa[CPG], sb[CPG];
    #pragma unroll
    for (int o = 16; o > 0; o >>= 1) {
        s  += __shfl_down_sync(0xffffffffu, s, o);
        sq += __shfl_down_sync(0xffffffffu, sq, o);
    }
    int wid = threadIdx.x >> 5, lid = threadIdx.x & 31;
    if (lid == 0) { ss[wid] = s; ssq[wid] = sq; }
    __syncthreads();
    if (wid == 0) {
        int nw = blockDim.x >> 5;
        s  = (lid < nw) ? ss[lid]  : 0.f;
        sq = (lid < nw) ? ssq[lid] : 0.f;
        #pragma unroll
        for (int o = 16; o > 0; o >>= 1) {
            s  += __shfl_down_sync(0xffffffffu, s, o);
            sq += __shfl_down_sync(0xffffffffu, sq, o);
        }
        if (lid == 0) { ss[0] = s; ssq[0] = sq; }
    }
    __syncthreads();
    {
        const float invn = 1.f / (float)(CPG * HWp);
        float mean = ss[0] * invn;
        float var  = ssq[0] * invn - mean * mean;
        float rstd = rsqrtf(var + EPSV);
        if (threadIdx.x < CPG) {
            int c = g * CPG + threadIdx.x;
            float a = rstd * gnw[c];
            sa[threadIdx.x] = a;
            sb[threadIdx.x] = gnb[c] - mean * a;
        }
    }
    __syncthreads();
    __nv_bfloat162* dst = (__nv_bfloat162*)(g_xnb + base);
    const int per_c4 = HWp / 4;  // float4s per channel
    for (int i = threadIdx.x; i < n4; i += blockDim.x) {
        int c = i / per_c4;
        float a = sa[c], bb = sb[c];
        float4 v = p[i];
        dst[2 * i]     = __floats2bfloat162_rn(v.x * a + bb, v.y * a + bb);
        dst[2 * i + 1] = __floats2bfloat162_rn(v.z * a + bb, v.w * a + bb);
    }
}

// ============================================================
// LayerNorm on context
// ============================================================
__global__ void ln_kernel(const float* __restrict__ ctx,
                          const float* __restrict__ w,
                          const float* __restrict__ bb) {
    int row = blockIdx.x;
    const float* xr = ctx + (size_t)row * CTXd;
    float s = 0.f, sq = 0.f;
    for (int i = threadIdx.x; i < CTXd; i += blockDim.x) {
        float v = xr[i];
        s += v; sq += v * v;
    }
    __shared__ float ss[32], ssq[32];
    __shared__ float smean, srstd;
    #pragma unroll
    for (int o = 16; o > 0; o >>= 1) {
        s  += __shfl_down_sync(0xffffffffu, s, o);
        sq += __shfl_down_sync(0xffffffffu, sq, o);
    }
    int wid = threadIdx.x >> 5, lid = threadIdx.x & 31;
    if (lid == 0) { ss[wid] = s; ssq[wid] = sq; }
    __syncthreads();
    if (wid == 0) {
        int nw = blockDim.x >> 5;
        s  = (lid < nw) ? ss[lid]  : 0.f;
        sq = (lid < nw) ? ssq[lid] : 0.f;
        #pragma unroll
        for (int o = 16; o > 0; o >>= 1) {
            s  += __shfl_down_sync(0xffffffffu, s, o);
            sq += __shfl_down_sync(0xffffffffu, sq, o);
        }
        if (lid == 0) {
            const float invn = 1.f / (float)CTXd;
            float mean = s * invn;
            float var  = sq * invn - mean * mean;
            smean = mean;
            srstd = rsqrtf(var + EPSV);
        }
    }
    __syncthreads();
    float mean = smean, rstd = srstd;
    for (int i = threadIdx.x; i < CTXd; i += blockDim.x) {
        g_cn[(size_t)row * CTXd + i] = (xr[i] - mean) * rstd * w[i] + bb[i];
    }
}

// ============================================================
// Weight bf16 conversion (q_w, out_w)
// ============================================================
__global__ void conv_w_kernel(const float* __restrict__ qw, const float* __restrict__ ow) {
    int i = blockIdx.x * blockDim.x + threadIdx.x;
    const int N = Cdim * Cdim;
    if (i < N) g_qwb[i] = __float2bfloat16(qw[i]);
    else       g_owb[i - N] = __float2bfloat16(ow[i - N]);
}

// ============================================================
// K/V projection (fp32, small)
// ============================================================
#define KV_BM 64
#define KV_BN 64
#define KV_BK 16
__global__ void kv_gemm(const float* __restrict__ kw, const float* __restrict__ kb,
                        const float* __restrict__ vw, const float* __restrict__ vb) {
    __shared__ float As[KV_BM][KV_BK + 1];
    __shared__ float Ws[KV_BN][KV_BK + 1];
    const float* W    = blockIdx.z ? vw : kw;
    const float* bias = blockIdx.z ? vb : kb;
    float*       out  = blockIdx.z ? g_v : g_k;
    const int NROWS = Bsz * Sctx;

    int n0 = blockIdx.x * KV_BM;
    int o0 = blockIdx.y * KV_BN;
    int tid = threadIdx.x;
    int tx = tid & 15, ty = tid >> 4;
    int lrow = tid >> 2;
    int lcol = (tid & 3) * 4;

    float acc[4][4] = {};
    for (int k0 = 0; k0 < CTXd; k0 += KV_BK) {
        int n = n0 + lrow;
        float4 av = (n < NROWS)
            ? *(const float4*)(g_cn + (size_t)n * CTXd + k0 + lcol)
            : make_float4(0.f, 0.f, 0.f, 0.f);
        As[lrow][lcol] = av.x; As[lrow][lcol + 1] = av.y;
        As[lrow][lcol + 2] = av.z; As[lrow][lcol + 3] = av.w;
        float4 wv = *(const float4*)(W + (size_t)(o0 + lrow) * CTXd + k0 + lcol);
        Ws[lrow][lcol] = wv.x; Ws[lrow][lcol + 1] = wv.y;
        Ws[lrow][lcol + 2] = wv.z; Ws[lrow][lcol + 3] = wv.w;
        __syncthreads();
        #pragma unroll
        for (int k = 0; k < KV_BK; k++) {
            float af[4], wf[4];
            #pragma unroll
            for (int i = 0; i < 4; i++) af[i] = As[ty * 4 + i][k];
            #pragma unroll
            for (int j = 0; j < 4; j++) wf[j] = Ws[tx * 4 + j][k];
            #pragma unroll
            for (int i = 0; i < 4; i++)
                #pragma unroll
                for (int j = 0; j < 4; j++)
                    acc[i][j] += af[i] * wf[j];
        }
        __syncthreads();
    }
    #pragma unroll
    for (int i = 0; i < 4; i++) {
        int n = n0 + ty * 4 + i;
        if (n >= NROWS) continue;
        #pragma unroll
        for (int j = 0; j < 4; j++) {
            int o = o0 + tx * 4 + j;
            out[(size_t)n * Cdim + o] = acc[i][j] + bias[o];
        }
    }
}

// ============================================================
// bf16 mma.sync GEMM with 3-stage cp.async pipeline.
// D[o,p] = sum_c W[o,c] * X[c,p] (+bias, +residual)
// CTA tile 128(o) x 128(p) x 32; 256 threads, warp tile 64x32.
// ============================================================
#define A_STRIDE 40
#define B_STRIDE 136
#define STAGES 3
#define A_STAGE_BYTES (128 * A_STRIDE * 2)
#define B_STAGE_BYTES (32 * B_STRIDE * 2)
#define NIT (Cdim / 32)

template <bool BF16OUT>
__global__ void __launch_bounds__(256, 2)
mma_gemm(const __nv_bfloat16* __restrict__ Wb,
         const __nv_bfloat16* __restrict__ Xb,
         const float* __restrict__ bias,
         const float* __restrict__ residual,
         void* __restrict__ outv) {
    __shared__ __align__(16) char smem_[STAGES * (A_STAGE_BYTES + B_STAGE_BYTES)];

    const int tid  = threadIdx.x;
    const int warp = tid >> 5, lane = tid & 31;
    const int wm = warp >> 2, wn = warp & 3;
    const int p0 = blockIdx.x * 128;
    const int o0 = blockIdx.y * 128;
    const int b  = blockIdx.z;
    const __nv_bfloat16* Xbb = Xb + (size_t)b * Cdim * HWp;

    const uint32_t sbase = smem_u32(smem_);
    const uint32_t sB0 = sbase + STAGES * A_STAGE_BYTES;

    const int a_ld_row = tid >> 2;            // 0..63 (+64)
    const int a_ld_col = (tid & 3) * 8;
    const int b_ld_row = tid >> 4;            // 0..15 (+16)
    const int b_ld_col = (tid & 15) * 8;

    const uint32_t a_lm_base =
        ((wm * 64 + (lane & 15)) * A_STRIDE + (lane >> 4) * 8) * 2;
    const uint32_t b_lm_base = ((lane & 15) * B_STRIDE + wn * 32) * 2;

    const uint32_t a_st_off = (a_ld_row * A_STRIDE + a_ld_col) * 2;
    const uint32_t a_st_off2 = ((a_ld_row + 64) * A_STRIDE + a_ld_col) * 2;
    const uint32_t b_st_off = (b_ld_row * B_STRIDE + b_ld_col) * 2;
    const uint32_t b_st_off2 = ((b_ld_row + 16) * B_STRIDE + b_ld_col) * 2;

    float acc[4][4][4] = {};

    // prologue: issue stages 0..STAGES-2
    #pragma unroll
    for (int s = 0; s < STAGES - 1; s++) {
        const int k0 = s * 32;
        uint32_t aS = sbase + s * A_STAGE_BYTES;
        uint32_t bS = sB0 + s * B_STAGE_BYTES;
        cp_async16(aS + a_st_off,
                   Wb + (size_t)(o0 + a_ld_row) * Cdim + k0 + a_ld_col);
        cp_async16(aS + a_st_off2,
                   Wb + (size_t)(o0 + a_ld_row + 64) * Cdim + k0 + a_ld_col);
        cp_async16(bS + b_st_off,
                   Xbb + (size_t)(k0 + b_ld_row) * HWp + p0 + b_ld_col);
        cp_async16(bS + b_st_off2,
                   Xbb + (size_t)(k0 + b_ld_row + 16) * HWp + p0 + b_ld_col);
        cp_commit();
    }

    #pragma unroll 1
    for (int it = 0; it < NIT; it++) {
        cp_wait<STAGES - 2>();
        __syncthreads();

        // issue stage it+STAGES-1
        {
            const int sl = it + STAGES - 1;
            if (sl < NIT) {
                const int k0 = sl * 32;
                const int sb = sl % STAGES;
                uint32_t aS = sbase + sb * A_STAGE_BYTES;
                uint32_t bS = sB0 + sb * B_STAGE_BYTES;
                cp_async16(aS + a_st_off,
                           Wb + (size_t)(o0 + a_ld_row) * Cdim + k0 + a_ld_col);
                cp_async16(aS + a_st_off2,
                           Wb + (size_t)(o0 + a_ld_row + 64) * Cdim + k0 + a_ld_col);
                cp_async16(bS + b_st_off,
                           Xbb + (size_t)(k0 + b_ld_row) * HWp + p0 + b_ld_col);
                cp_async16(bS + b_st_off2,
                           Xbb + (size_t)(k0 + b_ld_row + 16) * HWp + p0 + b_ld_col);
            }
            cp_commit();
        }

        const int sc = it % STAGES;
        const uint32_t aBuf = sbase + sc * A_STAGE_BYTES;
        const uint32_t bBuf = sB0 + sc * B_STAGE_BYTES;

        #pragma unroll
        for (int kk = 0; kk < 2; kk++) {
            uint32_t af[4][4];
            #pragma unroll
            for (int mt = 0; mt < 4; mt++) {
                uint32_t addr = aBuf + a_lm_base + (mt * 16 * A_STRIDE + kk * 16) * 2;
                asm volatile(
                    "ldmatrix.sync.aligned.m8n8.x4.shared.b16 {%0,%1,%2,%3}, [%4];"
                    : "=r"(af[mt][0]), "=r"(af[mt][1]), "=r"(af[mt][2]), "=r"(af[mt][3])
                    : "r"(addr));
            }
            uint32_t bf[4][2];
            #pragma unroll
            for (int nt = 0; nt < 4; nt++) {
                uint32_t addr = bBuf + b_lm_base + (kk * 16 * B_STRIDE + nt * 8) * 2;
                asm volatile(
                    "ldmatrix.sync.aligned.m8n8.x2.trans.shared.b16 {%0,%1}, [%2];"
                    : "=r"(bf[nt][0]), "=r"(bf[nt][1]) : "r"(addr));
            }
            #pragma unroll
            for (int mt = 0; mt < 4; mt++)
                #pragma unroll
                for (int nt = 0; nt < 4; nt++) {
                    asm volatile(
                        "mma.sync.aligned.m16n8k16.row.col.f32.bf16.bf16.f32 "
                        "{%0,%1,%2,%3}, {%4,%5,%6,%7}, {%8,%9}, {%0,%1,%2,%3};"
                        : "+f"(acc[mt][nt][0]), "+f"(acc[mt][nt][1]),
                          "+f"(acc[mt][nt][2]), "+f"(acc[mt][nt][3])
                        : "r"(af[mt][0]), "r"(af[mt][1]), "r"(af[mt][2]), "r"(af[mt][3]),
                          "r"(bf[nt][0]), "r"(bf[nt][1]));
                }
        }
    }

    const int row_base = o0 + wm * 64 + (lane >> 2);
    const int col_base = p0 + wn * 32 + (lane & 3) * 2;
    #pragma unroll
    for (int mt = 0; mt < 4; mt++) {
        #pragma unroll
        for (int half = 0; half < 2; half++) {
            int row = row_base + mt * 16 + half * 8;
            float bi = bias[row];
            size_t rb = ((size_t)b * Cdim + row) * HWp;
            #pragma unroll
            for (int nt = 0; nt < 4; nt++) {
                int col = col_base + nt * 8;
                float rx = acc[mt][nt][half * 2]     + bi;
                float ry = acc[mt][nt][half * 2 + 1] + bi;
                if (BF16OUT) {
                    __nv_bfloat16* outb = (__nv_bfloat16*)outv;
                    *(__nv_bfloat162*)(outb + rb + col) = __floats2bfloat162_rn(rx, ry);
                } else {
                    float* outf = (float*)outv;
                    if (residual) {
                        float2 rv = *(const float2*)(residual + rb + col);
                        rx += rv.x; ry += rv.y;
                    }
                    float2 r; r.x = rx; r.y = ry;
                    *(float2*)(outf + rb + col) = r;
                }
            }
        }
    }
}

// ============================================================
// Tensor-core flash attention: block = (b, h, 128-pixel tile)
// ============================================================
#define QS_STR 72
#define KS_STR 88
#define VS_STR 72
#define OD_STR 136
#define SPAD 80

__global__ void __launch_bounds__(128)
attn_mma_kernel() {
    __shared__ __align__(16) __nv_bfloat16 sQ[128 * QS_STR];  // reused as O [64][OD_STR]
    __shared__ __align__(16) __nv_bfloat16 sK[64 * KS_STR];   // K^T [d][s]
    __shared__ __align__(16) __nv_bfloat16 sV[SPAD * VS_STR]; // V [s][d]

    const int tid = threadIdx.x;
    const int warp = tid >> 5, lane = tid & 31;
    const int b = blockIdx.z, h = blockIdx.y;
    const int p0 = blockIdx.x * 128;
    const int ch0 = h * HD;

    const __nv_bfloat16* qg = g_qb + ((size_t)b * Cdim + ch0) * HWp + p0;
    #pragma unroll 4
    for (int i = tid; i < 128 * 64; i += 128) {
        int d = i >> 7, px = i & 127;
        sQ[px * QS_STR + d] = qg[(size_t)d * HWp + px];
    }
    const float* kg = g_k + (size_t)b * Sctx * Cdim + ch0;
    #pragma unroll 4
    for (int i = tid; i < 77 * 64; i += 128) {
        int s = i >> 6, d = i & 63;
        sK[d * KS_STR + s] = __float2bfloat16(kg[(size_t)s * Cdim + d]);
    }
    for (int i = tid; i < 3 * 64; i += 128) {
        int s = 77 + (i >> 6), d = i & 63;
        sK[d * KS_STR + s] = __float2bfloat16(0.f);
    }
    const float* vg = g_v + (size_t)b * Sctx * Cdim + ch0;
    #pragma unroll 4
    for (int i = tid; i < SPAD * 64; i += 128) {
        int s = i >> 6, d = i & 63;
        float v = (s < Sctx) ? vg[(size_t)s * Cdim + d] : 0.f;
        sV[s * VS_STR + d] = __float2bfloat16(v);
    }
    __syncthreads();

    const uint32_t qbase = smem_u32(sQ);
    const uint32_t kbase = smem_u32(sK);
    const uint32_t vbase = smem_u32(sV);

    float c[2][10][4];
    #pragma unroll
    for (int mt = 0; mt < 2; mt++)
        #pragma unroll
        for (int nt = 0; nt < 10; nt++)
            #pragma unroll
            for (int r = 0; r < 4; r++) c[mt][nt][r] = 0.f;

    const uint32_t a_lm = qbase +
        ((warp * 32 + (lane & 15)) * QS_STR + (lane >> 4) * 8) * 2;

    #pragma unroll
    for (int kk = 0; kk < 4; kk++) {
        uint32_t af[2][4];
        #pragma unroll
        for (int mt = 0; mt < 2; mt++) {
            uint32_t addr = a_lm + (mt * 16 * QS_STR + kk * 16) * 2;
            asm volatile(
                "ldmatrix.sync.aligned.m8n8.x4.shared.b16 {%0,%1,%2,%3}, [%4];"
                : "=r"(af[mt][0]), "=r"(af[mt][1]), "=r"(af[mt][2]), "=r"(af[mt][3])
                : "r"(addr));
        }
        uint32_t bf[10][2];
        #pragma unroll
        for (int nt = 0; nt < 10; nt++) {
            uint32_t addr = kbase + ((kk * 16 + (lane & 15)) * KS_STR + nt * 8) * 2;
            asm volatile(
                "ldmatrix.sync.aligned.m8n8.x2.trans.shared.b16 {%0,%1}, [%2];"
                : "=r"(bf[nt][0]), "=r"(bf[nt][1]) : "r"(addr));
        }
        #pragma unroll
        for (int mt = 0; mt < 2; mt++)
            #pragma unroll
            for (int nt = 0; nt < 10; nt++) {
                asm volatile(
                    "mma.sync.aligned.m16n8k16.row.col.f32.bf16.bf16.f32 "
                    "{%0,%1,%2,%3}, {%4,%5,%6,%7}, {%8,%9}, {%0,%1,%2,%3};"
                    : "+f"(c[mt][nt][0]), "+f"(c[mt][nt][1]),
                      "+f"(c[mt][nt][2]), "+f"(c[mt][nt][3])
                    : "r"(af[mt][0]), "r"(af[mt][1]), "r"(af[mt][2]), "r"(af[mt][3]),
                      "r"(bf[nt][0]), "r"(bf[nt][1]));
            }
    }
    __syncthreads();

    const float scale = 0.125f;
    uint32_t pu[2][10][2];
    float iv[2][2];
    #pragma unroll
    for (int mt = 0; mt < 2; mt++) {
        float mx0 = -1e30f, mx1 = -1e30f;
        #pragma unroll
        for (int nt = 0; nt < 10; nt++) {
            int col = nt * 8 + (lane & 3) * 2;
            c[mt][nt][0] = (col     < Sctx) ? c[mt][nt][0] * scale : -1e30f;
            c[mt][nt][1] = (col + 1 < Sctx) ? c[mt][nt][1] * scale : -1e30f;
            c[mt][nt][2] = (col     < Sctx) ? c[mt][nt][2] * scale : -1e30f;
            c[mt][nt][3] = (col + 1 < Sctx) ? c[mt][nt][3] * scale : -1e30f;
            mx0 = fmaxf(mx0, fmaxf(c[mt][nt][0], c[mt][nt][1]));
            mx1 = fmaxf(mx1, fmaxf(c[mt][nt][2], c[mt][nt][3]));
        }
        mx0 = fmaxf(mx0, __shfl_xor_sync(0xffffffffu, mx0, 1));
        mx0 = fmaxf(mx0, __shfl_xor_sync(0xffffffffu, mx0, 2));
        mx1 = fmaxf(mx1, __shfl_xor_sync(0xffffffffu, mx1, 1));
        mx1 = fmaxf(mx1, __shfl_xor_sync(0xffffffffu, mx1, 2));
        float s0 = 0.f, s1 = 0.f;
        #pragma unroll
        for (int nt = 0; nt < 10; nt++) {
            float e0 = __expf(c[mt][nt][0] - mx0);
            float e1 = __expf(c[mt][nt][1] - mx0);
            float e2 = __expf(c[mt][nt][2] - mx1);
            float e3 = __expf(c[mt][nt][3] - mx1);
            s0 += e0 + e1; s1 += e2 + e3;
            pu[mt][nt][0] = pack_bf16(e0, e1);
            pu[mt][nt][1] = pack_bf16(e2, e3);
        }
        s0 += __shfl_xor_sync(0xffffffffu, s0, 1);
        s0 += __shfl_xor_sync(0xffffffffu, s0, 2);
        s1 += __shfl_xor_sync(0xffffffffu, s1, 1);
        s1 += __shfl_xor_sync(0xffffffffu, s1, 2);
        iv[mt][0] = 1.f / s0;
        iv[mt][1] = 1.f / s1;
    }

    float o[2][8][4];
    #pragma unroll
    for (int mt = 0; mt < 2; mt++)
        #pragma unroll
        for (int nt = 0; nt < 8; nt++)
            #pragma unroll
            for (int r = 0; r < 4; r++) o[mt][nt][r] = 0.f;

    #pragma unroll
    for (int kk = 0; kk < 5; kk++) {
        uint32_t bv[8][2];
        #pragma unroll
        for (int nt = 0; nt < 8; nt++) {
            uint32_t addr = vbase + ((kk * 16 + (lane & 15)) * VS_STR + nt * 8) * 2;
            asm volatile(
                "ldmatrix.sync.aligned.m8n8.x2.trans.shared.b16 {%0,%1}, [%2];"
                : "=r"(bv[nt][0]), "=r"(bv[nt][1]) : "r"(addr));
        }
        #pragma unroll
        for (int mt = 0; mt < 2; mt++) {
            uint32_t a0 = pu[mt][2 * kk][0];
            uint32_t a1 = pu[mt][2 * kk][1];
            uint32_t a2 = pu[mt][2 * kk + 1][0];
            uint32_t a3 = pu[mt][2 * kk + 1][1];
            #pragma unroll
            for (int nt = 0; nt < 8; nt++) {
                asm volatile(
                    "mma.sync.aligned.m16n8k16.row.col.f32.bf16.bf16.f32 "
                    "{%0,%1,%2,%3}, {%4,%5,%6,%7}, {%8,%9}, {%0,%1,%2,%3};"
                    : "+f"(o[mt][nt][0]), "+f"(o[mt][nt][1]),
                      "+f"(o[mt][nt][2]), "+f"(o[mt][nt][3])
                    : "r"(a0), "r"(a1), "r"(a2), "r"(a3),
                      "r"(bv[nt][0]), "r"(bv[nt][1]));
            }
        }
    }

    __nv_bfloat16* Od = sQ;
    #pragma unroll
    for (int mt = 0; mt < 2; mt++) {
        int pxa = warp * 32 + mt * 16 + (lane >> 2);
        #pragma unroll
        for (int nt = 0; nt < 8; nt++) {
            int d = nt * 8 + (lane & 3) * 2;
            Od[d * OD_STR + pxa]           = __float2bfloat16(o[mt][nt][0] * iv[mt][0]);
            Od[(d + 1) * OD_STR + pxa]     = __float2bfloat16(o[mt][nt][1] * iv[mt][0]);
            Od[d * OD_STR + pxa + 8]       = __float2bfloat16(o[mt][nt][2] * iv[mt][1]);
            Od[(d + 1) * OD_STR + pxa + 8] = __float2bfloat16(o[mt][nt][3] * iv[mt][1]);
        }
    }
    __syncthreads();

    __nv_bfloat16* og = g_aob + ((size_t)b * Cdim + ch0) * HWp + p0;
    #pragma unroll 2
    for (int i = tid; i < 64 * 16; i += 128) {
        int d = i >> 4, cc = (i & 15) * 8;
        *(uint4*)(og + (size_t)d * HWp + cc) = *(const uint4*)(Od + d * OD_STR + cc);
    }
}

// ============================================================
extern "C" void kernel_launch(void* const* d_in, const int* in_sizes, int n_in,
                              void* d_out, int out_size) {
    const float* x       = (const float*)d_in[0];
    const float* context = (const float*)d_in[1];
    const float* gn_w    = (const float*)d_in[2];
    const float* gn_b    = (const float*)d_in[3];
    const float* ln_w    = (const float*)d_in[4];
    const float* ln_b    = (const float*)d_in[5];
    const float* q_w     = (const float*)d_in[6];
    const float* q_b     = (const float*)d_in[7];
    const float* k_w     = (const float*)d_in[8];
    const float* k_b     = (const float*)d_in[9];
    const float* v_w     = (const float*)d_in[10];
    const float* v_b     = (const float*)d_in[11];
    const float* out_w   = (const float*)d_in[12];
    const float* out_b   = (const float*)d_in[13];
    float* out = (float*)d_out;

    __nv_bfloat16 *qb = nullptr, *xnb = nullptr, *aob = nullptr, *qwb = nullptr, *owb = nullptr;
    cudaGetSymbolAddress((void**)&qb,  g_qb);
    cudaGetSymbolAddress((void**)&xnb, g_xnb);
    cudaGetSymbolAddress((void**)&aob, g_aob);
    cudaGetSymbolAddress((void**)&qwb, g_qwb);
    cudaGetSymbolAddress((void**)&owb, g_owb);

    gn_fuse_kernel<<<Bsz * NGROUPS, 512>>>(x, gn_w, gn_b);
    ln_kernel<<<Bsz * Sctx, 256>>>(context, ln_w, ln_b);
    conv_w_kernel<<<(2 * Cdim * Cdim) / 512, 512>>>(q_w, out_w);
    kv_gemm<<<dim3((Bsz * Sctx + KV_BM - 1) / KV_BM, Cdim / KV_BN, 2), 256>>>(
        k_w, k_b, v_w, v_b);
    mma_gemm<true><<<dim3(HWp / 128, Cdim / 128, Bsz), 256>>>(
        qwb, xnb, q_b, nullptr, qb);
    attn_mma_kernel<<<dim3(HWp / 128, NHEADS, Bsz), 128>>>();
    mma_gemm<false><<<dim3(HWp / 128, Cdim / 128, Bsz), 256>>>(
        owb, aob, out_b, x, out);
}

// round 7
// speedup vs baseline: 4.7201x; 1.1822x over previous
#include <cuda_runtime.h>
#include <cuda_bf16.h>
#include <cstdint>

#define Bsz 16
#define Cdim 512
#define HWp 4096
#define Sctx 77
#define CTXd 768
#define NHEADS 8
#define HD 64
#define NGROUPS 32
#define CPG 16
#define EPSV 1e-5f
#define NROWS (Bsz * Sctx)      // 1232
#define NROWS_PAD 1280

// ---- scratch (static device globals; no runtime allocation) ----
__device__ __nv_bfloat16 g_qb [(size_t)Bsz * Cdim * HWp]; // Q  (B, C, HW) bf16
__device__ __nv_bfloat16 g_xnb[(size_t)Bsz * Cdim * HWp]; // GN(x) bf16
__device__ __nv_bfloat16 g_aob[(size_t)Bsz * Cdim * HWp]; // attn out bf16
__device__ __nv_bfloat16 g_cnb[(size_t)NROWS_PAD * CTXd]; // layernormed ctx bf16 (padded)
__device__ __nv_bfloat16 g_kb [(size_t)NROWS * Cdim];     // K bf16 (n, C)
__device__ __nv_bfloat16 g_vb [(size_t)NROWS * Cdim];     // V bf16 (n, C)
__device__ __nv_bfloat16 g_qwb[Cdim * Cdim];              // q_w bf16
__device__ __nv_bfloat16 g_owb[Cdim * Cdim];              // out_w bf16
__device__ __nv_bfloat16 g_kwb[Cdim * CTXd];              // k_w bf16
__device__ __nv_bfloat16 g_vwb[Cdim * CTXd];              // v_w bf16

__device__ __forceinline__ uint32_t smem_u32(const void* p) {
    uint32_t a;
    asm("{ .reg .u64 t; cvta.to.shared.u64 t, %1; cvt.u32.u64 %0, t; }"
        : "=r"(a) : "l"(p));
    return a;
}
__device__ __forceinline__ uint32_t pack_bf16(float lo, float hi) {
    __nv_bfloat162 p = __floats2bfloat162_rn(lo, hi);
    return *reinterpret_cast<uint32_t*>(&p);
}
__device__ __forceinline__ void cp_async16(uint32_t dst, const void* src) {
    asm volatile("cp.async.cg.shared.global [%0], [%1], 16;"
                 :: "r"(dst), "l"(src));
}
__device__ __forceinline__ void cp_commit() {
    asm volatile("cp.async.commit_group;" ::: "memory");
}
template <int N>
__device__ __forceinline__ void cp_wait() {
    asm volatile("cp.async.wait_group %0;" :: "n"(N) : "memory");
}

// ============================================================
// Fused GroupNorm: one block per (b,g); reduce, then apply + bf16
// ============================================================
__global__ void __launch_bounds__(512)
gn_fuse_kernel(const float* __restrict__ x,
               const float* __restrict__ gnw,
               const float* __restrict__ gnb) {
    int blk = blockIdx.x;
    int b = blk / NGROUPS, g = blk % NGROUPS;
    const size_t base = ((size_t)b * Cdim + (size_t)g * CPG) * HWp;
    const float4* p = (const float4*)(x + base);
    const int n4 = CPG * HWp / 4;  // 16384
    float s = 0.f, sq = 0.f;
    for (int i = threadIdx.x; i < n4; i += blockDim.x) {
        float4 v = p[i];
        s  += v.x + v.y + v.z + v.w;
        sq += v.x * v.x + v.y * v.y + v.z * v.z + v.w * v.w;
    }
    __shared__ float ss[32], ssq[32];
    __shared__ float sa[CPG], sb[CPG];
    #pragma unroll
    for (int o = 16; o > 0; o >>= 1) {
        s  += __shfl_down_sync(0xffffffffu, s, o);
        sq += __shfl_down_sync(0xffffffffu, sq, o);
    }
    int wid = threadIdx.x >> 5, lid = threadIdx.x & 31;
    if (lid == 0) { ss[wid] = s; ssq[wid] = sq; }
    __syncthreads();
    if (wid == 0) {
        int nw = blockDim.x >> 5;
        s  = (lid < nw) ? ss[lid]  : 0.f;
        sq = (lid < nw) ? ssq[lid] : 0.f;
        #pragma unroll
        for (int o = 16; o > 0; o >>= 1) {
            s  += __shfl_down_sync(0xffffffffu, s, o);
            sq += __shfl_down_sync(0xffffffffu, sq, o);
        }
        if (lid == 0) { ss[0] = s; ssq[0] = sq; }
    }
    __syncthreads();
    {
        const float invn = 1.f / (float)(CPG * HWp);
        float mean = ss[0] * invn;
        float var  = ssq[0] * invn - mean * mean;
        float rstd = rsqrtf(var + EPSV);
        if (threadIdx.x < CPG) {
            int c = g * CPG + threadIdx.x;
            float a = rstd * gnw[c];
            sa[threadIdx.x] = a;
            sb[threadIdx.x] = gnb[c] - mean * a;
        }
    }
    __syncthreads();
    __nv_bfloat162* dst = (__nv_bfloat162*)(g_xnb + base);
    const int per_c4 = HWp / 4;
    for (int i = threadIdx.x; i < n4; i += blockDim.x) {
        int c = i / per_c4;
        float a = sa[c], bb = sb[c];
        float4 v = p[i];
        dst[2 * i]     = __floats2bfloat162_rn(v.x * a + bb, v.y * a + bb);
        dst[2 * i + 1] = __floats2bfloat162_rn(v.z * a + bb, v.w * a + bb);
    }
}

// ============================================================
// LayerNorm on context -> bf16
// ============================================================
__global__ void ln_kernel(const float* __restrict__ ctx,
                          const float* __restrict__ w,
                          const float* __restrict__ bb) {
    int row = blockIdx.x;
    const float* xr = ctx + (size_t)row * CTXd;
    float s = 0.f, sq = 0.f;
    for (int i = threadIdx.x; i < CTXd; i += blockDim.x) {
        float v = xr[i];
        s += v; sq += v * v;
    }
    __shared__ float ss[32], ssq[32];
    __shared__ float smean, srstd;
    #pragma unroll
    for (int o = 16; o > 0; o >>= 1) {
        s  += __shfl_down_sync(0xffffffffu, s, o);
        sq += __shfl_down_sync(0xffffffffu, sq, o);
    }
    int wid = threadIdx.x >> 5, lid = threadIdx.x & 31;
    if (lid == 0) { ss[wid] = s; ssq[wid] = sq; }
    __syncthreads();
    if (wid == 0) {
        int nw = blockDim.x >> 5;
        s  = (lid < nw) ? ss[lid]  : 0.f;
        sq = (lid < nw) ? ssq[lid] : 0.f;
        #pragma unroll
        for (int o = 16; o > 0; o >>= 1) {
            s  += __shfl_down_sync(0xffffffffu, s, o);
            sq += __shfl_down_sync(0xffffffffu, sq, o);
        }
        if (lid == 0) {
            const float invn = 1.f / (float)CTXd;
            float mean = s * invn;
            float var  = sq * invn - mean * mean;
            smean = mean;
            srstd = rsqrtf(var + EPSV);
        }
    }
    __syncthreads();
    float mean = smean, rstd = srstd;
    for (int i = threadIdx.x; i < CTXd; i += blockDim.x) {
        g_cnb[(size_t)row * CTXd + i] =
            __float2bfloat16((xr[i] - mean) * rstd * w[i] + bb[i]);
    }
}

// ============================================================
// Weight bf16 conversion (q_w, out_w, k_w, v_w)
// ============================================================
#define NQW (Cdim * Cdim)
#define NKW (Cdim * CTXd)
__global__ void conv_w_kernel(const float* __restrict__ qw, const float* __restrict__ ow,
                              const float* __restrict__ kw, const float* __restrict__ vw) {
    int i = blockIdx.x * blockDim.x + threadIdx.x;
    if (i < NQW)                 g_qwb[i] = __float2bfloat16(qw[i]);
    else if (i < 2 * NQW)        g_owb[i - NQW] = __float2bfloat16(ow[i - NQW]);
    else if (i < 2 * NQW + NKW)  g_kwb[i - 2 * NQW] = __float2bfloat16(kw[i - 2 * NQW]);
    else                         g_vwb[i - 2 * NQW - NKW] = __float2bfloat16(vw[i - 2 * NQW - NKW]);
}

// ============================================================
// K/V projection via bf16 mma.sync (NT): out[n,o] = sum_j cn[n,j]*W[o,j]+b[o]
// CTA 128(n) x 128(o) x 32; 256 threads, 8 warps (2x4), warp 64x32.
// A = cn [n][j] K-major; B = W [o][j] K-major (non-trans ldmatrix).
// grid: (Cdim/128, NROWS_PAD/128, 2)
// ============================================================
#define KVA_STR 40
#define KV_STAGE_BYTES (128 * KVA_STR * 2)
#define KV_STAGES 3
#define KV_NIT (CTXd / 32)

__global__ void __launch_bounds__(256, 2)
kv_mma(const float* __restrict__ kb_, const float* __restrict__ vb_) {
    __shared__ __align__(16) char smem_[KV_STAGES * 2 * KV_STAGE_BYTES];

    const __nv_bfloat16* W    = blockIdx.z ? g_vwb : g_kwb;
    const float*         bias = blockIdx.z ? vb_ : kb_;
    __nv_bfloat16*       out  = blockIdx.z ? g_vb : g_kb;

    const int tid  = threadIdx.x;
    const int warp = tid >> 5, lane = tid & 31;
    const int wm = warp >> 2, wn = warp & 3;
    const int n0 = blockIdx.y * 128;
    const int o0 = blockIdx.x * 128;

    const uint32_t sbase = smem_u32(smem_);
    const uint32_t sB0 = sbase + KV_STAGES * KV_STAGE_BYTES;

    const int ld_row = tid >> 2;          // 0..63 (+64)
    const int ld_col = (tid & 3) * 8;

    const uint32_t st_off  = (ld_row * KVA_STR + ld_col) * 2;
    const uint32_t st_off2 = ((ld_row + 64) * KVA_STR + ld_col) * 2;

    // A frag (rows = n): x4 non-trans
    const uint32_t a_lm_base =
        ((wm * 64 + (lane & 15)) * KVA_STR + (lane >> 4) * 8) * 2;
    // B frag (rows = o): x2 non-trans; lanes 0-7 k+0, 8-15 k+8
    const uint32_t b_lm_part =
        ((lane & 7) * KVA_STR + ((lane >> 3) & 1) * 8) * 2;

    float acc[4][4][4] = {};

    #pragma unroll
    for (int s = 0; s < KV_STAGES - 1; s++) {
        const int k0 = s * 32;
        uint32_t aS = sbase + s * KV_STAGE_BYTES;
        uint32_t bS = sB0 + s * KV_STAGE_BYTES;
        cp_async16(aS + st_off,  g_cnb + (size_t)(n0 + ld_row) * CTXd + k0 + ld_col);
        cp_async16(aS + st_off2, g_cnb + (size_t)(n0 + ld_row + 64) * CTXd + k0 + ld_col);
        cp_async16(bS + st_off,  W + (size_t)(o0 + ld_row) * CTXd + k0 + ld_col);
        cp_async16(bS + st_off2, W + (size_t)(o0 + ld_row + 64) * CTXd + k0 + ld_col);
        cp_commit();
    }

    #pragma unroll 1
    for (int it = 0; it < KV_NIT; it++) {
        cp_wait<KV_STAGES - 2>();
        __syncthreads();
        {
            const int sl = it + KV_STAGES - 1;
            if (sl < KV_NIT) {
                const int k0 = sl * 32;
                const int sb = sl % KV_STAGES;
                uint32_t aS = sbase + sb * KV_STAGE_BYTES;
                uint32_t bS = sB0 + sb * KV_STAGE_BYTES;
                cp_async16(aS + st_off,  g_cnb + (size_t)(n0 + ld_row) * CTXd + k0 + ld_col);
                cp_async16(aS + st_off2, g_cnb + (size_t)(n0 + ld_row + 64) * CTXd + k0 + ld_col);
                cp_async16(bS + st_off,  W + (size_t)(o0 + ld_row) * CTXd + k0 + ld_col);
                cp_async16(bS + st_off2, W + (size_t)(o0 + ld_row + 64) * CTXd + k0 + ld_col);
            }
            cp_commit();
        }

        const int sc = it % KV_STAGES;
        const uint32_t aBuf = sbase + sc * KV_STAGE_BYTES;
        const uint32_t bBuf = sB0 + sc * KV_STAGE_BYTES;

        #pragma unroll
        for (int kk = 0; kk < 2; kk++) {
            uint32_t af[4][4];
            #pragma unroll
            for (int mt = 0; mt < 4; mt++) {
                uint32_t addr = aBuf + a_lm_base + (mt * 16 * KVA_STR + kk * 16) * 2;
                asm volatile(
                    "ldmatrix.sync.aligned.m8n8.x4.shared.b16 {%0,%1,%2,%3}, [%4];"
                    : "=r"(af[mt][0]), "=r"(af[mt][1]), "=r"(af[mt][2]), "=r"(af[mt][3])
                    : "r"(addr));
            }
            uint32_t bf[4][2];
            #pragma unroll
            for (int nt = 0; nt < 4; nt++) {
                uint32_t addr = bBuf + b_lm_part +
                    (((wn * 32 + nt * 8) * KVA_STR) + kk * 16) * 2;
                asm volatile(
                    "ldmatrix.sync.aligned.m8n8.x2.shared.b16 {%0,%1}, [%2];"
                    : "=r"(bf[nt][0]), "=r"(bf[nt][1]) : "r"(addr));
            }
            #pragma unroll
            for (int mt = 0; mt < 4; mt++)
                #pragma unroll
                for (int nt = 0; nt < 4; nt++) {
                    asm volatile(
                        "mma.sync.aligned.m16n8k16.row.col.f32.bf16.bf16.f32 "
                        "{%0,%1,%2,%3}, {%4,%5,%6,%7}, {%8,%9}, {%0,%1,%2,%3};"
                        : "+f"(acc[mt][nt][0]), "+f"(acc[mt][nt][1]),
                          "+f"(acc[mt][nt][2]), "+f"(acc[mt][nt][3])
                        : "r"(af[mt][0]), "r"(af[mt][1]), "r"(af[mt][2]), "r"(af[mt][3]),
                          "r"(bf[nt][0]), "r"(bf[nt][1]));
                }
        }
    }

    // epilogue: rows = n (guarded), cols = o (contiguous, bf16x2 store)
    const int row_base = n0 + wm * 64 + (lane >> 2);
    const int col_base = o0 + wn * 32 + (lane & 3) * 2;
    #pragma unroll
    for (int mt = 0; mt < 4; mt++) {
        #pragma unroll
        for (int half = 0; half < 2; half++) {
            int row = row_base + mt * 16 + half * 8;
            if (row >= NROWS) continue;
            #pragma unroll
            for (int nt = 0; nt < 4; nt++) {
                int col = col_base + nt * 8;
                float bi0 = bias[col], bi1 = bias[col + 1];
                *(__nv_bfloat162*)(out + (size_t)row * Cdim + col) =
                    __floats2bfloat162_rn(acc[mt][nt][half * 2] + bi0,
                                          acc[mt][nt][half * 2 + 1] + bi1);
            }
        }
    }
}

// ============================================================
// bf16 mma.sync GEMM with 3-stage cp.async pipeline.
// D[o,p] = sum_c W[o,c] * X[c,p] (+bias, +residual)
// ============================================================
#define A_STRIDE 40
#define B_STRIDE 136
#define STAGES 3
#define A_STAGE_BYTES (128 * A_STRIDE * 2)
#define B_STAGE_BYTES (32 * B_STRIDE * 2)
#define NIT (Cdim / 32)

template <bool BF16OUT>
__global__ void __launch_bounds__(256, 2)
mma_gemm(const __nv_bfloat16* __restrict__ Wb,
         const __nv_bfloat16* __restrict__ Xb,
         const float* __restrict__ bias,
         const float* __restrict__ residual,
         void* __restrict__ outv) {
    __shared__ __align__(16) char smem_[STAGES * (A_STAGE_BYTES + B_STAGE_BYTES)];

    const int tid  = threadIdx.x;
    const int warp = tid >> 5, lane = tid & 31;
    const int wm = warp >> 2, wn = warp & 3;
    const int p0 = blockIdx.x * 128;
    const int o0 = blockIdx.y * 128;
    const int b  = blockIdx.z;
    const __nv_bfloat16* Xbb = Xb + (size_t)b * Cdim * HWp;

    const uint32_t sbase = smem_u32(smem_);
    const uint32_t sB0 = sbase + STAGES * A_STAGE_BYTES;

    const int a_ld_row = tid >> 2;
    const int a_ld_col = (tid & 3) * 8;
    const int b_ld_row = tid >> 4;
    const int b_ld_col = (tid & 15) * 8;

    const uint32_t a_lm_base =
        ((wm * 64 + (lane & 15)) * A_STRIDE + (lane >> 4) * 8) * 2;
    const uint32_t b_lm_base = ((lane & 15) * B_STRIDE + wn * 32) * 2;

    const uint32_t a_st_off = (a_ld_row * A_STRIDE + a_ld_col) * 2;
    const uint32_t a_st_off2 = ((a_ld_row + 64) * A_STRIDE + a_ld_col) * 2;
    const uint32_t b_st_off = (b_ld_row * B_STRIDE + b_ld_col) * 2;
    const uint32_t b_st_off2 = ((b_ld_row + 16) * B_STRIDE + b_ld_col) * 2;

    float acc[4][4][4] = {};

    #pragma unroll
    for (int s = 0; s < STAGES - 1; s++) {
        const int k0 = s * 32;
        uint32_t aS = sbase + s * A_STAGE_BYTES;
        uint32_t bS = sB0 + s * B_STAGE_BYTES;
        cp_async16(aS + a_st_off,
                   Wb + (size_t)(o0 + a_ld_row) * Cdim + k0 + a_ld_col);
        cp_async16(aS + a_st_off2,
                   Wb + (size_t)(o0 + a_ld_row + 64) * Cdim + k0 + a_ld_col);
        cp_async16(bS + b_st_off,
                   Xbb + (size_t)(k0 + b_ld_row) * HWp + p0 + b_ld_col);
        cp_async16(bS + b_st_off2,
                   Xbb + (size_t)(k0 + b_ld_row + 16) * HWp + p0 + b_ld_col);
        cp_commit();
    }

    #pragma unroll 1
    for (int it = 0; it < NIT; it++) {
        cp_wait<STAGES - 2>();
        __syncthreads();
        {
            const int sl = it + STAGES - 1;
            if (sl < NIT) {
                const int k0 = sl * 32;
                const int sb = sl % STAGES;
                uint32_t aS = sbase + sb * A_STAGE_BYTES;
                uint32_t bS = sB0 + sb * B_STAGE_BYTES;
                cp_async16(aS + a_st_off,
                           Wb + (size_t)(o0 + a_ld_row) * Cdim + k0 + a_ld_col);
                cp_async16(aS + a_st_off2,
                           Wb + (size_t)(o0 + a_ld_row + 64) * Cdim + k0 + a_ld_col);
                cp_async16(bS + b_st_off,
                           Xbb + (size_t)(k0 + b_ld_row) * HWp + p0 + b_ld_col);
                cp_async16(bS + b_st_off2,
                           Xbb + (size_t)(k0 + b_ld_row + 16) * HWp + p0 + b_ld_col);
            }
            cp_commit();
        }

        const int sc = it % STAGES;
        const uint32_t aBuf = sbase + sc * A_STAGE_BYTES;
        const uint32_t bBuf = sB0 + sc * B_STAGE_BYTES;

        #pragma unroll
        for (int kk = 0; kk < 2; kk++) {
            uint32_t af[4][4];
            #pragma unroll
            for (int mt = 0; mt < 4; mt++) {
                uint32_t addr = aBuf + a_lm_base + (mt * 16 * A_STRIDE + kk * 16) * 2;
                asm volatile(
                    "ldmatrix.sync.aligned.m8n8.x4.shared.b16 {%0,%1,%2,%3}, [%4];"
                    : "=r"(af[mt][0]), "=r"(af[mt][1]), "=r"(af[mt][2]), "=r"(af[mt][3])
                    : "r"(addr));
            }
            uint32_t bf[4][2];
            #pragma unroll
            for (int nt = 0; nt < 4; nt++) {
                uint32_t addr = bBuf + b_lm_base + (kk * 16 * B_STRIDE + nt * 8) * 2;
                asm volatile(
                    "ldmatrix.sync.aligned.m8n8.x2.trans.shared.b16 {%0,%1}, [%2];"
                    : "=r"(bf[nt][0]), "=r"(bf[nt][1]) : "r"(addr));
            }
            #pragma unroll
            for (int mt = 0; mt < 4; mt++)
                #pragma unroll
                for (int nt = 0; nt < 4; nt++) {
                    asm volatile(
                        "mma.sync.aligned.m16n8k16.row.col.f32.bf16.bf16.f32 "
                        "{%0,%1,%2,%3}, {%4,%5,%6,%7}, {%8,%9}, {%0,%1,%2,%3};"
                        : "+f"(acc[mt][nt][0]), "+f"(acc[mt][nt][1]),
                          "+f"(acc[mt][nt][2]), "+f"(acc[mt][nt][3])
                        : "r"(af[mt][0]), "r"(af[mt][1]), "r"(af[mt][2]), "r"(af[mt][3]),
                          "r"(bf[nt][0]), "r"(bf[nt][1]));
                }
        }
    }

    const int row_base = o0 + wm * 64 + (lane >> 2);
    const int col_base = p0 + wn * 32 + (lane & 3) * 2;
    #pragma unroll
    for (int mt = 0; mt < 4; mt++) {
        #pragma unroll
        for (int half = 0; half < 2; half++) {
            int row = row_base + mt * 16 + half * 8;
            float bi = bias[row];
            size_t rb = ((size_t)b * Cdim + row) * HWp;
            #pragma unroll
            for (int nt = 0; nt < 4; nt++) {
                int col = col_base + nt * 8;
                float rx = acc[mt][nt][half * 2]     + bi;
                float ry = acc[mt][nt][half * 2 + 1] + bi;
                if (BF16OUT) {
                    __nv_bfloat16* outb = (__nv_bfloat16*)outv;
                    *(__nv_bfloat162*)(outb + rb + col) = __floats2bfloat162_rn(rx, ry);
                } else {
                    float* outf = (float*)outv;
                    if (residual) {
                        float2 rv = *(const float2*)(residual + rb + col);
                        rx += rv.x; ry += rv.y;
                    }
                    float2 r; r.x = rx; r.y = ry;
                    *(float2*)(outf + rb + col) = r;
                }
            }
        }
    }
}

// ============================================================
// Tensor-core flash attention: block = (b, h, 128-pixel tile)
// ============================================================
#define QS_STR 72
#define KS_STR 88
#define VS_STR 72
#define OD_STR 136
#define SPAD 80

__global__ void __launch_bounds__(128)
attn_mma_kernel() {
    __shared__ __align__(16) __nv_bfloat16 sQ[128 * QS_STR];  // reused as O [64][OD_STR]
    __shared__ __align__(16) __nv_bfloat16 sK[64 * KS_STR];   // K^T [d][s]
    __shared__ __align__(16) __nv_bfloat16 sV[SPAD * VS_STR]; // V [s][d]

    const int tid = threadIdx.x;
    const int warp = tid >> 5, lane = tid & 31;
    const int b = blockIdx.z, h = blockIdx.y;
    const int p0 = blockIdx.x * 128;
    const int ch0 = h * HD;

    const __nv_bfloat16* qg = g_qb + ((size_t)b * Cdim + ch0) * HWp + p0;
    #pragma unroll 4
    for (int i = tid; i < 128 * 64; i += 128) {
        int d = i >> 7, px = i & 127;
        sQ[px * QS_STR + d] = qg[(size_t)d * HWp + px];
    }
    const __nv_bfloat16* kg = g_kb + (size_t)b * Sctx * Cdim + ch0;
    #pragma unroll 4
    for (int i = tid; i < 77 * 64; i += 128) {
        int s = i >> 6, d = i & 63;
        sK[d * KS_STR + s] = kg[(size_t)s * Cdim + d];
    }
    for (int i = tid; i < 3 * 64; i += 128) {
        int s = 77 + (i >> 6), d = i & 63;
        sK[d * KS_STR + s] = __float2bfloat16(0.f);
    }
    const __nv_bfloat16* vg = g_vb + (size_t)b * Sctx * Cdim + ch0;
    // V rows 0..76: vectorized copy (8 bf16 per uint4)
    for (int i = tid; i < 77 * 8; i += 128) {
        int s = i >> 3, dd = (i & 7) * 8;
        *(uint4*)(sV + s * VS_STR + dd) = *(const uint4*)(vg + (size_t)s * Cdim + dd);
    }
    if (tid < 24) {  // zero rows 77..79 (3*64 = 24 uint4)
        int s = 77 + tid / 8, dd = (tid & 7) * 8;
        uint4 z = {0, 0, 0, 0};
        *(uint4*)(sV + s * VS_STR + dd) = z;
    }
    __syncthreads();

    const uint32_t qbase = smem_u32(sQ);
    const uint32_t kbase = smem_u32(sK);
    const uint32_t vbase = smem_u32(sV);

    float c[2][10][4];
    #pragma unroll
    for (int mt = 0; mt < 2; mt++)
        #pragma unroll
        for (int nt = 0; nt < 10; nt++)
            #pragma unroll
            for (int r = 0; r < 4; r++) c[mt][nt][r] = 0.f;

    const uint32_t a_lm = qbase +
        ((warp * 32 + (lane & 15)) * QS_STR + (lane >> 4) * 8) * 2;

    #pragma unroll
    for (int kk = 0; kk < 4; kk++) {
        uint32_t af[2][4];
        #pragma unroll
        for (int mt = 0; mt < 2; mt++) {
            uint32_t addr = a_lm + (mt * 16 * QS_STR + kk * 16) * 2;
            asm volatile(
                "ldmatrix.sync.aligned.m8n8.x4.shared.b16 {%0,%1,%2,%3}, [%4];"
                : "=r"(af[mt][0]), "=r"(af[mt][1]), "=r"(af[mt][2]), "=r"(af[mt][3])
                : "r"(addr));
        }
        uint32_t bf[10][2];
        #pragma unroll
        for (int nt = 0; nt < 10; nt++) {
            uint32_t addr = kbase + ((kk * 16 + (lane & 15)) * KS_STR + nt * 8) * 2;
            asm volatile(
                "ldmatrix.sync.aligned.m8n8.x2.trans.shared.b16 {%0,%1}, [%2];"
                : "=r"(bf[nt][0]), "=r"(bf[nt][1]) : "r"(addr));
        }
        #pragma unroll
        for (int mt = 0; mt < 2; mt++)
            #pragma unroll
            for (int nt = 0; nt < 10; nt++) {
                asm volatile(
                    "mma.sync.aligned.m16n8k16.row.col.f32.bf16.bf16.f32 "
                    "{%0,%1,%2,%3}, {%4,%5,%6,%7}, {%8,%9}, {%0,%1,%2,%3};"
                    : "+f"(c[mt][nt][0]), "+f"(c[mt][nt][1]),
                      "+f"(c[mt][nt][2]), "+f"(c[mt][nt][3])
                    : "r"(af[mt][0]), "r"(af[mt][1]), "r"(af[mt][2]), "r"(af[mt][3]),
                      "r"(bf[nt][0]), "r"(bf[nt][1]));
            }
    }
    __syncthreads();

    const float scale = 0.125f;
    uint32_t pu[2][10][2];
    float iv[2][2];
    #pragma unroll
    for (int mt = 0; mt < 2; mt++) {
        float mx0 = -1e30f, mx1 = -1e30f;
        #pragma unroll
        for (int nt = 0; nt < 10; nt++) {
            int col = nt * 8 + (lane & 3) * 2;
            c[mt][nt][0] = (col     < Sctx) ? c[mt][nt][0] * scale : -1e30f;
            c[mt][nt][1] = (col + 1 < Sctx) ? c[mt][nt][1] * scale : -1e30f;
            c[mt][nt][2] = (col     < Sctx) ? c[mt][nt][2] * scale : -1e30f;
            c[mt][nt][3] = (col + 1 < Sctx) ? c[mt][nt][3] * scale : -1e30f;
            mx0 = fmaxf(mx0, fmaxf(c[mt][nt][0], c[mt][nt][1]));
            mx1 = fmaxf(mx1, fmaxf(c[mt][nt][2], c[mt][nt][3]));
        }
        mx0 = fmaxf(mx0, __shfl_xor_sync(0xffffffffu, mx0, 1));
        mx0 = fmaxf(mx0, __shfl_xor_sync(0xffffffffu, mx0, 2));
        mx1 = fmaxf(mx1, __shfl_xor_sync(0xffffffffu, mx1, 1));
        mx1 = fmaxf(mx1, __shfl_xor_sync(0xffffffffu, mx1, 2));
        float s0 = 0.f, s1 = 0.f;
        #pragma unroll
        for (int nt = 0; nt < 10; nt++) {
            float e0 = __expf(c[mt][nt][0] - mx0);
            float e1 = __expf(c[mt][nt][1] - mx0);
            float e2 = __expf(c[mt][nt][2] - mx1);
            float e3 = __expf(c[mt][nt][3] - mx1);
            s0 += e0 + e1; s1 += e2 + e3;
            pu[mt][nt][0] = pack_bf16(e0, e1);
            pu[mt][nt][1] = pack_bf16(e2, e3);
        }
        s0 += __shfl_xor_sync(0xffffffffu, s0, 1);
        s0 += __shfl_xor_sync(0xffffffffu, s0, 2);
        s1 += __shfl_xor_sync(0xffffffffu, s1, 1);
        s1 += __shfl_xor_sync(0xffffffffu, s1, 2);
        iv[mt][0] = 1.f / s0;
        iv[mt][1] = 1.f / s1;
    }

    float o[2][8][4];
    #pragma unroll
    for (int mt = 0; mt < 2; mt++)
        #pragma unroll
        for (int nt = 0; nt < 8; nt++)
            #pragma unroll
            for (int r = 0; r < 4; r++) o[mt][nt][r] = 0.f;

    #pragma unroll
    for (int kk = 0; kk < 5; kk++) {
        uint32_t bv[8][2];
        #pragma unroll
        for (int nt = 0; nt < 8; nt++) {
            uint32_t addr = vbase + ((kk * 16 + (lane & 15)) * VS_STR + nt * 8) * 2;
            asm volatile(
                "ldmatrix.sync.aligned.m8n8.x2.trans.shared.b16 {%0,%1}, [%2];"
                : "=r"(bv[nt][0]), "=r"(bv[nt][1]) : "r"(addr));
        }
        #pragma unroll
        for (int mt = 0; mt < 2; mt++) {
            uint32_t a0 = pu[mt][2 * kk][0];
            uint32_t a1 = pu[mt][2 * kk][1];
            uint32_t a2 = pu[mt][2 * kk + 1][0];
            uint32_t a3 = pu[mt][2 * kk + 1][1];
            #pragma unroll
            for (int nt = 0; nt < 8; nt++) {
                asm volatile(
                    "mma.sync.aligned.m16n8k16.row.col.f32.bf16.bf16.f32 "
                    "{%0,%1,%2,%3}, {%4,%5,%6,%7}, {%8,%9}, {%0,%1,%2,%3};"
                    : "+f"(o[mt][nt][0]), "+f"(o[mt][nt][1]),
                      "+f"(o[mt][nt][2]), "+f"(o[mt][nt][3])
                    : "r"(a0), "r"(a1), "r"(a2), "r"(a3),
                      "r"(bv[nt][0]), "r"(bv[nt][1]));
            }
        }
    }

    __nv_bfloat16* Od = sQ;
    #pragma unroll
    for (int mt = 0; mt < 2; mt++) {
        int pxa = warp * 32 + mt * 16 + (lane >> 2);
        #pragma unroll
        for (int nt = 0; nt < 8; nt++) {
            int d = nt * 8 + (lane & 3) * 2;
            Od[d * OD_STR + pxa]           = __float2bfloat16(o[mt][nt][0] * iv[mt][0]);
            Od[(d + 1) * OD_STR + pxa]     = __float2bfloat16(o[mt][nt][1] * iv[mt][0]);
            Od[d * OD_STR + pxa + 8]       = __float2bfloat16(o[mt][nt][2] * iv[mt][1]);
            Od[(d + 1) * OD_STR + pxa + 8] = __float2bfloat16(o[mt][nt][3] * iv[mt][1]);
        }
    }
    __syncthreads();

    __nv_bfloat16* og = g_aob + ((size_t)b * Cdim + ch0) * HWp + p0;
    #pragma unroll 2
    for (int i = tid; i < 64 * 16; i += 128) {
        int d = i >> 4, cc = (i & 15) * 8;
        *(uint4*)(og + (size_t)d * HWp + cc) = *(const uint4*)(Od + d * OD_STR + cc);
    }
}

// ============================================================
extern "C" void kernel_launch(void* const* d_in, const int* in_sizes, int n_in,
                              void* d_out, int out_size) {
    const float* x       = (const float*)d_in[0];
    const float* context = (const float*)d_in[1];
    const float* gn_w    = (const float*)d_in[2];
    const float* gn_b    = (const float*)d_in[3];
    const float* ln_w    = (const float*)d_in[4];
    const float* ln_b    = (const float*)d_in[5];
    const float* q_w     = (const float*)d_in[6];
    const float* q_b     = (const float*)d_in[7];
    const float* k_w     = (const float*)d_in[8];
    const float* k_b     = (const float*)d_in[9];
    const float* v_w     = (const float*)d_in[10];
    const float* v_b     = (const float*)d_in[11];
    const float* out_w   = (const float*)d_in[12];
    const float* out_b   = (const float*)d_in[13];
    float* out = (float*)d_out;

    __nv_bfloat16 *qb = nullptr, *xnb = nullptr, *aob = nullptr, *qwb = nullptr, *owb = nullptr;
    cudaGetSymbolAddress((void**)&qb,  g_qb);
    cudaGetSymbolAddress((void**)&xnb, g_xnb);
    cudaGetSymbolAddress((void**)&aob, g_aob);
    cudaGetSymbolAddress((void**)&qwb, g_qwb);
    cudaGetSymbolAddress((void**)&owb, g_owb);

    gn_fuse_kernel<<<Bsz * NGROUPS, 512>>>(x, gn_w, gn_b);
    ln_kernel<<<Bsz * Sctx, 256>>>(context, ln_w, ln_b);
    conv_w_kernel<<<(2 * NQW + 2 * NKW) / 512, 512>>>(q_w, out_w, k_w, v_w);
    kv_mma<<<dim3(Cdim / 128, NROWS_PAD / 128, 2), 256>>>(k_b, v_b);
    mma_gemm<true><<<dim3(HWp / 128, Cdim / 128, Bsz), 256>>>(
        qwb, xnb, q_b, nullptr, qb);
    attn_mma_kernel<<<dim3(HWp / 128, NHEADS, Bsz), 128>>>();
    mma_gemm<false><<<dim3(HWp / 128, Cdim / 128, Bsz), 256>>>(
        owb, aob, out_b, x, out);
}

// round 8
// speedup vs baseline: 4.8736x; 1.0325x over previous
#include <cuda_runtime.h>
#include <cuda_bf16.h>
#include <cstdint>

#define Bsz 16
#define Cdim 512
#define HWp 4096
#define Sctx 77
#define CTXd 768
#define NHEADS 8
#define HD 64
#define NGROUPS 32
#define CPG 16
#define EPSV 1e-5f
#define NROWS (Bsz * Sctx)      // 1232
#define NROWS_PAD 1280

// ---- scratch (static device globals; no runtime allocation) ----
__device__ __nv_bfloat16 g_qb [(size_t)Bsz * Cdim * HWp]; // Q  (B, C, HW) bf16
__device__ __nv_bfloat16 g_xnb[(size_t)Bsz * Cdim * HWp]; // GN(x) bf16
__device__ __nv_bfloat16 g_aob[(size_t)Bsz * Cdim * HWp]; // attn out bf16
__device__ __nv_bfloat16 g_cnb[(size_t)NROWS_PAD * CTXd]; // layernormed ctx bf16 (padded)
__device__ __nv_bfloat16 g_kb [(size_t)NROWS * Cdim];     // K bf16 (n, C)
__device__ __nv_bfloat16 g_vb [(size_t)NROWS * Cdim];     // V bf16 (n, C)
__device__ __nv_bfloat16 g_qwb[Cdim * Cdim];              // q_w bf16
__device__ __nv_bfloat16 g_owb[Cdim * Cdim];              // out_w bf16
__device__ __nv_bfloat16 g_kwb[Cdim * CTXd];              // k_w bf16
__device__ __nv_bfloat16 g_vwb[Cdim * CTXd];              // v_w bf16

__device__ __forceinline__ uint32_t smem_u32(const void* p) {
    uint32_t a;
    asm("{ .reg .u64 t; cvta.to.shared.u64 t, %1; cvt.u32.u64 %0, t; }"
        : "=r"(a) : "l"(p));
    return a;
}
__device__ __forceinline__ uint32_t pack_bf16(float lo, float hi) {
    __nv_bfloat162 p = __floats2bfloat162_rn(lo, hi);
    return *reinterpret_cast<uint32_t*>(&p);
}
__device__ __forceinline__ void cp_async16(uint32_t dst, const void* src) {
    asm volatile("cp.async.cg.shared.global [%0], [%1], 16;"
                 :: "r"(dst), "l"(src));
}
__device__ __forceinline__ void cp_commit() {
    asm volatile("cp.async.commit_group;" ::: "memory");
}
template <int N>
__device__ __forceinline__ void cp_wait() {
    asm volatile("cp.async.wait_group %0;" :: "n"(N) : "memory");
}

// ============================================================
// Fused GroupNorm: one block per (b,g); reduce, then apply + bf16
// ============================================================
__global__ void __launch_bounds__(512)
gn_fuse_kernel(const float* __restrict__ x,
               const float* __restrict__ gnw,
               const float* __restrict__ gnb) {
    int blk = blockIdx.x;
    int b = blk / NGROUPS, g = blk % NGROUPS;
    const size_t base = ((size_t)b * Cdim + (size_t)g * CPG) * HWp;
    const float4* p = (const float4*)(x + base);
    const int n4 = CPG * HWp / 4;  // 16384
    float s = 0.f, sq = 0.f;
    for (int i = threadIdx.x; i < n4; i += blockDim.x) {
        float4 v = p[i];
        s  += v.x + v.y + v.z + v.w;
        sq += v.x * v.x + v.y * v.y + v.z * v.z + v.w * v.w;
    }
    __shared__ float ss[32], ssq[32];
    __shared__ float sa[CPG], sb[CPG];
    #pragma unroll
    for (int o = 16; o > 0; o >>= 1) {
        s  += __shfl_down_sync(0xffffffffu, s, o);
        sq += __shfl_down_sync(0xffffffffu, sq, o);
    }
    int wid = threadIdx.x >> 5, lid = threadIdx.x & 31;
    if (lid == 0) { ss[wid] = s; ssq[wid] = sq; }
    __syncthreads();
    if (wid == 0) {
        int nw = blockDim.x >> 5;
        s  = (lid < nw) ? ss[lid]  : 0.f;
        sq = (lid < nw) ? ssq[lid] : 0.f;
        #pragma unroll
        for (int o = 16; o > 0; o >>= 1) {
            s  += __shfl_down_sync(0xffffffffu, s, o);
            sq += __shfl_down_sync(0xffffffffu, sq, o);
        }
        if (lid == 0) { ss[0] = s; ssq[0] = sq; }
    }
    __syncthreads();
    {
        const float invn = 1.f / (float)(CPG * HWp);
        float mean = ss[0] * invn;
        float var  = ssq[0] * invn - mean * mean;
        float rstd = rsqrtf(var + EPSV);
        if (threadIdx.x < CPG) {
            int c = g * CPG + threadIdx.x;
            float a = rstd * gnw[c];
            sa[threadIdx.x] = a;
            sb[threadIdx.x] = gnb[c] - mean * a;
        }
    }
    __syncthreads();
    __nv_bfloat162* dst = (__nv_bfloat162*)(g_xnb + base);
    const int per_c4 = HWp / 4;
    for (int i = threadIdx.x; i < n4; i += blockDim.x) {
        int c = i / per_c4;
        float a = sa[c], bb = sb[c];
        float4 v = p[i];
        dst[2 * i]     = __floats2bfloat162_rn(v.x * a + bb, v.y * a + bb);
        dst[2 * i + 1] = __floats2bfloat162_rn(v.z * a + bb, v.w * a + bb);
    }
}

// ============================================================
// LayerNorm on context -> bf16
// ============================================================
__global__ void ln_kernel(const float* __restrict__ ctx,
                          const float* __restrict__ w,
                          const float* __restrict__ bb) {
    int row = blockIdx.x;
    const float* xr = ctx + (size_t)row * CTXd;
    float s = 0.f, sq = 0.f;
    for (int i = threadIdx.x; i < CTXd; i += blockDim.x) {
        float v = xr[i];
        s += v; sq += v * v;
    }
    __shared__ float ss[32], ssq[32];
    __shared__ float smean, srstd;
    #pragma unroll
    for (int o = 16; o > 0; o >>= 1) {
        s  += __shfl_down_sync(0xffffffffu, s, o);
        sq += __shfl_down_sync(0xffffffffu, sq, o);
    }
    int wid = threadIdx.x >> 5, lid = threadIdx.x & 31;
    if (lid == 0) { ss[wid] = s; ssq[wid] = sq; }
    __syncthreads();
    if (wid == 0) {
        int nw = blockDim.x >> 5;
        s  = (lid < nw) ? ss[lid]  : 0.f;
        sq = (lid < nw) ? ssq[lid] : 0.f;
        #pragma unroll
        for (int o = 16; o > 0; o >>= 1) {
            s  += __shfl_down_sync(0xffffffffu, s, o);
            sq += __shfl_down_sync(0xffffffffu, sq, o);
        }
        if (lid == 0) {
            const float invn = 1.f / (float)CTXd;
            float mean = s * invn;
            float var  = sq * invn - mean * mean;
            smean = mean;
            srstd = rsqrtf(var + EPSV);
        }
    }
    __syncthreads();
    float mean = smean, rstd = srstd;
    for (int i = threadIdx.x; i < CTXd; i += blockDim.x) {
        g_cnb[(size_t)row * CTXd + i] =
            __float2bfloat16((xr[i] - mean) * rstd * w[i] + bb[i]);
    }
}

// ============================================================
// Weight bf16 conversion (q_w, out_w, k_w, v_w)
// ============================================================
#define NQW (Cdim * Cdim)
#define NKW (Cdim * CTXd)
__global__ void conv_w_kernel(const float* __restrict__ qw, const float* __restrict__ ow,
                              const float* __restrict__ kw, const float* __restrict__ vw) {
    int i = blockIdx.x * blockDim.x + threadIdx.x;
    if (i < NQW)                 g_qwb[i] = __float2bfloat16(qw[i]);
    else if (i < 2 * NQW)        g_owb[i - NQW] = __float2bfloat16(ow[i - NQW]);
    else if (i < 2 * NQW + NKW)  g_kwb[i - 2 * NQW] = __float2bfloat16(kw[i - 2 * NQW]);
    else                         g_vwb[i - 2 * NQW - NKW] = __float2bfloat16(vw[i - 2 * NQW - NKW]);
}

// ============================================================
// K/V projection via bf16 mma.sync (NT) — unchanged from R7
// ============================================================
#define KVA_STR 40
#define KV_STAGE_BYTES (128 * KVA_STR * 2)
#define KV_STAGES 3
#define KV_NIT (CTXd / 32)

__global__ void __launch_bounds__(256, 2)
kv_mma(const float* __restrict__ kb_, const float* __restrict__ vb_) {
    __shared__ __align__(16) char smem_[KV_STAGES * 2 * KV_STAGE_BYTES];

    const __nv_bfloat16* W    = blockIdx.z ? g_vwb : g_kwb;
    const float*         bias = blockIdx.z ? vb_ : kb_;
    __nv_bfloat16*       out  = blockIdx.z ? g_vb : g_kb;

    const int tid  = threadIdx.x;
    const int warp = tid >> 5, lane = tid & 31;
    const int wm = warp >> 2, wn = warp & 3;
    const int n0 = blockIdx.y * 128;
    const int o0 = blockIdx.x * 128;

    const uint32_t sbase = smem_u32(smem_);
    const uint32_t sB0 = sbase + KV_STAGES * KV_STAGE_BYTES;

    const int ld_row = tid >> 2;
    const int ld_col = (tid & 3) * 8;

    const uint32_t st_off  = (ld_row * KVA_STR + ld_col) * 2;
    const uint32_t st_off2 = ((ld_row + 64) * KVA_STR + ld_col) * 2;

    const uint32_t a_lm_base =
        ((wm * 64 + (lane & 15)) * KVA_STR + (lane >> 4) * 8) * 2;
    const uint32_t b_lm_part =
        ((lane & 7) * KVA_STR + ((lane >> 3) & 1) * 8) * 2;

    float acc[4][4][4] = {};

    #pragma unroll
    for (int s = 0; s < KV_STAGES - 1; s++) {
        const int k0 = s * 32;
        uint32_t aS = sbase + s * KV_STAGE_BYTES;
        uint32_t bS = sB0 + s * KV_STAGE_BYTES;
        cp_async16(aS + st_off,  g_cnb + (size_t)(n0 + ld_row) * CTXd + k0 + ld_col);
        cp_async16(aS + st_off2, g_cnb + (size_t)(n0 + ld_row + 64) * CTXd + k0 + ld_col);
        cp_async16(bS + st_off,  W + (size_t)(o0 + ld_row) * CTXd + k0 + ld_col);
        cp_async16(bS + st_off2, W + (size_t)(o0 + ld_row + 64) * CTXd + k0 + ld_col);
        cp_commit();
    }

    #pragma unroll 1
    for (int it = 0; it < KV_NIT; it++) {
        cp_wait<KV_STAGES - 2>();
        __syncthreads();
        {
            const int sl = it + KV_STAGES - 1;
            if (sl < KV_NIT) {
                const int k0 = sl * 32;
                const int sb = sl % KV_STAGES;
                uint32_t aS = sbase + sb * KV_STAGE_BYTES;
                uint32_t bS = sB0 + sb * KV_STAGE_BYTES;
                cp_async16(aS + st_off,  g_cnb + (size_t)(n0 + ld_row) * CTXd + k0 + ld_col);
                cp_async16(aS + st_off2, g_cnb + (size_t)(n0 + ld_row + 64) * CTXd + k0 + ld_col);
                cp_async16(bS + st_off,  W + (size_t)(o0 + ld_row) * CTXd + k0 + ld_col);
                cp_async16(bS + st_off2, W + (size_t)(o0 + ld_row + 64) * CTXd + k0 + ld_col);
            }
            cp_commit();
        }

        const int sc = it % KV_STAGES;
        const uint32_t aBuf = sbase + sc * KV_STAGE_BYTES;
        const uint32_t bBuf = sB0 + sc * KV_STAGE_BYTES;

        #pragma unroll
        for (int kk = 0; kk < 2; kk++) {
            uint32_t af[4][4];
            #pragma unroll
            for (int mt = 0; mt < 4; mt++) {
                uint32_t addr = aBuf + a_lm_base + (mt * 16 * KVA_STR + kk * 16) * 2;
                asm volatile(
                    "ldmatrix.sync.aligned.m8n8.x4.shared.b16 {%0,%1,%2,%3}, [%4];"
                    : "=r"(af[mt][0]), "=r"(af[mt][1]), "=r"(af[mt][2]), "=r"(af[mt][3])
                    : "r"(addr));
            }
            uint32_t bf[4][2];
            #pragma unroll
            for (int nt = 0; nt < 4; nt++) {
                uint32_t addr = bBuf + b_lm_part +
                    (((wn * 32 + nt * 8) * KVA_STR) + kk * 16) * 2;
                asm volatile(
                    "ldmatrix.sync.aligned.m8n8.x2.shared.b16 {%0,%1}, [%2];"
                    : "=r"(bf[nt][0]), "=r"(bf[nt][1]) : "r"(addr));
            }
            #pragma unroll
            for (int mt = 0; mt < 4; mt++)
                #pragma unroll
                for (int nt = 0; nt < 4; nt++) {
                    asm volatile(
                        "mma.sync.aligned.m16n8k16.row.col.f32.bf16.bf16.f32 "
                        "{%0,%1,%2,%3}, {%4,%5,%6,%7}, {%8,%9}, {%0,%1,%2,%3};"
                        : "+f"(acc[mt][nt][0]), "+f"(acc[mt][nt][1]),
                          "+f"(acc[mt][nt][2]), "+f"(acc[mt][nt][3])
                        : "r"(af[mt][0]), "r"(af[mt][1]), "r"(af[mt][2]), "r"(af[mt][3]),
                          "r"(bf[nt][0]), "r"(bf[nt][1]));
                }
        }
    }

    const int row_base = n0 + wm * 64 + (lane >> 2);
    const int col_base = o0 + wn * 32 + (lane & 3) * 2;
    #pragma unroll
    for (int mt = 0; mt < 4; mt++) {
        #pragma unroll
        for (int half = 0; half < 2; half++) {
            int row = row_base + mt * 16 + half * 8;
            if (row >= NROWS) continue;
            #pragma unroll
            for (int nt = 0; nt < 4; nt++) {
                int col = col_base + nt * 8;
                float bi0 = bias[col], bi1 = bias[col + 1];
                *(__nv_bfloat162*)(out + (size_t)row * Cdim + col) =
                    __floats2bfloat162_rn(acc[mt][nt][half * 2] + bi0,
                                          acc[mt][nt][half * 2 + 1] + bi1);
            }
        }
    }
}

// ============================================================
// bf16 mma.sync GEMM, 3-stage cp.async, 128 threads / 4 warps,
// warp tile 64x64 (2x2 warps). D[o,p] = sum_c W[o,c]*X[c,p]
// ============================================================
#define A_STRIDE 40
#define B_STRIDE 136
#define STAGES 3
#define A_STAGE_BYTES (128 * A_STRIDE * 2)
#define B_STAGE_BYTES (32 * B_STRIDE * 2)
#define NIT (Cdim / 32)

template <bool BF16OUT>
__global__ void __launch_bounds__(128, 2)
mma_gemm(const __nv_bfloat16* __restrict__ Wb,
         const __nv_bfloat16* __restrict__ Xb,
         const float* __restrict__ bias,
         const float* __restrict__ residual,
         void* __restrict__ outv) {
    __shared__ __align__(16) char smem_[STAGES * (A_STAGE_BYTES + B_STAGE_BYTES)];

    const int tid  = threadIdx.x;
    const int warp = tid >> 5, lane = tid & 31;
    const int wm = warp >> 1, wn = warp & 1;   // 2x2 warps, tile 64x64
    const int p0 = blockIdx.x * 128;
    const int o0 = blockIdx.y * 128;
    const int b  = blockIdx.z;
    const __nv_bfloat16* Xbb = Xb + (size_t)b * Cdim * HWp;

    const uint32_t sbase = smem_u32(smem_);
    const uint32_t sB0 = sbase + STAGES * A_STAGE_BYTES;

    // loaders (128 threads): A 128x32 -> 4 chunks, B 32x128 -> 4 chunks
    const int a_ld_row = tid >> 2;            // 0..31 (+32*j)
    const int a_ld_col = (tid & 3) * 8;
    const int b_ld_row = tid >> 4;            // 0..7  (+8*j)
    const int b_ld_col = (tid & 15) * 8;

    const uint32_t a_lm_base =
        ((wm * 64 + (lane & 15)) * A_STRIDE + (lane >> 4) * 8) * 2;
    const uint32_t b_lm_base = ((lane & 15) * B_STRIDE + wn * 64) * 2;

    uint32_t a_st[4], b_st[4];
    #pragma unroll
    for (int j = 0; j < 4; j++) {
        a_st[j] = ((a_ld_row + j * 32) * A_STRIDE + a_ld_col) * 2;
        b_st[j] = ((b_ld_row + j * 8) * B_STRIDE + b_ld_col) * 2;
    }

    float acc[4][8][4] = {};

    #pragma unroll
    for (int s = 0; s < STAGES - 1; s++) {
        const int k0 = s * 32;
        uint32_t aS = sbase + s * A_STAGE_BYTES;
        uint32_t bS = sB0 + s * B_STAGE_BYTES;
        #pragma unroll
        for (int j = 0; j < 4; j++) {
            cp_async16(aS + a_st[j],
                       Wb + (size_t)(o0 + a_ld_row + j * 32) * Cdim + k0 + a_ld_col);
            cp_async16(bS + b_st[j],
                       Xbb + (size_t)(k0 + b_ld_row + j * 8) * HWp + p0 + b_ld_col);
        }
        cp_commit();
    }

    #pragma unroll 1
    for (int it = 0; it < NIT; it++) {
        cp_wait<STAGES - 2>();
        __syncthreads();
        {
            const int sl = it + STAGES - 1;
            if (sl < NIT) {
                const int k0 = sl * 32;
                const int sb = sl % STAGES;
                uint32_t aS = sbase + sb * A_STAGE_BYTES;
                uint32_t bS = sB0 + sb * B_STAGE_BYTES;
                #pragma unroll
                for (int j = 0; j < 4; j++) {
                    cp_async16(aS + a_st[j],
                               Wb + (size_t)(o0 + a_ld_row + j * 32) * Cdim + k0 + a_ld_col);
                    cp_async16(bS + b_st[j],
                               Xbb + (size_t)(k0 + b_ld_row + j * 8) * HWp + p0 + b_ld_col);
                }
            }
            cp_commit();
        }

        const int sc = it % STAGES;
        const uint32_t aBuf = sbase + sc * A_STAGE_BYTES;
        const uint32_t bBuf = sB0 + sc * B_STAGE_BYTES;

        #pragma unroll
        for (int kk = 0; kk < 2; kk++) {
            uint32_t af[4][4];
            #pragma unroll
            for (int mt = 0; mt < 4; mt++) {
                uint32_t addr = aBuf + a_lm_base + (mt * 16 * A_STRIDE + kk * 16) * 2;
                asm volatile(
                    "ldmatrix.sync.aligned.m8n8.x4.shared.b16 {%0,%1,%2,%3}, [%4];"
                    : "=r"(af[mt][0]), "=r"(af[mt][1]), "=r"(af[mt][2]), "=r"(af[mt][3])
                    : "r"(addr));
            }
            uint32_t bf[8][2];
            #pragma unroll
            for (int nt = 0; nt < 8; nt++) {
                uint32_t addr = bBuf + b_lm_base + (kk * 16 * B_STRIDE + nt * 8) * 2;
                asm volatile(
                    "ldmatrix.sync.aligned.m8n8.x2.trans.shared.b16 {%0,%1}, [%2];"
                    : "=r"(bf[nt][0]), "=r"(bf[nt][1]) : "r"(addr));
            }
            #pragma unroll
            for (int mt = 0; mt < 4; mt++)
                #pragma unroll
                for (int nt = 0; nt < 8; nt++) {
                    asm volatile(
                        "mma.sync.aligned.m16n8k16.row.col.f32.bf16.bf16.f32 "
                        "{%0,%1,%2,%3}, {%4,%5,%6,%7}, {%8,%9}, {%0,%1,%2,%3};"
                        : "+f"(acc[mt][nt][0]), "+f"(acc[mt][nt][1]),
                          "+f"(acc[mt][nt][2]), "+f"(acc[mt][nt][3])
                        : "r"(af[mt][0]), "r"(af[mt][1]), "r"(af[mt][2]), "r"(af[mt][3]),
                          "r"(bf[nt][0]), "r"(bf[nt][1]));
                }
        }
    }

    const int row_base = o0 + wm * 64 + (lane >> 2);
    const int col_base = p0 + wn * 64 + (lane & 3) * 2;
    #pragma unroll
    for (int mt = 0; mt < 4; mt++) {
        #pragma unroll
        for (int half = 0; half < 2; half++) {
            int row = row_base + mt * 16 + half * 8;
            float bi = bias[row];
            size_t rb = ((size_t)b * Cdim + row) * HWp;
            #pragma unroll
            for (int nt = 0; nt < 8; nt++) {
                int col = col_base + nt * 8;
                float rx = acc[mt][nt][half * 2]     + bi;
                float ry = acc[mt][nt][half * 2 + 1] + bi;
                if (BF16OUT) {
                    __nv_bfloat16* outb = (__nv_bfloat16*)outv;
                    *(__nv_bfloat162*)(outb + rb + col) = __floats2bfloat162_rn(rx, ry);
                } else {
                    float* outf = (float*)outv;
                    if (residual) {
                        float2 rv = *(const float2*)(residual + rb + col);
                        rx += rv.x; ry += rv.y;
                    }
                    float2 r; r.x = rx; r.y = ry;
                    *(float2*)(outf + rb + col) = r;
                }
            }
        }
    }
}

// ============================================================
// Tensor-core flash attention — unchanged from R7
// ============================================================
#define QS_STR 72
#define KS_STR 88
#define VS_STR 72
#define OD_STR 136
#define SPAD 80

__global__ void __launch_bounds__(128)
attn_mma_kernel() {
    __shared__ __align__(16) __nv_bfloat16 sQ[128 * QS_STR];
    __shared__ __align__(16) __nv_bfloat16 sK[64 * KS_STR];
    __shared__ __align__(16) __nv_bfloat16 sV[SPAD * VS_STR];

    const int tid = threadIdx.x;
    const int warp = tid >> 5, lane = tid & 31;
    const int b = blockIdx.z, h = blockIdx.y;
    const int p0 = blockIdx.x * 128;
    const int ch0 = h * HD;

    const __nv_bfloat16* qg = g_qb + ((size_t)b * Cdim + ch0) * HWp + p0;
    #pragma unroll 4
    for (int i = tid; i < 128 * 64; i += 128) {
        int d = i >> 7, px = i & 127;
        sQ[px * QS_STR + d] = qg[(size_t)d * HWp + px];
    }
    const __nv_bfloat16* kg = g_kb + (size_t)b * Sctx * Cdim + ch0;
    #pragma unroll 4
    for (int i = tid; i < 77 * 64; i += 128) {
        int s = i >> 6, d = i & 63;
        sK[d * KS_STR + s] = kg[(size_t)s * Cdim + d];
    }
    for (int i = tid; i < 3 * 64; i += 128) {
        int s = 77 + (i >> 6), d = i & 63;
        sK[d * KS_STR + s] = __float2bfloat16(0.f);
    }
    const __nv_bfloat16* vg = g_vb + (size_t)b * Sctx * Cdim + ch0;
    for (int i = tid; i < 77 * 8; i += 128) {
        int s = i >> 3, dd = (i & 7) * 8;
        *(uint4*)(sV + s * VS_STR + dd) = *(const uint4*)(vg + (size_t)s * Cdim + dd);
    }
    if (tid < 24) {
        int s = 77 + tid / 8, dd = (tid & 7) * 8;
        uint4 z = {0, 0, 0, 0};
        *(uint4*)(sV + s * VS_STR + dd) = z;
    }
    __syncthreads();

    const uint32_t qbase = smem_u32(sQ);
    const uint32_t kbase = smem_u32(sK);
    const uint32_t vbase = smem_u32(sV);

    float c[2][10][4];
    #pragma unroll
    for (int mt = 0; mt < 2; mt++)
        #pragma unroll
        for (int nt = 0; nt < 10; nt++)
            #pragma unroll
            for (int r = 0; r < 4; r++) c[mt][nt][r] = 0.f;

    const uint32_t a_lm = qbase +
        ((warp * 32 + (lane & 15)) * QS_STR + (lane >> 4) * 8) * 2;

    #pragma unroll
    for (int kk = 0; kk < 4; kk++) {
        uint32_t af[2][4];
        #pragma unroll
        for (int mt = 0; mt < 2; mt++) {
            uint32_t addr = a_lm + (mt * 16 * QS_STR + kk * 16) * 2;
            asm volatile(
                "ldmatrix.sync.aligned.m8n8.x4.shared.b16 {%0,%1,%2,%3}, [%4];"
                : "=r"(af[mt][0]), "=r"(af[mt][1]), "=r"(af[mt][2]), "=r"(af[mt][3])
                : "r"(addr));
        }
        uint32_t bf[10][2];
        #pragma unroll
        for (int nt = 0; nt < 10; nt++) {
            uint32_t addr = kbase + ((kk * 16 + (lane & 15)) * KS_STR + nt * 8) * 2;
            asm volatile(
                "ldmatrix.sync.aligned.m8n8.x2.trans.shared.b16 {%0,%1}, [%2];"
                : "=r"(bf[nt][0]), "=r"(bf[nt][1]) : "r"(addr));
        }
        #pragma unroll
        for (int mt = 0; mt < 2; mt++)
            #pragma unroll
            for (int nt = 0; nt < 10; nt++) {
                asm volatile(
                    "mma.sync.aligned.m16n8k16.row.col.f32.bf16.bf16.f32 "
                    "{%0,%1,%2,%3}, {%4,%5,%6,%7}, {%8,%9}, {%0,%1,%2,%3};"
                    : "+f"(c[mt][nt][0]), "+f"(c[mt][nt][1]),
                      "+f"(c[mt][nt][2]), "+f"(c[mt][nt][3])
                    : "r"(af[mt][0]), "r"(af[mt][1]), "r"(af[mt][2]), "r"(af[mt][3]),
                      "r"(bf[nt][0]), "r"(bf[nt][1]));
            }
    }
    __syncthreads();

    const float scale = 0.125f;
    uint32_t pu[2][10][2];
    float iv[2][2];
    #pragma unroll
    for (int mt = 0; mt < 2; mt++) {
        float mx0 = -1e30f, mx1 = -1e30f;
        #pragma unroll
        for (int nt = 0; nt < 10; nt++) {
            int col = nt * 8 + (lane & 3) * 2;
            c[mt][nt][0] = (col     < Sctx) ? c[mt][nt][0] * scale : -1e30f;
            c[mt][nt][1] = (col + 1 < Sctx) ? c[mt][nt][1] * scale : -1e30f;
            c[mt][nt][2] = (col     < Sctx) ? c[mt][nt][2] * scale : -1e30f;
            c[mt][nt][3] = (col + 1 < Sctx) ? c[mt][nt][3] * scale : -1e30f;
            mx0 = fmaxf(mx0, fmaxf(c[mt][nt][0], c[mt][nt][1]));
            mx1 = fmaxf(mx1, fmaxf(c[mt][nt][2], c[mt][nt][3]));
        }
        mx0 = fmaxf(mx0, __shfl_xor_sync(0xffffffffu, mx0, 1));
        mx0 = fmaxf(mx0, __shfl_xor_sync(0xffffffffu, mx0, 2));
        mx1 = fmaxf(mx1, __shfl_xor_sync(0xffffffffu, mx1, 1));
        mx1 = fmaxf(mx1, __shfl_xor_sync(0xffffffffu, mx1, 2));
        float s0 = 0.f, s1 = 0.f;
        #pragma unroll
        for (int nt = 0; nt < 10; nt++) {
            float e0 = __expf(c[mt][nt][0] - mx0);
            float e1 = __expf(c[mt][nt][1] - mx0);
            float e2 = __expf(c[mt][nt][2] - mx1);
            float e3 = __expf(c[mt][nt][3] - mx1);
            s0 += e0 + e1; s1 += e2 + e3;
            pu[mt][nt][0] = pack_bf16(e0, e1);
            pu[mt][nt][1] = pack_bf16(e2, e3);
        }
        s0 += __shfl_xor_sync(0xffffffffu, s0, 1);
        s0 += __shfl_xor_sync(0xffffffffu, s0, 2);
        s1 += __shfl_xor_sync(0xffffffffu, s1, 1);
        s1 += __shfl_xor_sync(0xffffffffu, s1, 2);
        iv[mt][0] = 1.f / s0;
        iv[mt][1] = 1.f / s1;
    }

    float o[2][8][4];
    #pragma unroll
    for (int mt = 0; mt < 2; mt++)
        #pragma unroll
        for (int nt = 0; nt < 8; nt++)
            #pragma unroll
            for (int r = 0; r < 4; r++) o[mt][nt][r] = 0.f;

    #pragma unroll
    for (int kk = 0; kk < 5; kk++) {
        uint32_t bv[8][2];
        #pragma unroll
        for (int nt = 0; nt < 8; nt++) {
            uint32_t addr = vbase + ((kk * 16 + (lane & 15)) * VS_STR + nt * 8) * 2;
            asm volatile(
                "ldmatrix.sync.aligned.m8n8.x2.trans.shared.b16 {%0,%1}, [%2];"
                : "=r"(bv[nt][0]), "=r"(bv[nt][1]) : "r"(addr));
        }
        #pragma unroll
        for (int mt = 0; mt < 2; mt++) {
            uint32_t a0 = pu[mt][2 * kk][0];
            uint32_t a1 = pu[mt][2 * kk][1];
            uint32_t a2 = pu[mt][2 * kk + 1][0];
            uint32_t a3 = pu[mt][2 * kk + 1][1];
            #pragma unroll
            for (int nt = 0; nt < 8; nt++) {
                asm volatile(
                    "mma.sync.aligned.m16n8k16.row.col.f32.bf16.bf16.f32 "
                    "{%0,%1,%2,%3}, {%4,%5,%6,%7}, {%8,%9}, {%0,%1,%2,%3};"
                    : "+f"(o[mt][nt][0]), "+f"(o[mt][nt][1]),
                      "+f"(o[mt][nt][2]), "+f"(o[mt][nt][3])
                    : "r"(a0), "r"(a1), "r"(a2), "r"(a3),
                      "r"(bv[nt][0]), "r"(bv[nt][1]));
            }
        }
    }

    __nv_bfloat16* Od = sQ;
    #pragma unroll
    for (int mt = 0; mt < 2; mt++) {
        int pxa = warp * 32 + mt * 16 + (lane >> 2);
        #pragma unroll
        for (int nt = 0; nt < 8; nt++) {
            int d = nt * 8 + (lane & 3) * 2;
            Od[d * OD_STR + pxa]           = __float2bfloat16(o[mt][nt][0] * iv[mt][0]);
            Od[(d + 1) * OD_STR + pxa]     = __float2bfloat16(o[mt][nt][1] * iv[mt][0]);
            Od[d * OD_STR + pxa + 8]       = __float2bfloat16(o[mt][nt][2] * iv[mt][1]);
            Od[(d + 1) * OD_STR + pxa + 8] = __float2bfloat16(o[mt][nt][3] * iv[mt][1]);
        }
    }
    __syncthreads();

    __nv_bfloat16* og = g_aob + ((size_t)b * Cdim + ch0) * HWp + p0;
    #pragma unroll 2
    for (int i = tid; i < 64 * 16; i += 128) {
        int d = i >> 4, cc = (i & 15) * 8;
        *(uint4*)(og + (size_t)d * HWp + cc) = *(const uint4*)(Od + d * OD_STR + cc);
    }
}

// ============================================================
extern "C" void kernel_launch(void* const* d_in, const int* in_sizes, int n_in,
                              void* d_out, int out_size) {
    const float* x       = (const float*)d_in[0];
    const float* context = (const float*)d_in[1];
    const float* gn_w    = (const float*)d_in[2];
    const float* gn_b    = (const float*)d_in[3];
    const float* ln_w    = (const float*)d_in[4];
    const float* ln_b    = (const float*)d_in[5];
    const float* q_w     = (const float*)d_in[6];
    const float* q_b     = (const float*)d_in[7];
    const float* k_w     = (const float*)d_in[8];
    const float* k_b     = (const float*)d_in[9];
    const float* v_w     = (const float*)d_in[10];
    const float* v_b     = (const float*)d_in[11];
    const float* out_w   = (const float*)d_in[12];
    const float* out_b   = (const float*)d_in[13];
    float* out = (float*)d_out;

    __nv_bfloat16 *qb = nullptr, *xnb = nullptr, *aob = nullptr, *qwb = nullptr, *owb = nullptr;
    cudaGetSymbolAddress((void**)&qb,  g_qb);
    cudaGetSymbolAddress((void**)&xnb, g_xnb);
    cudaGetSymbolAddress((void**)&aob, g_aob);
    cudaGetSymbolAddress((void**)&qwb, g_qwb);
    cudaGetSymbolAddress((void**)&owb, g_owb);

    gn_fuse_kernel<<<Bsz * NGROUPS, 512>>>(x, gn_w, gn_b);
    ln_kernel<<<Bsz * Sctx, 256>>>(context, ln_w, ln_b);
    conv_w_kernel<<<(2 * NQW + 2 * NKW) / 512, 512>>>(q_w, out_w, k_w, v_w);
    kv_mma<<<dim3(Cdim / 128, NROWS_PAD / 128, 2), 256>>>(k_b, v_b);
    mma_gemm<true><<<dim3(HWp / 128, Cdim / 128, Bsz), 128>>>(
        qwb, xnb, q_b, nullptr, qb);
    attn_mma_kernel<<<dim3(HWp / 128, NHEADS, Bsz), 128>>>();
    mma_gemm<false><<<dim3(HWp / 128, Cdim / 128, Bsz), 128>>>(
        owb, aob, out_b, x, out);
}

// round 9
// speedup vs baseline: 5.7318x; 1.1761x over previous
#include <cuda_runtime.h>
#include <cuda_bf16.h>
#include <cstdint>

#define Bsz 16
#define Cdim 512
#define HWp 4096
#define Sctx 77
#define CTXd 768
#define NHEADS 8
#define HD 64
#define NGROUPS 32
#define CPG 16
#define EPSV 1e-5f
#define NROWS (Bsz * Sctx)      // 1232
#define NROWS_PAD 1280

// ---- scratch (static device globals; no runtime allocation) ----
__device__ __nv_bfloat16 g_qb [(size_t)Bsz * Cdim * HWp]; // Q  (B, C, HW) bf16
__device__ __nv_bfloat16 g_xnb[(size_t)Bsz * Cdim * HWp]; // GN(x) bf16
__device__ __nv_bfloat16 g_aob[(size_t)Bsz * Cdim * HWp]; // attn out bf16
__device__ __nv_bfloat16 g_cnb[(size_t)NROWS_PAD * CTXd]; // layernormed ctx bf16 (padded)
__device__ __nv_bfloat16 g_kb [(size_t)NROWS * Cdim];     // K bf16 (n, C)
__device__ __nv_bfloat16 g_vb [(size_t)NROWS * Cdim];     // V bf16 (n, C)
__device__ __nv_bfloat16 g_qwb[Cdim * Cdim];              // q_w bf16
__device__ __nv_bfloat16 g_owb[Cdim * Cdim];              // out_w bf16
__device__ __nv_bfloat16 g_kwb[Cdim * CTXd];              // k_w bf16
__device__ __nv_bfloat16 g_vwb[Cdim * CTXd];              // v_w bf16

__device__ __forceinline__ uint32_t smem_u32(const void* p) {
    uint32_t a;
    asm("{ .reg .u64 t; cvta.to.shared.u64 t, %1; cvt.u32.u64 %0, t; }"
        : "=r"(a) : "l"(p));
    return a;
}
__device__ __forceinline__ uint32_t pack_bf16(float lo, float hi) {
    __nv_bfloat162 p = __floats2bfloat162_rn(lo, hi);
    return *reinterpret_cast<uint32_t*>(&p);
}
__device__ __forceinline__ void cp_async16(uint32_t dst, const void* src) {
    asm volatile("cp.async.cg.shared.global [%0], [%1], 16;"
                 :: "r"(dst), "l"(src));
}
__device__ __forceinline__ void cp_commit() {
    asm volatile("cp.async.commit_group;" ::: "memory");
}
template <int N>
__device__ __forceinline__ void cp_wait() {
    asm volatile("cp.async.wait_group %0;" :: "n"(N) : "memory");
}

// ============================================================
// Fused GroupNorm: one block per (b,g); reduce, then apply + bf16
// ============================================================
__global__ void __launch_bounds__(512)
gn_fuse_kernel(const float* __restrict__ x,
               const float* __restrict__ gnw,
               const float* __restrict__ gnb) {
    int blk = blockIdx.x;
    int b = blk / NGROUPS, g = blk % NGROUPS;
    const size_t base = ((size_t)b * Cdim + (size_t)g * CPG) * HWp;
    const float4* p = (const float4*)(x + base);
    const int n4 = CPG * HWp / 4;  // 16384
    float s = 0.f, sq = 0.f;
    for (int i = threadIdx.x; i < n4; i += blockDim.x) {
        float4 v = p[i];
        s  += v.x + v.y + v.z + v.w;
        sq += v.x * v.x + v.y * v.y + v.z * v.z + v.w * v.w;
    }
    __shared__ float ss[32], ssq[32];
    __shared__ float sa[CPG], sb[CPG];
    #pragma unroll
    for (int o = 16; o > 0; o >>= 1) {
        s  += __shfl_down_sync(0xffffffffu, s, o);
        sq += __shfl_down_sync(0xffffffffu, sq, o);
    }
    int wid = threadIdx.x >> 5, lid = threadIdx.x & 31;
    if (lid == 0) { ss[wid] = s; ssq[wid] = sq; }
    __syncthreads();
    if (wid == 0) {
        int nw = blockDim.x >> 5;
        s  = (lid < nw) ? ss[lid]  : 0.f;
        sq = (lid < nw) ? ssq[lid] : 0.f;
        #pragma unroll
        for (int o = 16; o > 0; o >>= 1) {
            s  += __shfl_down_sync(0xffffffffu, s, o);
            sq += __shfl_down_sync(0xffffffffu, sq, o);
        }
        if (lid == 0) { ss[0] = s; ssq[0] = sq; }
    }
    __syncthreads();
    {
        const float invn = 1.f / (float)(CPG * HWp);
        float mean = ss[0] * invn;
        float var  = ssq[0] * invn - mean * mean;
        float rstd = rsqrtf(var + EPSV);
        if (threadIdx.x < CPG) {
            int c = g * CPG + threadIdx.x;
            float a = rstd * gnw[c];
            sa[threadIdx.x] = a;
            sb[threadIdx.x] = gnb[c] - mean * a;
        }
    }
    __syncthreads();
    __nv_bfloat162* dst = (__nv_bfloat162*)(g_xnb + base);
    const int per_c4 = HWp / 4;
    for (int i = threadIdx.x; i < n4; i += blockDim.x) {
        int c = i / per_c4;
        float a = sa[c], bb = sb[c];
        float4 v = p[i];
        dst[2 * i]     = __floats2bfloat162_rn(v.x * a + bb, v.y * a + bb);
        dst[2 * i + 1] = __floats2bfloat162_rn(v.z * a + bb, v.w * a + bb);
    }
}

// ============================================================
// LayerNorm on context -> bf16
// ============================================================
__global__ void ln_kernel(const float* __restrict__ ctx,
                          const float* __restrict__ w,
                          const float* __restrict__ bb) {
    int row = blockIdx.x;
    const float* xr = ctx + (size_t)row * CTXd;
    float s = 0.f, sq = 0.f;
    for (int i = threadIdx.x; i < CTXd; i += blockDim.x) {
        float v = xr[i];
        s += v; sq += v * v;
    }
    __shared__ float ss[32], ssq[32];
    __shared__ float smean, srstd;
    #pragma unroll
    for (int o = 16; o > 0; o >>= 1) {
        s  += __shfl_down_sync(0xffffffffu, s, o);
        sq += __shfl_down_sync(0xffffffffu, sq, o);
    }
    int wid = threadIdx.x >> 5, lid = threadIdx.x & 31;
    if (lid == 0) { ss[wid] = s; ssq[wid] = sq; }
    __syncthreads();
    if (wid == 0) {
        int nw = blockDim.x >> 5;
        s  = (lid < nw) ? ss[lid]  : 0.f;
        sq = (lid < nw) ? ssq[lid] : 0.f;
        #pragma unroll
        for (int o = 16; o > 0; o >>= 1) {
            s  += __shfl_down_sync(0xffffffffu, s, o);
            sq += __shfl_down_sync(0xffffffffu, sq, o);
        }
        if (lid == 0) {
            const float invn = 1.f / (float)CTXd;
            float mean = s * invn;
            float var  = sq * invn - mean * mean;
            smean = mean;
            srstd = rsqrtf(var + EPSV);
        }
    }
    __syncthreads();
    float mean = smean, rstd = srstd;
    for (int i = threadIdx.x; i < CTXd; i += blockDim.x) {
        g_cnb[(size_t)row * CTXd + i] =
            __float2bfloat16((xr[i] - mean) * rstd * w[i] + bb[i]);
    }
}

// ============================================================
// Weight bf16 conversion (q_w, out_w, k_w, v_w)
// ============================================================
#define NQW (Cdim * Cdim)
#define NKW (Cdim * CTXd)
__global__ void conv_w_kernel(const float* __restrict__ qw, const float* __restrict__ ow,
                              const float* __restrict__ kw, const float* __restrict__ vw) {
    int i = blockIdx.x * blockDim.x + threadIdx.x;
    if (i < NQW)                 g_qwb[i] = __float2bfloat16(qw[i]);
    else if (i < 2 * NQW)        g_owb[i - NQW] = __float2bfloat16(ow[i - NQW]);
    else if (i < 2 * NQW + NKW)  g_kwb[i - 2 * NQW] = __float2bfloat16(kw[i - 2 * NQW]);
    else                         g_vwb[i - 2 * NQW - NKW] = __float2bfloat16(vw[i - 2 * NQW - NKW]);
}

// ============================================================
// K/V projection via bf16 mma.sync (NT) — unchanged (20.6us proven)
// ============================================================
#define KVA_STR 40
#define KV_STAGE_BYTES (128 * KVA_STR * 2)
#define KV_STAGES 3
#define KV_NIT (CTXd / 32)

__global__ void __launch_bounds__(256, 2)
kv_mma(const float* __restrict__ kb_, const float* __restrict__ vb_) {
    __shared__ __align__(16) char smem_[KV_STAGES * 2 * KV_STAGE_BYTES];

    const __nv_bfloat16* W    = blockIdx.z ? g_vwb : g_kwb;
    const float*         bias = blockIdx.z ? vb_ : kb_;
    __nv_bfloat16*       out  = blockIdx.z ? g_vb : g_kb;

    const int tid  = threadIdx.x;
    const int warp = tid >> 5, lane = tid & 31;
    const int wm = warp >> 2, wn = warp & 3;
    const int n0 = blockIdx.y * 128;
    const int o0 = blockIdx.x * 128;

    const uint32_t sbase = smem_u32(smem_);
    const uint32_t sB0 = sbase + KV_STAGES * KV_STAGE_BYTES;

    const int ld_row = tid >> 2;
    const int ld_col = (tid & 3) * 8;

    const uint32_t st_off  = (ld_row * KVA_STR + ld_col) * 2;
    const uint32_t st_off2 = ((ld_row + 64) * KVA_STR + ld_col) * 2;

    const uint32_t a_lm_base =
        ((wm * 64 + (lane & 15)) * KVA_STR + (lane >> 4) * 8) * 2;
    const uint32_t b_lm_part =
        ((lane & 7) * KVA_STR + ((lane >> 3) & 1) * 8) * 2;

    float acc[4][4][4] = {};

    #pragma unroll
    for (int s = 0; s < KV_STAGES - 1; s++) {
        const int k0 = s * 32;
        uint32_t aS = sbase + s * KV_STAGE_BYTES;
        uint32_t bS = sB0 + s * KV_STAGE_BYTES;
        cp_async16(aS + st_off,  g_cnb + (size_t)(n0 + ld_row) * CTXd + k0 + ld_col);
        cp_async16(aS + st_off2, g_cnb + (size_t)(n0 + ld_row + 64) * CTXd + k0 + ld_col);
        cp_async16(bS + st_off,  W + (size_t)(o0 + ld_row) * CTXd + k0 + ld_col);
        cp_async16(bS + st_off2, W + (size_t)(o0 + ld_row + 64) * CTXd + k0 + ld_col);
        cp_commit();
    }

    #pragma unroll 1
    for (int it = 0; it < KV_NIT; it++) {
        cp_wait<KV_STAGES - 2>();
        __syncthreads();
        {
            const int sl = it + KV_STAGES - 1;
            if (sl < KV_NIT) {
                const int k0 = sl * 32;
                const int sb = sl % KV_STAGES;
                uint32_t aS = sbase + sb * KV_STAGE_BYTES;
                uint32_t bS = sB0 + sb * KV_STAGE_BYTES;
                cp_async16(aS + st_off,  g_cnb + (size_t)(n0 + ld_row) * CTXd + k0 + ld_col);
                cp_async16(aS + st_off2, g_cnb + (size_t)(n0 + ld_row + 64) * CTXd + k0 + ld_col);
                cp_async16(bS + st_off,  W + (size_t)(o0 + ld_row) * CTXd + k0 + ld_col);
                cp_async16(bS + st_off2, W + (size_t)(o0 + ld_row + 64) * CTXd + k0 + ld_col);
            }
            cp_commit();
        }

        const int sc = it % KV_STAGES;
        const uint32_t aBuf = sbase + sc * KV_STAGE_BYTES;
        const uint32_t bBuf = sB0 + sc * KV_STAGE_BYTES;

        #pragma unroll
        for (int kk = 0; kk < 2; kk++) {
            uint32_t af[4][4];
            #pragma unroll
            for (int mt = 0; mt < 4; mt++) {
                uint32_t addr = aBuf + a_lm_base + (mt * 16 * KVA_STR + kk * 16) * 2;
                asm volatile(
                    "ldmatrix.sync.aligned.m8n8.x4.shared.b16 {%0,%1,%2,%3}, [%4];"
                    : "=r"(af[mt][0]), "=r"(af[mt][1]), "=r"(af[mt][2]), "=r"(af[mt][3])
                    : "r"(addr));
            }
            uint32_t bf[4][2];
            #pragma unroll
            for (int nt = 0; nt < 4; nt++) {
                uint32_t addr = bBuf + b_lm_part +
                    (((wn * 32 + nt * 8) * KVA_STR) + kk * 16) * 2;
                asm volatile(
                    "ldmatrix.sync.aligned.m8n8.x2.shared.b16 {%0,%1}, [%2];"
                    : "=r"(bf[nt][0]), "=r"(bf[nt][1]) : "r"(addr));
            }
            #pragma unroll
            for (int mt = 0; mt < 4; mt++)
                #pragma unroll
                for (int nt = 0; nt < 4; nt++) {
                    asm volatile(
                        "mma.sync.aligned.m16n8k16.row.col.f32.bf16.bf16.f32 "
                        "{%0,%1,%2,%3}, {%4,%5,%6,%7}, {%8,%9}, {%0,%1,%2,%3};"
                        : "+f"(acc[mt][nt][0]), "+f"(acc[mt][nt][1]),
                          "+f"(acc[mt][nt][2]), "+f"(acc[mt][nt][3])
                        : "r"(af[mt][0]), "r"(af[mt][1]), "r"(af[mt][2]), "r"(af[mt][3]),
                          "r"(bf[nt][0]), "r"(bf[nt][1]));
                }
        }
    }

    const int row_base = n0 + wm * 64 + (lane >> 2);
    const int col_base = o0 + wn * 32 + (lane & 3) * 2;
    #pragma unroll
    for (int mt = 0; mt < 4; mt++) {
        #pragma unroll
        for (int half = 0; half < 2; half++) {
            int row = row_base + mt * 16 + half * 8;
            if (row >= NROWS) continue;
            #pragma unroll
            for (int nt = 0; nt < 4; nt++) {
                int col = col_base + nt * 8;
                float bi0 = bias[col], bi1 = bias[col + 1];
                *(__nv_bfloat162*)(out + (size_t)row * Cdim + col) =
                    __floats2bfloat162_rn(acc[mt][nt][half * 2] + bi0,
                                          acc[mt][nt][half * 2 + 1] + bi1);
            }
        }
    }
}

// ============================================================
// bf16 mma.sync GEMM — R8 version (128 thr, warp tile 64x64)
// ============================================================
#define A_STRIDE 40
#define B_STRIDE 136
#define STAGES 3
#define A_STAGE_BYTES (128 * A_STRIDE * 2)
#define B_STAGE_BYTES (32 * B_STRIDE * 2)
#define NIT (Cdim / 32)

template <bool BF16OUT>
__global__ void __launch_bounds__(128, 2)
mma_gemm(const __nv_bfloat16* __restrict__ Wb,
         const __nv_bfloat16* __restrict__ Xb,
         const float* __restrict__ bias,
         const float* __restrict__ residual,
         void* __restrict__ outv) {
    __shared__ __align__(16) char smem_[STAGES * (A_STAGE_BYTES + B_STAGE_BYTES)];

    const int tid  = threadIdx.x;
    const int warp = tid >> 5, lane = tid & 31;
    const int wm = warp >> 1, wn = warp & 1;
    const int p0 = blockIdx.x * 128;
    const int o0 = blockIdx.y * 128;
    const int b  = blockIdx.z;
    const __nv_bfloat16* Xbb = Xb + (size_t)b * Cdim * HWp;

    const uint32_t sbase = smem_u32(smem_);
    const uint32_t sB0 = sbase + STAGES * A_STAGE_BYTES;

    const int a_ld_row = tid >> 2;
    const int a_ld_col = (tid & 3) * 8;
    const int b_ld_row = tid >> 4;
    const int b_ld_col = (tid & 15) * 8;

    const uint32_t a_lm_base =
        ((wm * 64 + (lane & 15)) * A_STRIDE + (lane >> 4) * 8) * 2;
    const uint32_t b_lm_base = ((lane & 15) * B_STRIDE + wn * 64) * 2;

    uint32_t a_st[4], b_st[4];
    #pragma unroll
    for (int j = 0; j < 4; j++) {
        a_st[j] = ((a_ld_row + j * 32) * A_STRIDE + a_ld_col) * 2;
        b_st[j] = ((b_ld_row + j * 8) * B_STRIDE + b_ld_col) * 2;
    }

    float acc[4][8][4] = {};

    #pragma unroll
    for (int s = 0; s < STAGES - 1; s++) {
        const int k0 = s * 32;
        uint32_t aS = sbase + s * A_STAGE_BYTES;
        uint32_t bS = sB0 + s * B_STAGE_BYTES;
        #pragma unroll
        for (int j = 0; j < 4; j++) {
            cp_async16(aS + a_st[j],
                       Wb + (size_t)(o0 + a_ld_row + j * 32) * Cdim + k0 + a_ld_col);
            cp_async16(bS + b_st[j],
                       Xbb + (size_t)(k0 + b_ld_row + j * 8) * HWp + p0 + b_ld_col);
        }
        cp_commit();
    }

    #pragma unroll 1
    for (int it = 0; it < NIT; it++) {
        cp_wait<STAGES - 2>();
        __syncthreads();
        {
            const int sl = it + STAGES - 1;
            if (sl < NIT) {
                const int k0 = sl * 32;
                const int sb = sl % STAGES;
                uint32_t aS = sbase + sb * A_STAGE_BYTES;
                uint32_t bS = sB0 + sb * B_STAGE_BYTES;
                #pragma unroll
                for (int j = 0; j < 4; j++) {
                    cp_async16(aS + a_st[j],
                               Wb + (size_t)(o0 + a_ld_row + j * 32) * Cdim + k0 + a_ld_col);
                    cp_async16(bS + b_st[j],
                               Xbb + (size_t)(k0 + b_ld_row + j * 8) * HWp + p0 + b_ld_col);
                }
            }
            cp_commit();
        }

        const int sc = it % STAGES;
        const uint32_t aBuf = sbase + sc * A_STAGE_BYTES;
        const uint32_t bBuf = sB0 + sc * B_STAGE_BYTES;

        #pragma unroll
        for (int kk = 0; kk < 2; kk++) {
            uint32_t af[4][4];
            #pragma unroll
            for (int mt = 0; mt < 4; mt++) {
                uint32_t addr = aBuf + a_lm_base + (mt * 16 * A_STRIDE + kk * 16) * 2;
                asm volatile(
                    "ldmatrix.sync.aligned.m8n8.x4.shared.b16 {%0,%1,%2,%3}, [%4];"
                    : "=r"(af[mt][0]), "=r"(af[mt][1]), "=r"(af[mt][2]), "=r"(af[mt][3])
                    : "r"(addr));
            }
            uint32_t bf[8][2];
            #pragma unroll
            for (int nt = 0; nt < 8; nt++) {
                uint32_t addr = bBuf + b_lm_base + (kk * 16 * B_STRIDE + nt * 8) * 2;
                asm volatile(
                    "ldmatrix.sync.aligned.m8n8.x2.trans.shared.b16 {%0,%1}, [%2];"
                    : "=r"(bf[nt][0]), "=r"(bf[nt][1]) : "r"(addr));
            }
            #pragma unroll
            for (int mt = 0; mt < 4; mt++)
                #pragma unroll
                for (int nt = 0; nt < 8; nt++) {
                    asm volatile(
                        "mma.sync.aligned.m16n8k16.row.col.f32.bf16.bf16.f32 "
                        "{%0,%1,%2,%3}, {%4,%5,%6,%7}, {%8,%9}, {%0,%1,%2,%3};"
                        : "+f"(acc[mt][nt][0]), "+f"(acc[mt][nt][1]),
                          "+f"(acc[mt][nt][2]), "+f"(acc[mt][nt][3])
                        : "r"(af[mt][0]), "r"(af[mt][1]), "r"(af[mt][2]), "r"(af[mt][3]),
                          "r"(bf[nt][0]), "r"(bf[nt][1]));
                }
        }
    }

    const int row_base = o0 + wm * 64 + (lane >> 2);
    const int col_base = p0 + wn * 64 + (lane & 3) * 2;
    #pragma unroll
    for (int mt = 0; mt < 4; mt++) {
        #pragma unroll
        for (int half = 0; half < 2; half++) {
            int row = row_base + mt * 16 + half * 8;
            float bi = bias[row];
            size_t rb = ((size_t)b * Cdim + row) * HWp;
            #pragma unroll
            for (int nt = 0; nt < 8; nt++) {
                int col = col_base + nt * 8;
                float rx = acc[mt][nt][half * 2]     + bi;
                float ry = acc[mt][nt][half * 2 + 1] + bi;
                if (BF16OUT) {
                    __nv_bfloat16* outb = (__nv_bfloat16*)outv;
                    *(__nv_bfloat162*)(outb + rb + col) = __floats2bfloat162_rn(rx, ry);
                } else {
                    float* outf = (float*)outv;
                    if (residual) {
                        float2 rv = *(const float2*)(residual + rb + col);
                        rx += rv.x; ry += rv.y;
                    }
                    float2 r; r.x = rx; r.y = ry;
                    *(float2*)(outf + rb + col) = r;
                }
            }
        }
    }
}

// ============================================================
// Tensor-core flash attention, vectorized staging:
//   sQ: [d=64][px 136-stride]  -> A-frags via ldmatrix.x4.TRANS
//   sK: [s=80][d 72-stride]    -> B-frags via ldmatrix.x2 (non-trans)
//   sV: [s=80][d 72-stride]    -> B-frags via ldmatrix.x2.trans (as before)
// ============================================================
#define QS_STR 136   // hw per d-row of sQ (128 px + 8 pad); also O stride
#define KS_STR 72    // hw per s-row of sK/sV (64 d + 8 pad)
#define SPAD 80

__global__ void __launch_bounds__(128)
attn_mma_kernel() {
    __shared__ __align__(16) __nv_bfloat16 sQ[64 * QS_STR];   // [d][px]; reused as O
    __shared__ __align__(16) __nv_bfloat16 sK[SPAD * KS_STR]; // [s][d]
    __shared__ __align__(16) __nv_bfloat16 sV[SPAD * KS_STR]; // [s][d]

    const int tid = threadIdx.x;
    const int warp = tid >> 5, lane = tid & 31;
    const int b = blockIdx.z, h = blockIdx.y;
    const int p0 = blockIdx.x * 128;
    const int ch0 = h * HD;

    // ---- stage Q [d][px] vectorized (64 rows x 16 uint4) ----
    const __nv_bfloat16* qg = g_qb + ((size_t)b * Cdim + ch0) * HWp + p0;
    #pragma unroll 4
    for (int i = tid; i < 64 * 16; i += 128) {
        int d = i >> 4, cc = (i & 15) * 8;
        *(uint4*)(sQ + d * QS_STR + cc) = *(const uint4*)(qg + (size_t)d * HWp + cc);
    }
    // ---- stage K [s][d] vectorized; zero rows 77..79 ----
    const __nv_bfloat16* kg = g_kb + (size_t)b * Sctx * Cdim + ch0;
    for (int i = tid; i < 77 * 8; i += 128) {
        int s = i >> 3, dd = (i & 7) * 8;
        *(uint4*)(sK + s * KS_STR + dd) = *(const uint4*)(kg + (size_t)s * Cdim + dd);
    }
    if (tid < 24) {
        int s = 77 + tid / 8, dd = (tid & 7) * 8;
        uint4 z = {0, 0, 0, 0};
        *(uint4*)(sK + s * KS_STR + dd) = z;
    }
    // ---- stage V [s][d] vectorized; zero rows 77..79 ----
    const __nv_bfloat16* vg = g_vb + (size_t)b * Sctx * Cdim + ch0;
    for (int i = tid; i < 77 * 8; i += 128) {
        int s = i >> 3, dd = (i & 7) * 8;
        *(uint4*)(sV + s * KS_STR + dd) = *(const uint4*)(vg + (size_t)s * Cdim + dd);
    }
    if (tid >= 104) {  // 24 threads zero V pad rows
        int t = tid - 104;
        int s = 77 + t / 8, dd = (t & 7) * 8;
        uint4 z = {0, 0, 0, 0};
        *(uint4*)(sV + s * KS_STR + dd) = z;
    }
    __syncthreads();

    const uint32_t qbase = smem_u32(sQ);
    const uint32_t kbase = smem_u32(sK);
    const uint32_t vbase = smem_u32(sV);

    // ---- S = Q @ K^T : M=128 px (warp:32), N=80 s, K=64 d ----
    float c[2][10][4];
    #pragma unroll
    for (int mt = 0; mt < 2; mt++)
        #pragma unroll
        for (int nt = 0; nt < 10; nt++)
            #pragma unroll
            for (int r = 0; r < 4; r++) c[mt][nt][r] = 0.f;

    // A-frag trans lane map: k_row in [d], m_col in [px]
    const int a_krow = ((lane >> 4) & 1) * 8 + (lane & 7);
    const int a_mcol = ((lane >> 3) & 1) * 8;
    // K B-frag non-trans lane map (kv_mma recipe)
    const uint32_t b_lm_part = ((lane & 7) * KS_STR + ((lane >> 3) & 1) * 8) * 2;

    #pragma unroll
    for (int kk = 0; kk < 4; kk++) {
        uint32_t af[2][4];
        #pragma unroll
        for (int mt = 0; mt < 2; mt++) {
            uint32_t addr = qbase +
                ((kk * 16 + a_krow) * QS_STR + warp * 32 + mt * 16 + a_mcol) * 2;
            asm volatile(
                "ldmatrix.sync.aligned.m8n8.x4.trans.shared.b16 {%0,%1,%2,%3}, [%4];"
                : "=r"(af[mt][0]), "=r"(af[mt][1]), "=r"(af[mt][2]), "=r"(af[mt][3])
                : "r"(addr));
        }
        uint32_t bf[10][2];
        #pragma unroll
        for (int nt = 0; nt < 10; nt++) {
            uint32_t addr = kbase + b_lm_part + ((nt * 8) * KS_STR + kk * 16) * 2;
            asm volatile(
                "ldmatrix.sync.aligned.m8n8.x2.shared.b16 {%0,%1}, [%2];"
                : "=r"(bf[nt][0]), "=r"(bf[nt][1]) : "r"(addr));
        }
        #pragma unroll
        for (int mt = 0; mt < 2; mt++)
            #pragma unroll
            for (int nt = 0; nt < 10; nt++) {
                asm volatile(
                    "mma.sync.aligned.m16n8k16.row.col.f32.bf16.bf16.f32 "
                    "{%0,%1,%2,%3}, {%4,%5,%6,%7}, {%8,%9}, {%0,%1,%2,%3};"
                    : "+f"(c[mt][nt][0]), "+f"(c[mt][nt][1]),
                      "+f"(c[mt][nt][2]), "+f"(c[mt][nt][3])
                    : "r"(af[mt][0]), "r"(af[mt][1]), "r"(af[mt][2]), "r"(af[mt][3]),
                      "r"(bf[nt][0]), "r"(bf[nt][1]));
            }
    }
    __syncthreads();  // done reading sQ (reused as O)

    // ---- softmax + pack P ----
    const float scale = 0.125f;
    uint32_t pu[2][10][2];
    float iv[2][2];
    #pragma unroll
    for (int mt = 0; mt < 2; mt++) {
        float mx0 = -1e30f, mx1 = -1e30f;
        #pragma unroll
        for (int nt = 0; nt < 10; nt++) {
            int col = nt * 8 + (lane & 3) * 2;
            c[mt][nt][0] = (col     < Sctx) ? c[mt][nt][0] * scale : -1e30f;
            c[mt][nt][1] = (col + 1 < Sctx) ? c[mt][nt][1] * scale : -1e30f;
            c[mt][nt][2] = (col     < Sctx) ? c[mt][nt][2] * scale : -1e30f;
            c[mt][nt][3] = (col + 1 < Sctx) ? c[mt][nt][3] * scale : -1e30f;
            mx0 = fmaxf(mx0, fmaxf(c[mt][nt][0], c[mt][nt][1]));
            mx1 = fmaxf(mx1, fmaxf(c[mt][nt][2], c[mt][nt][3]));
        }
        mx0 = fmaxf(mx0, __shfl_xor_sync(0xffffffffu, mx0, 1));
        mx0 = fmaxf(mx0, __shfl_xor_sync(0xffffffffu, mx0, 2));
        mx1 = fmaxf(mx1, __shfl_xor_sync(0xffffffffu, mx1, 1));
        mx1 = fmaxf(mx1, __shfl_xor_sync(0xffffffffu, mx1, 2));
        float s0 = 0.f, s1 = 0.f;
        #pragma unroll
        for (int nt = 0; nt < 10; nt++) {
            float e0 = __expf(c[mt][nt][0] - mx0);
            float e1 = __expf(c[mt][nt][1] - mx0);
            float e2 = __expf(c[mt][nt][2] - mx1);
            float e3 = __expf(c[mt][nt][3] - mx1);
            s0 += e0 + e1; s1 += e2 + e3;
            pu[mt][nt][0] = pack_bf16(e0, e1);
            pu[mt][nt][1] = pack_bf16(e2, e3);
        }
        s0 += __shfl_xor_sync(0xffffffffu, s0, 1);
        s0 += __shfl_xor_sync(0xffffffffu, s0, 2);
        s1 += __shfl_xor_sync(0xffffffffu, s1, 1);
        s1 += __shfl_xor_sync(0xffffffffu, s1, 2);
        iv[mt][0] = 1.f / s0;
        iv[mt][1] = 1.f / s1;
    }

    // ---- O = P @ V ----
    float o[2][8][4];
    #pragma unroll
    for (int mt = 0; mt < 2; mt++)
        #pragma unroll
        for (int nt = 0; nt < 8; nt++)
            #pragma unroll
            for (int r = 0; r < 4; r++) o[mt][nt][r] = 0.f;

    #pragma unroll
    for (int kk = 0; kk < 5; kk++) {
        uint32_t bv[8][2];
        #pragma unroll
        for (int nt = 0; nt < 8; nt++) {
            uint32_t addr = vbase + ((kk * 16 + (lane & 15)) * KS_STR + nt * 8) * 2;
            asm volatile(
                "ldmatrix.sync.aligned.m8n8.x2.trans.shared.b16 {%0,%1}, [%2];"
                : "=r"(bv[nt][0]), "=r"(bv[nt][1]) : "r"(addr));
        }
        #pragma unroll
        for (int mt = 0; mt < 2; mt++) {
            uint32_t a0 = pu[mt][2 * kk][0];
            uint32_t a1 = pu[mt][2 * kk][1];
            uint32_t a2 = pu[mt][2 * kk + 1][0];
            uint32_t a3 = pu[mt][2 * kk + 1][1];
            #pragma unroll
            for (int nt = 0; nt < 8; nt++) {
                asm volatile(
                    "mma.sync.aligned.m16n8k16.row.col.f32.bf16.bf16.f32 "
                    "{%0,%1,%2,%3}, {%4,%5,%6,%7}, {%8,%9}, {%0,%1,%2,%3};"
                    : "+f"(o[mt][nt][0]), "+f"(o[mt][nt][1]),
                      "+f"(o[mt][nt][2]), "+f"(o[mt][nt][3])
                    : "r"(a0), "r"(a1), "r"(a2), "r"(a3),
                      "r"(bv[nt][0]), "r"(bv[nt][1]));
            }
        }
    }

    // ---- normalize + transpose through smem (sQ reused as O [d][px]) ----
    __nv_bfloat16* Od = sQ;
    #pragma unroll
    for (int mt = 0; mt < 2; mt++) {
        int pxa = warp * 32 + mt * 16 + (lane >> 2);
        #pragma unroll
        for (int nt = 0; nt < 8; nt++) {
            int d = nt * 8 + (lane & 3) * 2;
            Od[d * QS_STR + pxa]           = __float2bfloat16(o[mt][nt][0] * iv[mt][0]);
            Od[(d + 1) * QS_STR + pxa]     = __float2bfloat16(o[mt][nt][1] * iv[mt][0]);
            Od[d * QS_STR + pxa + 8]       = __float2bfloat16(o[mt][nt][2] * iv[mt][1]);
            Od[(d + 1) * QS_STR + pxa + 8] = __float2bfloat16(o[mt][nt][3] * iv[mt][1]);
        }
    }
    __syncthreads();

    __nv_bfloat16* og = g_aob + ((size_t)b * Cdim + ch0) * HWp + p0;
    #pragma unroll 2
    for (int i = tid; i < 64 * 16; i += 128) {
        int d = i >> 4, cc = (i & 15) * 8;
        *(uint4*)(og + (size_t)d * HWp + cc) = *(const uint4*)(Od + d * QS_STR + cc);
    }
}

// ============================================================
extern "C" void kernel_launch(void* const* d_in, const int* in_sizes, int n_in,
                              void* d_out, int out_size) {
    const float* x       = (const float*)d_in[0];
    const float* context = (const float*)d_in[1];
    const float* gn_w    = (const float*)d_in[2];
    const float* gn_b    = (const float*)d_in[3];
    const float* ln_w    = (const float*)d_in[4];
    const float* ln_b    = (const float*)d_in[5];
    const float* q_w     = (const float*)d_in[6];
    const float* q_b     = (const float*)d_in[7];
    const float* k_w     = (const float*)d_in[8];
    const float* k_b     = (const float*)d_in[9];
    const float* v_w     = (const float*)d_in[10];
    const float* v_b     = (const float*)d_in[11];
    const float* out_w   = (const float*)d_in[12];
    const float* out_b   = (const float*)d_in[13];
    float* out = (float*)d_out;

    __nv_bfloat16 *qb = nullptr, *xnb = nullptr, *aob = nullptr, *qwb = nullptr, *owb = nullptr;
    cudaGetSymbolAddress((void**)&qb,  g_qb);
    cudaGetSymbolAddress((void**)&xnb, g_xnb);
    cudaGetSymbolAddress((void**)&aob, g_aob);
    cudaGetSymbolAddress((void**)&qwb, g_qwb);
    cudaGetSymbolAddress((void**)&owb, g_owb);

    // one-time side stream + events (created on the uncaptured correctness
    // call; reused as graph edges during capture)
    static cudaStream_t s_side = nullptr;
    static cudaEvent_t ev_fork = nullptr, ev_join = nullptr;
    if (s_side == nullptr) {
        cudaStreamCreateWithFlags(&s_side, cudaStreamNonBlocking);
        cudaEventCreateWithFlags(&ev_fork, cudaEventDisableTiming);
        cudaEventCreateWithFlags(&ev_join, cudaEventDisableTiming);
    }

    // main: weights first (needed by both chains)
    conv_w_kernel<<<(2 * NQW + 2 * NKW) / 512, 512>>>(q_w, out_w, k_w, v_w);
    cudaEventRecord(ev_fork, 0);
    // side chain: ln -> kv
    cudaStreamWaitEvent(s_side, ev_fork, 0);
    ln_kernel<<<Bsz * Sctx, 256, 0, s_side>>>(context, ln_w, ln_b);
    kv_mma<<<dim3(Cdim / 128, NROWS_PAD / 128, 2), 256, 0, s_side>>>(k_b, v_b);
    cudaEventRecord(ev_join, s_side);
    // main chain: gn -> qproj
    gn_fuse_kernel<<<Bsz * NGROUPS, 512>>>(x, gn_w, gn_b);
    mma_gemm<true><<<dim3(HWp / 128, Cdim / 128, Bsz), 128>>>(
        qwb, xnb, q_b, nullptr, qb);
    // join, then attention + out-projection
    cudaStreamWaitEvent(0, ev_join, 0);
    attn_mma_kernel<<<dim3(HWp / 128, NHEADS, Bsz), 128>>>();
    mma_gemm<false><<<dim3(HWp / 128, Cdim / 128, Bsz), 128>>>(
        owb, aob, out_b, x, out);
}

// round 10
// speedup vs baseline: 5.8294x; 1.0170x over previous
#include <cuda_runtime.h>
#include <cuda_bf16.h>
#include <cstdint>

#define Bsz 16
#define Cdim 512
#define HWp 4096
#define Sctx 77
#define CTXd 768
#define NHEADS 8
#define HD 64
#define NGROUPS 32
#define CPG 16
#define EPSV 1e-5f
#define NROWS (Bsz * Sctx)      // 1232
#define NROWS_PAD 1280

// ---- scratch (static device globals; no runtime allocation) ----
__device__ __nv_bfloat16 g_qb [(size_t)Bsz * Cdim * HWp]; // Q  (B, C, HW) bf16
__device__ __nv_bfloat16 g_xnb[(size_t)Bsz * Cdim * HWp]; // GN(x) bf16
__device__ __nv_bfloat16 g_aob[(size_t)Bsz * Cdim * HWp]; // attn out bf16
__device__ __nv_bfloat16 g_cnb[(size_t)NROWS_PAD * CTXd]; // layernormed ctx bf16 (padded)
__device__ __nv_bfloat16 g_kb [(size_t)NROWS * Cdim];     // K bf16 (n, C)
__device__ __nv_bfloat16 g_vb [(size_t)NROWS * Cdim];     // V bf16 (n, C)
__device__ __nv_bfloat16 g_qwb[Cdim * Cdim];              // q_w bf16
__device__ __nv_bfloat16 g_owb[Cdim * Cdim];              // out_w bf16
__device__ __nv_bfloat16 g_kwb[Cdim * CTXd];              // k_w bf16
__device__ __nv_bfloat16 g_vwb[Cdim * CTXd];              // v_w bf16

__device__ __forceinline__ uint32_t smem_u32(const void* p) {
    uint32_t a;
    asm("{ .reg .u64 t; cvta.to.shared.u64 t, %1; cvt.u32.u64 %0, t; }"
        : "=r"(a) : "l"(p));
    return a;
}
__device__ __forceinline__ uint32_t pack_bf16(float lo, float hi) {
    __nv_bfloat162 p = __floats2bfloat162_rn(lo, hi);
    return *reinterpret_cast<uint32_t*>(&p);
}
__device__ __forceinline__ void cp_async16(uint32_t dst, const void* src) {
    asm volatile("cp.async.cg.shared.global [%0], [%1], 16;"
                 :: "r"(dst), "l"(src));
}
__device__ __forceinline__ void cp_commit() {
    asm volatile("cp.async.commit_group;" ::: "memory");
}
template <int N>
__device__ __forceinline__ void cp_wait() {
    asm volatile("cp.async.wait_group %0;" :: "n"(N) : "memory");
}

// ============================================================
// Fused GroupNorm: one block per (b,g); reduce, then apply + bf16
// ============================================================
__global__ void __launch_bounds__(512)
gn_fuse_kernel(const float* __restrict__ x,
               const float* __restrict__ gnw,
               const float* __restrict__ gnb) {
    int blk = blockIdx.x;
    int b = blk / NGROUPS, g = blk % NGROUPS;
    const size_t base = ((size_t)b * Cdim + (size_t)g * CPG) * HWp;
    const float4* p = (const float4*)(x + base);
    const int n4 = CPG * HWp / 4;  // 16384
    float s = 0.f, sq = 0.f;
    for (int i = threadIdx.x; i < n4; i += blockDim.x) {
        float4 v = p[i];
        s  += v.x + v.y + v.z + v.w;
        sq += v.x * v.x + v.y * v.y + v.z * v.z + v.w * v.w;
    }
    __shared__ float ss[32], ssq[32];
    __shared__ float sa[CPG], sb[CPG];
    #pragma unroll
    for (int o = 16; o > 0; o >>= 1) {
        s  += __shfl_down_sync(0xffffffffu, s, o);
        sq += __shfl_down_sync(0xffffffffu, sq, o);
    }
    int wid = threadIdx.x >> 5, lid = threadIdx.x & 31;
    if (lid == 0) { ss[wid] = s; ssq[wid] = sq; }
    __syncthreads();
    if (wid == 0) {
        int nw = blockDim.x >> 5;
        s  = (lid < nw) ? ss[lid]  : 0.f;
        sq = (lid < nw) ? ssq[lid] : 0.f;
        #pragma unroll
        for (int o = 16; o > 0; o >>= 1) {
            s  += __shfl_down_sync(0xffffffffu, s, o);
            sq += __shfl_down_sync(0xffffffffu, sq, o);
        }
        if (lid == 0) { ss[0] = s; ssq[0] = sq; }
    }
    __syncthreads();
    {
        const float invn = 1.f / (float)(CPG * HWp);
        float mean = ss[0] * invn;
        float var  = ssq[0] * invn - mean * mean;
        float rstd = rsqrtf(var + EPSV);
        if (threadIdx.x < CPG) {
            int c = g * CPG + threadIdx.x;
            float a = rstd * gnw[c];
            sa[threadIdx.x] = a;
            sb[threadIdx.x] = gnb[c] - mean * a;
        }
    }
    __syncthreads();
    __nv_bfloat162* dst = (__nv_bfloat162*)(g_xnb + base);
    const int per_c4 = HWp / 4;
    for (int i = threadIdx.x; i < n4; i += blockDim.x) {
        int c = i / per_c4;
        float a = sa[c], bb = sb[c];
        float4 v = p[i];
        dst[2 * i]     = __floats2bfloat162_rn(v.x * a + bb, v.y * a + bb);
        dst[2 * i + 1] = __floats2bfloat162_rn(v.z * a + bb, v.w * a + bb);
    }
}

// ============================================================
// LayerNorm on context -> bf16
// ============================================================
__global__ void ln_kernel(const float* __restrict__ ctx,
                          const float* __restrict__ w,
                          const float* __restrict__ bb) {
    int row = blockIdx.x;
    const float* xr = ctx + (size_t)row * CTXd;
    float s = 0.f, sq = 0.f;
    for (int i = threadIdx.x; i < CTXd; i += blockDim.x) {
        float v = xr[i];
        s += v; sq += v * v;
    }
    __shared__ float ss[32], ssq[32];
    __shared__ float smean, srstd;
    #pragma unroll
    for (int o = 16; o > 0; o >>= 1) {
        s  += __shfl_down_sync(0xffffffffu, s, o);
        sq += __shfl_down_sync(0xffffffffu, sq, o);
    }
    int wid = threadIdx.x >> 5, lid = threadIdx.x & 31;
    if (lid == 0) { ss[wid] = s; ssq[wid] = sq; }
    __syncthreads();
    if (wid == 0) {
        int nw = blockDim.x >> 5;
        s  = (lid < nw) ? ss[lid]  : 0.f;
        sq = (lid < nw) ? ssq[lid] : 0.f;
        #pragma unroll
        for (int o = 16; o > 0; o >>= 1) {
            s  += __shfl_down_sync(0xffffffffu, s, o);
            sq += __shfl_down_sync(0xffffffffu, sq, o);
        }
        if (lid == 0) {
            const float invn = 1.f / (float)CTXd;
            float mean = s * invn;
            float var  = sq * invn - mean * mean;
            smean = mean;
            srstd = rsqrtf(var + EPSV);
        }
    }
    __syncthreads();
    float mean = smean, rstd = srstd;
    for (int i = threadIdx.x; i < CTXd; i += blockDim.x) {
        g_cnb[(size_t)row * CTXd + i] =
            __float2bfloat16((xr[i] - mean) * rstd * w[i] + bb[i]);
    }
}

// ============================================================
// Weight bf16 conversion (q_w, out_w, k_w, v_w)
// ============================================================
#define NQW (Cdim * Cdim)
#define NKW (Cdim * CTXd)
__global__ void conv_w_kernel(const float* __restrict__ qw, const float* __restrict__ ow,
                              const float* __restrict__ kw, const float* __restrict__ vw) {
    int i = blockIdx.x * blockDim.x + threadIdx.x;
    if (i < NQW)                 g_qwb[i] = __float2bfloat16(qw[i]);
    else if (i < 2 * NQW)        g_owb[i - NQW] = __float2bfloat16(ow[i - NQW]);
    else if (i < 2 * NQW + NKW)  g_kwb[i - 2 * NQW] = __float2bfloat16(kw[i - 2 * NQW]);
    else                         g_vwb[i - 2 * NQW - NKW] = __float2bfloat16(vw[i - 2 * NQW - NKW]);
}

// ============================================================
// K/V projection via bf16 mma.sync (NT) — unchanged (20.6us proven)
// ============================================================
#define KVA_STR 40
#define KV_STAGE_BYTES (128 * KVA_STR * 2)
#define KV_STAGES 3
#define KV_NIT (CTXd / 32)

__global__ void __launch_bounds__(256, 2)
kv_mma(const float* __restrict__ kb_, const float* __restrict__ vb_) {
    __shared__ __align__(16) char smem_[KV_STAGES * 2 * KV_STAGE_BYTES];

    const __nv_bfloat16* W    = blockIdx.z ? g_vwb : g_kwb;
    const float*         bias = blockIdx.z ? vb_ : kb_;
    __nv_bfloat16*       out  = blockIdx.z ? g_vb : g_kb;

    const int tid  = threadIdx.x;
    const int warp = tid >> 5, lane = tid & 31;
    const int wm = warp >> 2, wn = warp & 3;
    const int n0 = blockIdx.y * 128;
    const int o0 = blockIdx.x * 128;

    const uint32_t sbase = smem_u32(smem_);
    const uint32_t sB0 = sbase + KV_STAGES * KV_STAGE_BYTES;

    const int ld_row = tid >> 2;
    const int ld_col = (tid & 3) * 8;

    const uint32_t st_off  = (ld_row * KVA_STR + ld_col) * 2;
    const uint32_t st_off2 = ((ld_row + 64) * KVA_STR + ld_col) * 2;

    const uint32_t a_lm_base =
        ((wm * 64 + (lane & 15)) * KVA_STR + (lane >> 4) * 8) * 2;
    const uint32_t b_lm_part =
        ((lane & 7) * KVA_STR + ((lane >> 3) & 1) * 8) * 2;

    float acc[4][4][4] = {};

    #pragma unroll
    for (int s = 0; s < KV_STAGES - 1; s++) {
        const int k0 = s * 32;
        uint32_t aS = sbase + s * KV_STAGE_BYTES;
        uint32_t bS = sB0 + s * KV_STAGE_BYTES;
        cp_async16(aS + st_off,  g_cnb + (size_t)(n0 + ld_row) * CTXd + k0 + ld_col);
        cp_async16(aS + st_off2, g_cnb + (size_t)(n0 + ld_row + 64) * CTXd + k0 + ld_col);
        cp_async16(bS + st_off,  W + (size_t)(o0 + ld_row) * CTXd + k0 + ld_col);
        cp_async16(bS + st_off2, W + (size_t)(o0 + ld_row + 64) * CTXd + k0 + ld_col);
        cp_commit();
    }

    #pragma unroll 1
    for (int it = 0; it < KV_NIT; it++) {
        cp_wait<KV_STAGES - 2>();
        __syncthreads();
        {
            const int sl = it + KV_STAGES - 1;
            if (sl < KV_NIT) {
                const int k0 = sl * 32;
                const int sb = sl % KV_STAGES;
                uint32_t aS = sbase + sb * KV_STAGE_BYTES;
                uint32_t bS = sB0 + sb * KV_STAGE_BYTES;
                cp_async16(aS + st_off,  g_cnb + (size_t)(n0 + ld_row) * CTXd + k0 + ld_col);
                cp_async16(aS + st_off2, g_cnb + (size_t)(n0 + ld_row + 64) * CTXd + k0 + ld_col);
                cp_async16(bS + st_off,  W + (size_t)(o0 + ld_row) * CTXd + k0 + ld_col);
                cp_async16(bS + st_off2, W + (size_t)(o0 + ld_row + 64) * CTXd + k0 + ld_col);
            }
            cp_commit();
        }

        const int sc = it % KV_STAGES;
        const uint32_t aBuf = sbase + sc * KV_STAGE_BYTES;
        const uint32_t bBuf = sB0 + sc * KV_STAGE_BYTES;

        #pragma unroll
        for (int kk = 0; kk < 2; kk++) {
            uint32_t af[4][4];
            #pragma unroll
            for (int mt = 0; mt < 4; mt++) {
                uint32_t addr = aBuf + a_lm_base + (mt * 16 * KVA_STR + kk * 16) * 2;
                asm volatile(
                    "ldmatrix.sync.aligned.m8n8.x4.shared.b16 {%0,%1,%2,%3}, [%4];"
                    : "=r"(af[mt][0]), "=r"(af[mt][1]), "=r"(af[mt][2]), "=r"(af[mt][3])
                    : "r"(addr));
            }
            uint32_t bf[4][2];
            #pragma unroll
            for (int nt = 0; nt < 4; nt++) {
                uint32_t addr = bBuf + b_lm_part +
                    (((wn * 32 + nt * 8) * KVA_STR) + kk * 16) * 2;
                asm volatile(
                    "ldmatrix.sync.aligned.m8n8.x2.shared.b16 {%0,%1}, [%2];"
                    : "=r"(bf[nt][0]), "=r"(bf[nt][1]) : "r"(addr));
            }
            #pragma unroll
            for (int mt = 0; mt < 4; mt++)
                #pragma unroll
                for (int nt = 0; nt < 4; nt++) {
                    asm volatile(
                        "mma.sync.aligned.m16n8k16.row.col.f32.bf16.bf16.f32 "
                        "{%0,%1,%2,%3}, {%4,%5,%6,%7}, {%8,%9}, {%0,%1,%2,%3};"
                        : "+f"(acc[mt][nt][0]), "+f"(acc[mt][nt][1]),
                          "+f"(acc[mt][nt][2]), "+f"(acc[mt][nt][3])
                        : "r"(af[mt][0]), "r"(af[mt][1]), "r"(af[mt][2]), "r"(af[mt][3]),
                          "r"(bf[nt][0]), "r"(bf[nt][1]));
                }
        }
    }

    const int row_base = n0 + wm * 64 + (lane >> 2);
    const int col_base = o0 + wn * 32 + (lane & 3) * 2;
    #pragma unroll
    for (int mt = 0; mt < 4; mt++) {
        #pragma unroll
        for (int half = 0; half < 2; half++) {
            int row = row_base + mt * 16 + half * 8;
            if (row >= NROWS) continue;
            #pragma unroll
            for (int nt = 0; nt < 4; nt++) {
                int col = col_base + nt * 8;
                float bi0 = bias[col], bi1 = bias[col + 1];
                *(__nv_bfloat162*)(out + (size_t)row * Cdim + col) =
                    __floats2bfloat162_rn(acc[mt][nt][half * 2] + bi0,
                                          acc[mt][nt][half * 2 + 1] + bi1);
            }
        }
    }
}

// ============================================================
// bf16 mma.sync GEMM — 128 thr / 4 warps, warp tile 64x64,
// B fragments via x4.trans ldmatrix (2 n-frags per instr).
// ============================================================
#define A_STRIDE 40
#define B_STRIDE 136
#define STAGES 3
#define A_STAGE_BYTES (128 * A_STRIDE * 2)
#define B_STAGE_BYTES (32 * B_STRIDE * 2)
#define NIT (Cdim / 32)

template <bool BF16OUT>
__global__ void __launch_bounds__(128, 2)
mma_gemm(const __nv_bfloat16* __restrict__ Wb,
         const __nv_bfloat16* __restrict__ Xb,
         const float* __restrict__ bias,
         const float* __restrict__ residual,
         void* __restrict__ outv) {
    __shared__ __align__(16) char smem_[STAGES * (A_STAGE_BYTES + B_STAGE_BYTES)];

    const int tid  = threadIdx.x;
    const int warp = tid >> 5, lane = tid & 31;
    const int wm = warp >> 1, wn = warp & 1;
    const int p0 = blockIdx.x * 128;
    const int o0 = blockIdx.y * 128;
    const int b  = blockIdx.z;
    const __nv_bfloat16* Xbb = Xb + (size_t)b * Cdim * HWp;

    const uint32_t sbase = smem_u32(smem_);
    const uint32_t sB0 = sbase + STAGES * A_STAGE_BYTES;

    const int a_ld_row = tid >> 2;
    const int a_ld_col = (tid & 3) * 8;
    const int b_ld_row = tid >> 4;
    const int b_ld_col = (tid & 15) * 8;

    const uint32_t a_lm_base =
        ((wm * 64 + (lane & 15)) * A_STRIDE + (lane >> 4) * 8) * 2;
    // B x4.trans lane map: row=(lane&7)+((lane>>3)&1)*8 (k), col=((lane>>4)&1)*8
    const uint32_t b_lm4_base =
        (((lane & 7) + ((lane >> 3) & 1) * 8) * B_STRIDE +
         wn * 64 + ((lane >> 4) & 1) * 8) * 2;

    uint32_t a_st[4], b_st[4];
    #pragma unroll
    for (int j = 0; j < 4; j++) {
        a_st[j] = ((a_ld_row + j * 32) * A_STRIDE + a_ld_col) * 2;
        b_st[j] = ((b_ld_row + j * 8) * B_STRIDE + b_ld_col) * 2;
    }

    float acc[4][8][4] = {};

    #pragma unroll
    for (int s = 0; s < STAGES - 1; s++) {
        const int k0 = s * 32;
        uint32_t aS = sbase + s * A_STAGE_BYTES;
        uint32_t bS = sB0 + s * B_STAGE_BYTES;
        #pragma unroll
        for (int j = 0; j < 4; j++) {
            cp_async16(aS + a_st[j],
                       Wb + (size_t)(o0 + a_ld_row + j * 32) * Cdim + k0 + a_ld_col);
            cp_async16(bS + b_st[j],
                       Xbb + (size_t)(k0 + b_ld_row + j * 8) * HWp + p0 + b_ld_col);
        }
        cp_commit();
    }

    #pragma unroll 1
    for (int it = 0; it < NIT; it++) {
        cp_wait<STAGES - 2>();
        __syncthreads();
        {
            const int sl = it + STAGES - 1;
            if (sl < NIT) {
                const int k0 = sl * 32;
                const int sb = sl % STAGES;
                uint32_t aS = sbase + sb * A_STAGE_BYTES;
                uint32_t bS = sB0 + sb * B_STAGE_BYTES;
                #pragma unroll
                for (int j = 0; j < 4; j++) {
                    cp_async16(aS + a_st[j],
                               Wb + (size_t)(o0 + a_ld_row + j * 32) * Cdim + k0 + a_ld_col);
                    cp_async16(bS + b_st[j],
                               Xbb + (size_t)(k0 + b_ld_row + j * 8) * HWp + p0 + b_ld_col);
                }
            }
            cp_commit();
        }

        const int sc = it % STAGES;
        const uint32_t aBuf = sbase + sc * A_STAGE_BYTES;
        const uint32_t bBuf = sB0 + sc * B_STAGE_BYTES;

        #pragma unroll
        for (int kk = 0; kk < 2; kk++) {
            uint32_t af[4][4];
            #pragma unroll
            for (int mt = 0; mt < 4; mt++) {
                uint32_t addr = aBuf + a_lm_base + (mt * 16 * A_STRIDE + kk * 16) * 2;
                asm volatile(
                    "ldmatrix.sync.aligned.m8n8.x4.shared.b16 {%0,%1,%2,%3}, [%4];"
                    : "=r"(af[mt][0]), "=r"(af[mt][1]), "=r"(af[mt][2]), "=r"(af[mt][3])
                    : "r"(addr));
            }
            uint32_t bf[8][2];
            #pragma unroll
            for (int ntp = 0; ntp < 4; ntp++) {
                uint32_t addr = bBuf + b_lm4_base +
                    (kk * 16 * B_STRIDE + ntp * 16) * 2;
                asm volatile(
                    "ldmatrix.sync.aligned.m8n8.x4.trans.shared.b16 {%0,%1,%2,%3}, [%4];"
                    : "=r"(bf[2 * ntp][0]), "=r"(bf[2 * ntp][1]),
                      "=r"(bf[2 * ntp + 1][0]), "=r"(bf[2 * ntp + 1][1])
                    : "r"(addr));
            }
            #pragma unroll
            for (int mt = 0; mt < 4; mt++)
                #pragma unroll
                for (int nt = 0; nt < 8; nt++) {
                    asm volatile(
                        "mma.sync.aligned.m16n8k16.row.col.f32.bf16.bf16.f32 "
                        "{%0,%1,%2,%3}, {%4,%5,%6,%7}, {%8,%9}, {%0,%1,%2,%3};"
                        : "+f"(acc[mt][nt][0]), "+f"(acc[mt][nt][1]),
                          "+f"(acc[mt][nt][2]), "+f"(acc[mt][nt][3])
                        : "r"(af[mt][0]), "r"(af[mt][1]), "r"(af[mt][2]), "r"(af[mt][3]),
                          "r"(bf[nt][0]), "r"(bf[nt][1]));
                }
        }
    }

    const int row_base = o0 + wm * 64 + (lane >> 2);
    const int col_base = p0 + wn * 64 + (lane & 3) * 2;
    #pragma unroll
    for (int mt = 0; mt < 4; mt++) {
        #pragma unroll
        for (int half = 0; half < 2; half++) {
            int row = row_base + mt * 16 + half * 8;
            float bi = bias[row];
            size_t rb = ((size_t)b * Cdim + row) * HWp;
            #pragma unroll
            for (int nt = 0; nt < 8; nt++) {
                int col = col_base + nt * 8;
                float rx = acc[mt][nt][half * 2]     + bi;
                float ry = acc[mt][nt][half * 2 + 1] + bi;
                if (BF16OUT) {
                    __nv_bfloat16* outb = (__nv_bfloat16*)outv;
                    *(__nv_bfloat162*)(outb + rb + col) = __floats2bfloat162_rn(rx, ry);
                } else {
                    float* outf = (float*)outv;
                    if (residual) {
                        float2 rv = *(const float2*)(residual + rb + col);
                        rx += rv.x; ry += rv.y;
                    }
                    float2 r; r.x = rx; r.y = ry;
                    *(float2*)(outf + rb + col) = r;
                }
            }
        }
    }
}

// ============================================================
// Tensor-core flash attention — unchanged from R9
// ============================================================
#define QS_STR 136
#define KS_STR 72
#define SPAD 80

__global__ void __launch_bounds__(128)
attn_mma_kernel() {
    __shared__ __align__(16) __nv_bfloat16 sQ[64 * QS_STR];
    __shared__ __align__(16) __nv_bfloat16 sK[SPAD * KS_STR];
    __shared__ __align__(16) __nv_bfloat16 sV[SPAD * KS_STR];

    const int tid = threadIdx.x;
    const int warp = tid >> 5, lane = tid & 31;
    const int b = blockIdx.z, h = blockIdx.y;
    const int p0 = blockIdx.x * 128;
    const int ch0 = h * HD;

    const __nv_bfloat16* qg = g_qb + ((size_t)b * Cdim + ch0) * HWp + p0;
    #pragma unroll 4
    for (int i = tid; i < 64 * 16; i += 128) {
        int d = i >> 4, cc = (i & 15) * 8;
        *(uint4*)(sQ + d * QS_STR + cc) = *(const uint4*)(qg + (size_t)d * HWp + cc);
    }
    const __nv_bfloat16* kg = g_kb + (size_t)b * Sctx * Cdim + ch0;
    for (int i = tid; i < 77 * 8; i += 128) {
        int s = i >> 3, dd = (i & 7) * 8;
        *(uint4*)(sK + s * KS_STR + dd) = *(const uint4*)(kg + (size_t)s * Cdim + dd);
    }
    if (tid < 24) {
        int s = 77 + tid / 8, dd = (tid & 7) * 8;
        uint4 z = {0, 0, 0, 0};
        *(uint4*)(sK + s * KS_STR + dd) = z;
    }
    const __nv_bfloat16* vg = g_vb + (size_t)b * Sctx * Cdim + ch0;
    for (int i = tid; i < 77 * 8; i += 128) {
        int s = i >> 3, dd = (i & 7) * 8;
        *(uint4*)(sV + s * KS_STR + dd) = *(const uint4*)(vg + (size_t)s * Cdim + dd);
    }
    if (tid >= 104) {
        int t = tid - 104;
        int s = 77 + t / 8, dd = (t & 7) * 8;
        uint4 z = {0, 0, 0, 0};
        *(uint4*)(sV + s * KS_STR + dd) = z;
    }
    __syncthreads();

    const uint32_t qbase = smem_u32(sQ);
    const uint32_t kbase = smem_u32(sK);
    const uint32_t vbase = smem_u32(sV);

    float c[2][10][4];
    #pragma unroll
    for (int mt = 0; mt < 2; mt++)
        #pragma unroll
        for (int nt = 0; nt < 10; nt++)
            #pragma unroll
            for (int r = 0; r < 4; r++) c[mt][nt][r] = 0.f;

    const int a_krow = ((lane >> 4) & 1) * 8 + (lane & 7);
    const int a_mcol = ((lane >> 3) & 1) * 8;
    const uint32_t b_lm_part = ((lane & 7) * KS_STR + ((lane >> 3) & 1) * 8) * 2;

    #pragma unroll
    for (int kk = 0; kk < 4; kk++) {
        uint32_t af[2][4];
        #pragma unroll
        for (int mt = 0; mt < 2; mt++) {
            uint32_t addr = qbase +
                ((kk * 16 + a_krow) * QS_STR + warp * 32 + mt * 16 + a_mcol) * 2;
            asm volatile(
                "ldmatrix.sync.aligned.m8n8.x4.trans.shared.b16 {%0,%1,%2,%3}, [%4];"
                : "=r"(af[mt][0]), "=r"(af[mt][1]), "=r"(af[mt][2]), "=r"(af[mt][3])
                : "r"(addr));
        }
        uint32_t bf[10][2];
        #pragma unroll
        for (int nt = 0; nt < 10; nt++) {
            uint32_t addr = kbase + b_lm_part + ((nt * 8) * KS_STR + kk * 16) * 2;
            asm volatile(
                "ldmatrix.sync.aligned.m8n8.x2.shared.b16 {%0,%1}, [%2];"
                : "=r"(bf[nt][0]), "=r"(bf[nt][1]) : "r"(addr));
        }
        #pragma unroll
        for (int mt = 0; mt < 2; mt++)
            #pragma unroll
            for (int nt = 0; nt < 10; nt++) {
                asm volatile(
                    "mma.sync.aligned.m16n8k16.row.col.f32.bf16.bf16.f32 "
                    "{%0,%1,%2,%3}, {%4,%5,%6,%7}, {%8,%9}, {%0,%1,%2,%3};"
                    : "+f"(c[mt][nt][0]), "+f"(c[mt][nt][1]),
                      "+f"(c[mt][nt][2]), "+f"(c[mt][nt][3])
                    : "r"(af[mt][0]), "r"(af[mt][1]), "r"(af[mt][2]), "r"(af[mt][3]),
                      "r"(bf[nt][0]), "r"(bf[nt][1]));
            }
    }
    __syncthreads();

    const float scale = 0.125f;
    uint32_t pu[2][10][2];
    float iv[2][2];
    #pragma unroll
    for (int mt = 0; mt < 2; mt++) {
        float mx0 = -1e30f, mx1 = -1e30f;
        #pragma unroll
        for (int nt = 0; nt < 10; nt++) {
            int col = nt * 8 + (lane & 3) * 2;
            c[mt][nt][0] = (col     < Sctx) ? c[mt][nt][0] * scale : -1e30f;
            c[mt][nt][1] = (col + 1 < Sctx) ? c[mt][nt][1] * scale : -1e30f;
            c[mt][nt][2] = (col     < Sctx) ? c[mt][nt][2] * scale : -1e30f;
            c[mt][nt][3] = (col + 1 < Sctx) ? c[mt][nt][3] * scale : -1e30f;
            mx0 = fmaxf(mx0, fmaxf(c[mt][nt][0], c[mt][nt][1]));
            mx1 = fmaxf(mx1, fmaxf(c[mt][nt][2], c[mt][nt][3]));
        }
        mx0 = fmaxf(mx0, __shfl_xor_sync(0xffffffffu, mx0, 1));
        mx0 = fmaxf(mx0, __shfl_xor_sync(0xffffffffu, mx0, 2));
        mx1 = fmaxf(mx1, __shfl_xor_sync(0xffffffffu, mx1, 1));
        mx1 = fmaxf(mx1, __shfl_xor_sync(0xffffffffu, mx1, 2));
        float s0 = 0.f, s1 = 0.f;
        #pragma unroll
        for (int nt = 0; nt < 10; nt++) {
            float e0 = __expf(c[mt][nt][0] - mx0);
            float e1 = __expf(c[mt][nt][1] - mx0);
            float e2 = __expf(c[mt][nt][2] - mx1);
            float e3 = __expf(c[mt][nt][3] - mx1);
            s0 += e0 + e1; s1 += e2 + e3;
            pu[mt][nt][0] = pack_bf16(e0, e1);
            pu[mt][nt][1] = pack_bf16(e2, e3);
        }
        s0 += __shfl_xor_sync(0xffffffffu, s0, 1);
        s0 += __shfl_xor_sync(0xffffffffu, s0, 2);
        s1 += __shfl_xor_sync(0xffffffffu, s1, 1);
        s1 += __shfl_xor_sync(0xffffffffu, s1, 2);
        iv[mt][0] = 1.f / s0;
        iv[mt][1] = 1.f / s1;
    }

    float o[2][8][4];
    #pragma unroll
    for (int mt = 0; mt < 2; mt++)
        #pragma unroll
        for (int nt = 0; nt < 8; nt++)
            #pragma unroll
            for (int r = 0; r < 4; r++) o[mt][nt][r] = 0.f;

    #pragma unroll
    for (int kk = 0; kk < 5; kk++) {
        uint32_t bv[8][2];
        #pragma unroll
        for (int nt = 0; nt < 8; nt++) {
            uint32_t addr = vbase + ((kk * 16 + (lane & 15)) * KS_STR + nt * 8) * 2;
            asm volatile(
                "ldmatrix.sync.aligned.m8n8.x2.trans.shared.b16 {%0,%1}, [%2];"
                : "=r"(bv[nt][0]), "=r"(bv[nt][1]) : "r"(addr));
        }
        #pragma unroll
        for (int mt = 0; mt < 2; mt++) {
            uint32_t a0 = pu[mt][2 * kk][0];
            uint32_t a1 = pu[mt][2 * kk][1];
            uint32_t a2 = pu[mt][2 * kk + 1][0];
            uint32_t a3 = pu[mt][2 * kk + 1][1];
            #pragma unroll
            for (int nt = 0; nt < 8; nt++) {
                asm volatile(
                    "mma.sync.aligned.m16n8k16.row.col.f32.bf16.bf16.f32 "
                    "{%0,%1,%2,%3}, {%4,%5,%6,%7}, {%8,%9}, {%0,%1,%2,%3};"
                    : "+f"(o[mt][nt][0]), "+f"(o[mt][nt][1]),
                      "+f"(o[mt][nt][2]), "+f"(o[mt][nt][3])
                    : "r"(a0), "r"(a1), "r"(a2), "r"(a3),
                      "r"(bv[nt][0]), "r"(bv[nt][1]));
            }
        }
    }

    __nv_bfloat16* Od = sQ;
    #pragma unroll
    for (int mt = 0; mt < 2; mt++) {
        int pxa = warp * 32 + mt * 16 + (lane >> 2);
        #pragma unroll
        for (int nt = 0; nt < 8; nt++) {
            int d = nt * 8 + (lane & 3) * 2;
            Od[d * QS_STR + pxa]           = __float2bfloat16(o[mt][nt][0] * iv[mt][0]);
            Od[(d + 1) * QS_STR + pxa]     = __float2bfloat16(o[mt][nt][1] * iv[mt][0]);
            Od[d * QS_STR + pxa + 8]       = __float2bfloat16(o[mt][nt][2] * iv[mt][1]);
            Od[(d + 1) * QS_STR + pxa + 8] = __float2bfloat16(o[mt][nt][3] * iv[mt][1]);
        }
    }
    __syncthreads();

    __nv_bfloat16* og = g_aob + ((size_t)b * Cdim + ch0) * HWp + p0;
    #pragma unroll 2
    for (int i = tid; i < 64 * 16; i += 128) {
        int d = i >> 4, cc = (i & 15) * 8;
        *(uint4*)(og + (size_t)d * HWp + cc) = *(const uint4*)(Od + d * QS_STR + cc);
    }
}

// ============================================================
extern "C" void kernel_launch(void* const* d_in, const int* in_sizes, int n_in,
                              void* d_out, int out_size) {
    const float* x       = (const float*)d_in[0];
    const float* context = (const float*)d_in[1];
    const float* gn_w    = (const float*)d_in[2];
    const float* gn_b    = (const float*)d_in[3];
    const float* ln_w    = (const float*)d_in[4];
    const float* ln_b    = (const float*)d_in[5];
    const float* q_w     = (const float*)d_in[6];
    const float* q_b     = (const float*)d_in[7];
    const float* k_w     = (const float*)d_in[8];
    const float* k_b     = (const float*)d_in[9];
    const float* v_w     = (const float*)d_in[10];
    const float* v_b     = (const float*)d_in[11];
    const float* out_w   = (const float*)d_in[12];
    const float* out_b   = (const float*)d_in[13];
    float* out = (float*)d_out;

    __nv_bfloat16 *qb = nullptr, *xnb = nullptr, *aob = nullptr, *qwb = nullptr, *owb = nullptr;
    cudaGetSymbolAddress((void**)&qb,  g_qb);
    cudaGetSymbolAddress((void**)&xnb, g_xnb);
    cudaGetSymbolAddress((void**)&aob, g_aob);
    cudaGetSymbolAddress((void**)&qwb, g_qwb);
    cudaGetSymbolAddress((void**)&owb, g_owb);

    static cudaStream_t s_side = nullptr;
    static cudaEvent_t ev_fork = nullptr, ev_join = nullptr;
    if (s_side == nullptr) {
        cudaStreamCreateWithFlags(&s_side, cudaStreamNonBlocking);
        cudaEventCreateWithFlags(&ev_fork, cudaEventDisableTiming);
        cudaEventCreateWithFlags(&ev_join, cudaEventDisableTiming);
    }

    conv_w_kernel<<<(2 * NQW + 2 * NKW) / 512, 512>>>(q_w, out_w, k_w, v_w);
    cudaEventRecord(ev_fork, 0);
    cudaStreamWaitEvent(s_side, ev_fork, 0);
    ln_kernel<<<Bsz * Sctx, 256, 0, s_side>>>(context, ln_w, ln_b);
    kv_mma<<<dim3(Cdim / 128, NROWS_PAD / 128, 2), 256, 0, s_side>>>(k_b, v_b);
    cudaEventRecord(ev_join, s_side);
    gn_fuse_kernel<<<Bsz * NGROUPS, 512>>>(x, gn_w, gn_b);
    mma_gemm<true><<<dim3(HWp / 128, Cdim / 128, Bsz), 128>>>(
        qwb, xnb, q_b, nullptr, qb);
    cudaStreamWaitEvent(0, ev_join, 0);
    attn_mma_kernel<<<dim3(HWp / 128, NHEADS, Bsz), 128>>>();
    mma_gemm<false><<<dim3(HWp / 128, Cdim / 128, Bsz), 128>>>(
        owb, aob, out_b, x, out);
}